// round 3
// baseline (speedup 1.0000x reference)
#include <cuda_runtime.h>
#include <math.h>

// Problem constants
#define BB   4
#define SS   2048
#define DD   1024
#define HH   16
#define DHD  64
#define FFD  4096
#define ROWS (BB*SS)   // 8192

// ---------------- scratch (device globals; no allocation allowed) ----------
__device__ float g_xn [(size_t)ROWS*DD];
__device__ float g_qkv[(size_t)ROWS*3*DD];
__device__ float g_att[(size_t)ROWS*DD];
__device__ float g_ctx[(size_t)ROWS*DD];
__device__ float g_x1 [(size_t)ROWS*DD];
__device__ float g_u  [(size_t)ROWS*DD];
__device__ float g_al [(size_t)ROWS*DD];
__device__ float g_be [(size_t)ROWS*DD];
__device__ float g_ga [(size_t)ROWS*DD];
__device__ float g_x2 [(size_t)ROWS*DD];
__device__ float g_h  [(size_t)ROWS*DD];
__device__ float g_ffh[(size_t)ROWS*FFD];

// ---------------- LayerNorm: one block (256 thr) per row of 1024 -----------
__global__ void __launch_bounds__(256) layernorm_k(
    const float* __restrict__ x, const float* __restrict__ w,
    const float* __restrict__ b, float* __restrict__ y)
{
    int row = blockIdx.x;
    const float* xr = x + (size_t)row * DD;
    int tid = threadIdx.x;
    float4 v = *reinterpret_cast<const float4*>(xr + tid * 4);
    float s  = v.x + v.y + v.z + v.w;
    float ss = v.x*v.x + v.y*v.y + v.z*v.z + v.w*v.w;
    #pragma unroll
    for (int off = 16; off > 0; off >>= 1) {
        s  += __shfl_xor_sync(0xffffffffu, s,  off);
        ss += __shfl_xor_sync(0xffffffffu, ss, off);
    }
    __shared__ float sh_s[8], sh_ss[8];
    int wid = tid >> 5, lane = tid & 31;
    if (lane == 0) { sh_s[wid] = s; sh_ss[wid] = ss; }
    __syncthreads();
    float ts = 0.f, tss = 0.f;
    #pragma unroll
    for (int i = 0; i < 8; i++) { ts += sh_s[i]; tss += sh_ss[i]; }
    float mu   = ts * (1.0f / DD);
    float var  = tss * (1.0f / DD) - mu * mu;
    float rstd = rsqrtf(var + 1e-5f);
    float4 wv = *reinterpret_cast<const float4*>(w + tid * 4);
    float4 bv = *reinterpret_cast<const float4*>(b + tid * 4);
    float4 o;
    o.x = (v.x - mu) * rstd * wv.x + bv.x;
    o.y = (v.y - mu) * rstd * wv.y + bv.y;
    o.z = (v.z - mu) * rstd * wv.z + bv.z;
    o.w = (v.w - mu) * rstd * wv.w + bv.w;
    *reinterpret_cast<float4*>(y + (size_t)row * DD + tid * 4) = o;
}

// ---------------- GEMM: C[M,N] = A[M,K] @ B[N,K]^T (+ epilogue) ------------
// A row-major [M,K], B row-major [N,K] (PyTorch Linear weight layout).
// BM=BN=128, BK=16, 256 threads, 8x8 per thread.
// EPI: 0 = bias; 1 = dual (C=v+bias, C2=res+v+bias); 2 = bias+exact GELU;
//      3 = bias + residual.
#define GBM 128
#define GBN 128
#define GBK 16

template<int EPI>
__global__ void __launch_bounds__(256) gemm_nt(
    const float* __restrict__ A, const float* __restrict__ B,
    const float* __restrict__ bias, float* __restrict__ C,
    int M, int N, int K,
    const float* __restrict__ res, float* __restrict__ C2)
{
    __shared__ float As[GBK][GBM];
    __shared__ float Bs[GBK][GBN];

    int tid = threadIdx.x;
    int bm = blockIdx.y * GBM;
    int bn = blockIdx.x * GBN;

    int lr = tid >> 2;          // 0..63
    int lc = (tid & 3) << 2;    // 0,4,8,12
    int tx = tid & 15, ty = tid >> 4;

    const float* Aptr = A + (size_t)bm * K;
    const float* Bptr = B + (size_t)bn * K;

    float acc[8][8];
    #pragma unroll
    for (int i = 0; i < 8; i++)
        #pragma unroll
        for (int j = 0; j < 8; j++) acc[i][j] = 0.f;

    for (int k0 = 0; k0 < K; k0 += GBK) {
        #pragma unroll
        for (int r = 0; r < 2; r++) {
            int row = lr + r * 64;
            float4 va = *reinterpret_cast<const float4*>(Aptr + (size_t)row * K + k0 + lc);
            As[lc+0][row] = va.x; As[lc+1][row] = va.y;
            As[lc+2][row] = va.z; As[lc+3][row] = va.w;
            float4 vb = *reinterpret_cast<const float4*>(Bptr + (size_t)row * K + k0 + lc);
            Bs[lc+0][row] = vb.x; Bs[lc+1][row] = vb.y;
            Bs[lc+2][row] = vb.z; Bs[lc+3][row] = vb.w;
        }
        __syncthreads();
        #pragma unroll
        for (int kk = 0; kk < GBK; kk++) {
            float a[8], bfr[8];
            #pragma unroll
            for (int i = 0; i < 8; i++) a[i]   = As[kk][ty*8 + i];
            #pragma unroll
            for (int j = 0; j < 8; j++) bfr[j] = Bs[kk][tx*8 + j];
            #pragma unroll
            for (int i = 0; i < 8; i++)
                #pragma unroll
                for (int j = 0; j < 8; j++)
                    acc[i][j] = fmaf(a[i], bfr[j], acc[i][j]);
        }
        __syncthreads();
    }

    // epilogue
    float bval[8];
    #pragma unroll
    for (int j = 0; j < 8; j++) bval[j] = bias[bn + tx*8 + j];

    #pragma unroll
    for (int i = 0; i < 8; i++) {
        int r = bm + ty*8 + i;
        size_t base = (size_t)r * N + bn + tx*8;
        #pragma unroll
        for (int j = 0; j < 8; j++) {
            float v = acc[i][j] + bval[j];
            if (EPI == 2) {
                v = 0.5f * v * (1.0f + erff(v * 0.70710678118654752f));
            }
            if (EPI == 3) {
                v += res[base + j];
            }
            C[base + j] = v;
            if (EPI == 1) {
                C2[base + j] = res[base + j] + v;
            }
        }
    }
}

// ---------------- Causal flash attention, fp32, dh=64 ----------------------
// qkv: [ROWS, 3*D] with q at col 0, k at 1024, v at 2048; head h uses
// cols h*64..h*64+63 of each. out: [ROWS, D] in (B,S,H*dh) layout.
#define FA_PAD 65
#define FA_SMEM (4 * 64 * FA_PAD * (int)sizeof(float))   // Q,K,V,P tiles

__global__ void __launch_bounds__(256) flash_attn_k(
    const float* __restrict__ qkv, float* __restrict__ out)
{
    extern __shared__ float sm[];
    float* Qs = sm;
    float* Ks = sm + 64 * FA_PAD;
    float* Vs = sm + 2 * 64 * FA_PAD;
    float* Ps = sm + 3 * 64 * FA_PAD;

    int qt = blockIdx.x;     // query tile 0..31
    int h  = blockIdx.y;
    int b  = blockIdx.z;
    int tid = threadIdx.x;
    int tx = tid & 15, ty = tid >> 4;

    const size_t rstride = 3 * DD;
    const float* Qbase = qkv + ((size_t)b * SS + qt * 64) * rstride + h * DHD;
    const float* Kbase = qkv + (size_t)b * SS * rstride + DD     + h * DHD;
    const float* Vbase = qkv + (size_t)b * SS * rstride + 2 * DD + h * DHD;
    const float scale = 0.125f;   // 1/sqrt(64)

    // load Q tile (scaled)
    for (int i = tid; i < 64 * 16; i += 256) {
        int r = i >> 4, c = (i & 15) << 2;
        float4 v = *reinterpret_cast<const float4*>(Qbase + (size_t)r * rstride + c);
        Qs[r*FA_PAD + c+0] = v.x * scale;
        Qs[r*FA_PAD + c+1] = v.y * scale;
        Qs[r*FA_PAD + c+2] = v.z * scale;
        Qs[r*FA_PAD + c+3] = v.w * scale;
    }

    float m[4], l[4], o[4][4];
    #pragma unroll
    for (int i = 0; i < 4; i++) {
        m[i] = -INFINITY; l[i] = 0.f;
        #pragma unroll
        for (int j = 0; j < 4; j++) o[i][j] = 0.f;
    }

    int nkt = qt + 1;  // causal
    for (int kt = 0; kt < nkt; kt++) {
        __syncthreads();   // protect K/V/P reuse (also covers initial Q load)
        for (int i = tid; i < 64 * 16; i += 256) {
            int r = i >> 4, c = (i & 15) << 2;
            size_t goff = (size_t)(kt * 64 + r) * rstride + c;
            float4 kv = *reinterpret_cast<const float4*>(Kbase + goff);
            Ks[r*FA_PAD + c+0] = kv.x; Ks[r*FA_PAD + c+1] = kv.y;
            Ks[r*FA_PAD + c+2] = kv.z; Ks[r*FA_PAD + c+3] = kv.w;
            float4 vv = *reinterpret_cast<const float4*>(Vbase + goff);
            Vs[r*FA_PAD + c+0] = vv.x; Vs[r*FA_PAD + c+1] = vv.y;
            Vs[r*FA_PAD + c+2] = vv.z; Vs[r*FA_PAD + c+3] = vv.w;
        }
        __syncthreads();

        // S = Q @ K^T  (4x4 per thread)
        float s[4][4];
        #pragma unroll
        for (int i = 0; i < 4; i++)
            #pragma unroll
            for (int j = 0; j < 4; j++) s[i][j] = 0.f;

        #pragma unroll 8
        for (int d = 0; d < 64; d++) {
            float qa[4], kb[4];
            #pragma unroll
            for (int i = 0; i < 4; i++) qa[i] = Qs[(ty*4 + i)*FA_PAD + d];
            #pragma unroll
            for (int j = 0; j < 4; j++) kb[j] = Ks[(tx*4 + j)*FA_PAD + d];
            #pragma unroll
            for (int i = 0; i < 4; i++)
                #pragma unroll
                for (int j = 0; j < 4; j++)
                    s[i][j] = fmaf(qa[i], kb[j], s[i][j]);
        }

        if (kt == qt) {   // diagonal tile: causal mask (same local indices)
            #pragma unroll
            for (int i = 0; i < 4; i++)
                #pragma unroll
                for (int j = 0; j < 4; j++)
                    if (tx*4 + j > ty*4 + i) s[i][j] = -1e30f;
        }

        // online softmax update, per row (rows shared by 16-lane groups)
        #pragma unroll
        for (int i = 0; i < 4; i++) {
            float rm = fmaxf(fmaxf(s[i][0], s[i][1]), fmaxf(s[i][2], s[i][3]));
            #pragma unroll
            for (int off = 8; off > 0; off >>= 1)
                rm = fmaxf(rm, __shfl_xor_sync(0xffffffffu, rm, off));
            float mn = fmaxf(m[i], rm);
            float corr = __expf(m[i] - mn);
            float ps = 0.f;
            #pragma unroll
            for (int j = 0; j < 4; j++) {
                float p = __expf(s[i][j] - mn);
                Ps[(ty*4 + i)*FA_PAD + tx*4 + j] = p;
                ps += p;
            }
            #pragma unroll
            for (int off = 8; off > 0; off >>= 1)
                ps += __shfl_xor_sync(0xffffffffu, ps, off);
            l[i] = l[i] * corr + ps;
            m[i] = mn;
            #pragma unroll
            for (int j = 0; j < 4; j++) o[i][j] *= corr;
        }
        __syncthreads();

        // O += P @ V
        #pragma unroll 8
        for (int kk = 0; kk < 64; kk++) {
            float p[4], vv[4];
            #pragma unroll
            for (int i = 0; i < 4; i++) p[i]  = Ps[(ty*4 + i)*FA_PAD + kk];
            #pragma unroll
            for (int j = 0; j < 4; j++) vv[j] = Vs[kk*FA_PAD + tx*4 + j];
            #pragma unroll
            for (int i = 0; i < 4; i++)
                #pragma unroll
                for (int j = 0; j < 4; j++)
                    o[i][j] = fmaf(p[i], vv[j], o[i][j]);
        }
    }

    // write: out[b, qt*64 + row, h*64 + col]
    #pragma unroll
    for (int i = 0; i < 4; i++) {
        float invl = 1.0f / l[i];
        size_t orow = ((size_t)b * SS + qt * 64 + ty*4 + i) * DD + h * DHD + tx*4;
        #pragma unroll
        for (int j = 0; j < 4; j++)
            out[orow + j] = o[i][j] * invl;
    }
}

// ---------------- INL integrator: fused elementwise -------------------------
__global__ void __launch_bounds__(256) inl_k(
    const float* __restrict__ xs0, const float* __restrict__ ul,
    const float* __restrict__ al,  const float* __restrict__ bl,
    const float* __restrict__ gl,  const float* __restrict__ x1,
    float* __restrict__ x2)
{
    size_t i = (size_t)blockIdx.x * blockDim.x + threadIdx.x;
    float xs = xs0[i];
    float u  = ul[i];
    float av = al[i];
    float alpha = 1.0f / (1.0f + expf(-av));
    float bv = bl[i];
    float beta = (bv > 20.0f) ? bv : log1pf(expf(bv));
    float gv = gl[i];
    float g = 1.0f / (1.0f + expf(-gv));
    float vs = 0.0f;
    #pragma unroll
    for (int t = 0; t < 5; t++) {
        vs += 0.1f * (alpha * (0.0f - xs) - beta * vs + u);
        xs += 0.1f * g * vs;
    }
    x2[i] = x1[i] + xs;
}

// ---------------- launch ----------------------------------------------------
extern "C" void kernel_launch(void* const* d_in, const int* in_sizes, int n_in,
                              void* d_out, int out_size)
{
    const float* x          = (const float*)d_in[0];
    const float* ln_attn_w  = (const float*)d_in[1];
    const float* ln_attn_b  = (const float*)d_in[2];
    const float* attn_in_w  = (const float*)d_in[3];
    const float* attn_in_b  = (const float*)d_in[4];
    const float* attn_out_w = (const float*)d_in[5];
    const float* attn_out_b = (const float*)d_in[6];
    const float* ln1_w      = (const float*)d_in[7];
    const float* ln1_b      = (const float*)d_in[8];
    const float* ln2_w      = (const float*)d_in[9];
    const float* ln2_b      = (const float*)d_in[10];
    const float* inl_u_w    = (const float*)d_in[11];
    const float* inl_u_b    = (const float*)d_in[12];
    const float* inl_a_w    = (const float*)d_in[13];
    const float* inl_a_b    = (const float*)d_in[14];
    const float* inl_b_w    = (const float*)d_in[15];
    const float* inl_b_b    = (const float*)d_in[16];
    const float* inl_g_w    = (const float*)d_in[17];
    const float* inl_g_b    = (const float*)d_in[18];
    const float* ff1_w      = (const float*)d_in[19];
    const float* ff1_b      = (const float*)d_in[20];
    const float* ff2_w      = (const float*)d_in[21];
    const float* ff2_b      = (const float*)d_in[22];
    float* out = (float*)d_out;

    float *xn, *qkv, *att, *ctx, *x1, *u, *al, *be, *ga, *x2, *hbuf, *ffh;
    cudaGetSymbolAddress((void**)&xn,  g_xn);
    cudaGetSymbolAddress((void**)&qkv, g_qkv);
    cudaGetSymbolAddress((void**)&att, g_att);
    cudaGetSymbolAddress((void**)&ctx, g_ctx);
    cudaGetSymbolAddress((void**)&x1,  g_x1);
    cudaGetSymbolAddress((void**)&u,   g_u);
    cudaGetSymbolAddress((void**)&al,  g_al);
    cudaGetSymbolAddress((void**)&be,  g_be);
    cudaGetSymbolAddress((void**)&ga,  g_ga);
    cudaGetSymbolAddress((void**)&x2,  g_x2);
    cudaGetSymbolAddress((void**)&hbuf,g_h);
    cudaGetSymbolAddress((void**)&ffh, g_ffh);

    // 1) pre-attn LN
    layernorm_k<<<ROWS, 256>>>(x, ln_attn_w, ln_attn_b, xn);

    // 2) QKV projection
    gemm_nt<0><<<dim3(3*DD/GBN, ROWS/GBM), 256>>>(
        xn, attn_in_w, attn_in_b, qkv, ROWS, 3*DD, DD, nullptr, nullptr);

    // 3) causal flash attention
    cudaFuncSetAttribute(flash_attn_k,
        cudaFuncAttributeMaxDynamicSharedMemorySize, FA_SMEM);
    flash_attn_k<<<dim3(SS/64, HH, BB), 256, FA_SMEM>>>(qkv, att);

    // 4) out-projection; ctx = proj, x1 = x + proj
    gemm_nt<1><<<dim3(DD/GBN, ROWS/GBM), 256>>>(
        att, attn_out_w, attn_out_b, ctx, ROWS, DD, DD, x, x1);

    // 5) LN1(x1) -> xs0 (reuse xn)
    layernorm_k<<<ROWS, 256>>>(x1, ln1_w, ln1_b, xn);

    // 6) INL controller projections (linear + bias; activations fused later)
    gemm_nt<0><<<dim3(DD/GBN, ROWS/GBM), 256>>>(ctx, inl_u_w, inl_u_b, u,  ROWS, DD, DD, nullptr, nullptr);
    gemm_nt<0><<<dim3(DD/GBN, ROWS/GBM), 256>>>(ctx, inl_a_w, inl_a_b, al, ROWS, DD, DD, nullptr, nullptr);
    gemm_nt<0><<<dim3(DD/GBN, ROWS/GBM), 256>>>(ctx, inl_b_w, inl_b_b, be, ROWS, DD, DD, nullptr, nullptr);
    gemm_nt<0><<<dim3(DD/GBN, ROWS/GBM), 256>>>(ctx, inl_g_w, inl_g_b, ga, ROWS, DD, DD, nullptr, nullptr);

    // 7) fused INL dynamics: x2 = x1 + xs(5 steps)
    inl_k<<<(ROWS*(size_t)DD)/256, 256>>>(xn, u, al, be, ga, x1, x2);

    // 8) LN2(x2) -> h
    layernorm_k<<<ROWS, 256>>>(x2, ln2_w, ln2_b, hbuf);

    // 9) FF1 + exact GELU
    gemm_nt<2><<<dim3(FFD/GBN, ROWS/GBM), 256>>>(
        hbuf, ff1_w, ff1_b, ffh, ROWS, FFD, DD, nullptr, nullptr);

    // 10) FF2 + bias + residual -> out
    gemm_nt<3><<<dim3(DD/GBN, ROWS/GBM), 256>>>(
        ffh, ff2_w, ff2_b, out, ROWS, DD, FFD, x2, nullptr);
}

// round 6
// speedup vs baseline: 2.0342x; 2.0342x over previous
#include <cuda_runtime.h>
#include <cuda_bf16.h>
#include <cstdint>
#include <math.h>

// Problem constants
#define BB   4
#define SS   2048
#define DD   1024
#define HH   16
#define DHD  64
#define FFD  4096
#define ROWS (BB*SS)

// ---------------- scratch (device globals; no allocation allowed) ----------
__device__ float g_xn [(size_t)ROWS*DD];
__device__ float g_qkv[(size_t)ROWS*3*DD];
__device__ float g_att[(size_t)ROWS*DD];
__device__ float g_ctx[(size_t)ROWS*DD];
__device__ float g_x1 [(size_t)ROWS*DD];
__device__ float g_u  [(size_t)ROWS*DD];
__device__ float g_al [(size_t)ROWS*DD];
__device__ float g_be [(size_t)ROWS*DD];
__device__ float g_ga [(size_t)ROWS*DD];
__device__ float g_x2 [(size_t)ROWS*DD];
__device__ float g_h  [(size_t)ROWS*DD];
__device__ float g_ffh[(size_t)ROWS*FFD];

// ---------------- LayerNorm ------------------------------------------------
__global__ void __launch_bounds__(256) layernorm_k(
    const float* __restrict__ x, const float* __restrict__ w,
    const float* __restrict__ b, float* __restrict__ y)
{
    int row = blockIdx.x;
    const float* xr = x + (size_t)row * DD;
    int tid = threadIdx.x;
    float4 v = *reinterpret_cast<const float4*>(xr + tid * 4);
    float s  = v.x + v.y + v.z + v.w;
    float ss = v.x*v.x + v.y*v.y + v.z*v.z + v.w*v.w;
    #pragma unroll
    for (int off = 16; off > 0; off >>= 1) {
        s  += __shfl_xor_sync(0xffffffffu, s,  off);
        ss += __shfl_xor_sync(0xffffffffu, ss, off);
    }
    __shared__ float sh_s[8];
    __shared__ float sh_ss[8];
    int wid = tid >> 5;
    int lane = tid & 31;
    if (lane == 0) { sh_s[wid] = s; sh_ss[wid] = ss; }
    __syncthreads();
    float ts = 0.f, tss = 0.f;
    #pragma unroll
    for (int i = 0; i < 8; i++) { ts += sh_s[i]; tss += sh_ss[i]; }
    float mu   = ts * (1.0f / DD);
    float var  = tss * (1.0f / DD) - mu * mu;
    float rstd = rsqrtf(var + 1e-5f);
    float4 wv = *reinterpret_cast<const float4*>(w + tid * 4);
    float4 bv = *reinterpret_cast<const float4*>(b + tid * 4);
    float4 o;
    o.x = (v.x - mu) * rstd * wv.x + bv.x;
    o.y = (v.y - mu) * rstd * wv.y + bv.y;
    o.z = (v.z - mu) * rstd * wv.z + bv.z;
    o.w = (v.w - mu) * rstd * wv.w + bv.w;
    *reinterpret_cast<float4*>(y + (size_t)row * DD + tid * 4) = o;
}

// ============================================================================
// Tensor-core GEMM: C[M,N] = A[M,K] @ B[N,K]^T, fp32 via bf16 hi/lo split.
// Block tile 128x128x32, 256 threads (8 warps, 2x4), warp tile 64x32.
// 3 mma per k16 step: hi*hi + hi*lo + lo*hi, fp32 accumulate.
// EPI: 0 bias; 1 dual (C=v+bias, C2=res+v+bias); 2 bias+GELU; 3 bias+res.
// ============================================================================
#define TBM 128
#define TBN 128
#define TBK 32
#define STG_U4 2048
#define OFF_AHI 0
#define OFF_ALO 512
#define OFF_BHI 1024
#define OFF_BLO 1536
#define TC_SMEM (2 * STG_U4 * 16)

__device__ __forceinline__ void ldsm4(unsigned &r0, unsigned &r1,
                                      unsigned &r2, unsigned &r3,
                                      unsigned addr)
{
    asm volatile(
        "ldmatrix.sync.aligned.m8n8.x4.shared.b16 {%0,%1,%2,%3}, [%4];\n"
        : "=r"(r0), "=r"(r1), "=r"(r2), "=r"(r3)
        : "r"(addr));
}

__device__ __forceinline__ void mma16816(float* c,
    unsigned a0, unsigned a1, unsigned a2, unsigned a3,
    unsigned b0, unsigned b1)
{
    asm volatile(
        "mma.sync.aligned.m16n8k16.row.col.f32.bf16.bf16.f32 "
        "{%0,%1,%2,%3}, {%4,%5,%6,%7}, {%8,%9}, {%0,%1,%2,%3};\n"
        : "+f"(c[0]), "+f"(c[1]), "+f"(c[2]), "+f"(c[3])
        : "r"(a0), "r"(a1), "r"(a2), "r"(a3), "r"(b0), "r"(b1));
}

__device__ __forceinline__ void bsplit2(float x, float y,
                                        unsigned &h, unsigned &l)
{
    __nv_bfloat162 hb = __floats2bfloat162_rn(x, y);
    float hx = __bfloat162float(hb.x);
    float hy = __bfloat162float(hb.y);
    __nv_bfloat162 lb = __floats2bfloat162_rn(x - hx, y - hy);
    h = *reinterpret_cast<unsigned*>(&hb);
    l = *reinterpret_cast<unsigned*>(&lb);
}

__device__ __forceinline__ void conv16(const float4* r,
                                       uint4 &h0, uint4 &l0,
                                       uint4 &h1, uint4 &l1)
{
    bsplit2(r[0].x, r[0].y, h0.x, l0.x);
    bsplit2(r[0].z, r[0].w, h0.y, l0.y);
    bsplit2(r[1].x, r[1].y, h0.z, l0.z);
    bsplit2(r[1].z, r[1].w, h0.w, l0.w);
    bsplit2(r[2].x, r[2].y, h1.x, l1.x);
    bsplit2(r[2].z, r[2].w, h1.y, l1.y);
    bsplit2(r[3].x, r[3].y, h1.z, l1.z);
    bsplit2(r[3].z, r[3].w, h1.w, l1.w);
}

template<int EPI>
__global__ void __launch_bounds__(256, 1) gemm_tc(
    const float* __restrict__ A, const float* __restrict__ B,
    const float* __restrict__ bias, float* __restrict__ C,
    int M, int N, int K,
    const float* __restrict__ res, float* __restrict__ C2)
{
    extern __shared__ uint4 sm4[];
    const int tid  = threadIdx.x;
    const int lane = tid & 31;
    const int warp = tid >> 5;
    const int wm   = warp >> 2;
    const int wn   = warp & 3;
    const int bm   = blockIdx.y * TBM;
    const int bn   = blockIdx.x * TBN;

    const unsigned smem_base =
        (unsigned)__cvta_generic_to_shared((void*)sm4);

    // writer indexing: thread -> (row 0..127, k-half 0..1)
    const int wrow  = tid >> 1;
    const int whalf = tid & 1;
    const int wswz  = (wrow >> 1) & 3;
    const int wc0   = (2 * whalf)     ^ wswz;
    const int wc1   = (2 * whalf + 1) ^ wswz;

    const float* Ag = A + (size_t)(bm + wrow) * K + whalf * 16;
    const float* Bg = B + (size_t)(bn + wrow) * K + whalf * 16;

    float acc[4][4][4];
    #pragma unroll
    for (int i = 0; i < 4; i++) {
        #pragma unroll
        for (int j = 0; j < 4; j++) {
            #pragma unroll
            for (int q = 0; q < 4; q++) {
                acc[i][j][q] = 0.f;
            }
        }
    }

    // reader indexing (loop-invariant)
    const int ar      = lane & 15;
    const int aswz    = (ar >> 1) & 3;
    const int acolsel = lane >> 4;
    const int br      = (lane & 7) | ((lane >> 4) << 3);
    const int bswz    = (br >> 1) & 3;
    const int bcolsel = (lane >> 3) & 1;

    float4 ra[4];
    float4 rb[4];
    #pragma unroll
    for (int q = 0; q < 4; q++) {
        ra[q] = *reinterpret_cast<const float4*>(Ag + q * 4);
        rb[q] = *reinterpret_cast<const float4*>(Bg + q * 4);
    }

    const int nk = K / TBK;
    for (int kt = 0; kt < nk; ++kt) {
        const int stBase = (kt & 1) * STG_U4;

        // store staged registers to smem (hi/lo planes, swizzled)
        {
            uint4 h0, l0, h1, l1;
            conv16(ra, h0, l0, h1, l1);
            sm4[stBase + OFF_AHI + wrow * 4 + wc0] = h0;
            sm4[stBase + OFF_AHI + wrow * 4 + wc1] = h1;
            sm4[stBase + OFF_ALO + wrow * 4 + wc0] = l0;
            sm4[stBase + OFF_ALO + wrow * 4 + wc1] = l1;
            conv16(rb, h0, l0, h1, l1);
            sm4[stBase + OFF_BHI + wrow * 4 + wc0] = h0;
            sm4[stBase + OFF_BHI + wrow * 4 + wc1] = h1;
            sm4[stBase + OFF_BLO + wrow * 4 + wc0] = l0;
            sm4[stBase + OFF_BLO + wrow * 4 + wc1] = l1;
        }
        __syncthreads();

        // prefetch next k-tile from global
        if (kt + 1 < nk) {
            Ag += TBK;
            Bg += TBK;
            #pragma unroll
            for (int q = 0; q < 4; q++) {
                ra[q] = *reinterpret_cast<const float4*>(Ag + q * 4);
                rb[q] = *reinterpret_cast<const float4*>(Bg + q * 4);
            }
        }

        // two k16 steps per stage
        #pragma unroll
        for (int s = 0; s < 2; s++) {
            const int acol = (2 * s + acolsel) ^ aswz;
            const int bcol = (2 * s + bcolsel) ^ bswz;

            unsigned ahi[4][4];
            unsigned alo[4][4];
            #pragma unroll
            for (int i = 0; i < 4; i++) {
                int row = wm * 64 + i * 16 + ar;
                unsigned ad = smem_base +
                    (unsigned)((stBase + OFF_AHI + row * 4 + acol) << 4);
                ldsm4(ahi[i][0], ahi[i][1], ahi[i][2], ahi[i][3], ad);
                ldsm4(alo[i][0], alo[i][1], alo[i][2], alo[i][3],
                      ad + (unsigned)((OFF_ALO - OFF_AHI) << 4));
            }
            unsigned bhi[4][2];
            unsigned blo[4][2];
            #pragma unroll
            for (int p = 0; p < 2; p++) {
                int row = wn * 32 + p * 16 + br;
                unsigned ad = smem_base +
                    (unsigned)((stBase + OFF_BHI + row * 4 + bcol) << 4);
                unsigned t0, t1, t2, t3;
                ldsm4(t0, t1, t2, t3, ad);
                bhi[2*p][0]   = t0;
                bhi[2*p][1]   = t1;
                bhi[2*p+1][0] = t2;
                bhi[2*p+1][1] = t3;
                ldsm4(t0, t1, t2, t3,
                      ad + (unsigned)((OFF_BLO - OFF_BHI) << 4));
                blo[2*p][0]   = t0;
                blo[2*p][1]   = t1;
                blo[2*p+1][0] = t2;
                blo[2*p+1][1] = t3;
            }
            #pragma unroll
            for (int i = 0; i < 4; i++) {
                #pragma unroll
                for (int j = 0; j < 4; j++) {
                    mma16816(acc[i][j],
                             ahi[i][0], ahi[i][1], ahi[i][2], ahi[i][3],
                             bhi[j][0], bhi[j][1]);
                    mma16816(acc[i][j],
                             ahi[i][0], ahi[i][1], ahi[i][2], ahi[i][3],
                             blo[j][0], blo[j][1]);
                    mma16816(acc[i][j],
                             alo[i][0], alo[i][1], alo[i][2], alo[i][3],
                             bhi[j][0], bhi[j][1]);
                }
            }
        }
        __syncthreads();
    }

    // epilogue
    const int rg = lane >> 2;
    const int q2 = (lane & 3) * 2;
    #pragma unroll
    for (int i = 0; i < 4; i++) {
        int r0 = bm + wm * 64 + i * 16 + rg;
        int r1 = r0 + 8;
        #pragma unroll
        for (int j = 0; j < 4; j++) {
            int col = bn + wn * 32 + j * 8 + q2;
            float b0 = bias[col];
            float b1 = bias[col + 1];
            float v0 = acc[i][j][0] + b0;
            float v1 = acc[i][j][1] + b1;
            float v2 = acc[i][j][2] + b0;
            float v3 = acc[i][j][3] + b1;
            size_t p0 = (size_t)r0 * N + col;
            size_t p1 = (size_t)r1 * N + col;
            if (EPI == 2) {
                v0 = 0.5f * v0 * (1.0f + erff(v0 * 0.70710678118654752f));
                v1 = 0.5f * v1 * (1.0f + erff(v1 * 0.70710678118654752f));
                v2 = 0.5f * v2 * (1.0f + erff(v2 * 0.70710678118654752f));
                v3 = 0.5f * v3 * (1.0f + erff(v3 * 0.70710678118654752f));
            }
            if (EPI == 3) {
                v0 += res[p0];
                v1 += res[p0 + 1];
                v2 += res[p1];
                v3 += res[p1 + 1];
            }
            C[p0]     = v0;
            C[p0 + 1] = v1;
            C[p1]     = v2;
            C[p1 + 1] = v3;
            if (EPI == 1) {
                C2[p0]     = res[p0]     + v0;
                C2[p0 + 1] = res[p0 + 1] + v1;
                C2[p1]     = res[p1]     + v2;
                C2[p1 + 1] = res[p1 + 1] + v3;
            }
        }
    }
}

// ---------------- Causal flash attention, fp32, dh=64 ----------------------
#define FA_PAD 65
#define FA_SMEM (4 * 64 * FA_PAD * (int)sizeof(float))

__global__ void __launch_bounds__(256) flash_attn_k(
    const float* __restrict__ qkv, float* __restrict__ out)
{
    extern __shared__ float sm[];
    float* Qs = sm;
    float* Ks = sm + 64 * FA_PAD;
    float* Vs = sm + 2 * 64 * FA_PAD;
    float* Ps = sm + 3 * 64 * FA_PAD;

    int qt = blockIdx.x;
    int h  = blockIdx.y;
    int b  = blockIdx.z;
    int tid = threadIdx.x;
    int tx = tid & 15;
    int ty = tid >> 4;

    const size_t rstride = 3 * DD;
    const float* Qbase = qkv + ((size_t)b * SS + qt * 64) * rstride + h * DHD;
    const float* Kbase = qkv + (size_t)b * SS * rstride + DD     + h * DHD;
    const float* Vbase = qkv + (size_t)b * SS * rstride + 2 * DD + h * DHD;
    const float scale = 0.125f;

    for (int i = tid; i < 64 * 16; i += 256) {
        int r = i >> 4;
        int c = (i & 15) << 2;
        float4 v = *reinterpret_cast<const float4*>(Qbase + (size_t)r * rstride + c);
        Qs[r*FA_PAD + c+0] = v.x * scale;
        Qs[r*FA_PAD + c+1] = v.y * scale;
        Qs[r*FA_PAD + c+2] = v.z * scale;
        Qs[r*FA_PAD + c+3] = v.w * scale;
    }

    float m[4], l[4], o[4][4];
    #pragma unroll
    for (int i = 0; i < 4; i++) {
        m[i] = -INFINITY;
        l[i] = 0.f;
        #pragma unroll
        for (int j = 0; j < 4; j++) o[i][j] = 0.f;
    }

    int nkt = qt + 1;
    for (int kt = 0; kt < nkt; kt++) {
        __syncthreads();
        for (int i = tid; i < 64 * 16; i += 256) {
            int r = i >> 4;
            int c = (i & 15) << 2;
            size_t goff = (size_t)(kt * 64 + r) * rstride + c;
            float4 kv = *reinterpret_cast<const float4*>(Kbase + goff);
            Ks[r*FA_PAD + c+0] = kv.x;
            Ks[r*FA_PAD + c+1] = kv.y;
            Ks[r*FA_PAD + c+2] = kv.z;
            Ks[r*FA_PAD + c+3] = kv.w;
            float4 vv = *reinterpret_cast<const float4*>(Vbase + goff);
            Vs[r*FA_PAD + c+0] = vv.x;
            Vs[r*FA_PAD + c+1] = vv.y;
            Vs[r*FA_PAD + c+2] = vv.z;
            Vs[r*FA_PAD + c+3] = vv.w;
        }
        __syncthreads();

        float s[4][4];
        #pragma unroll
        for (int i = 0; i < 4; i++) {
            #pragma unroll
            for (int j = 0; j < 4; j++) s[i][j] = 0.f;
        }

        #pragma unroll 8
        for (int d = 0; d < 64; d++) {
            float qa[4], kb[4];
            #pragma unroll
            for (int i = 0; i < 4; i++) qa[i] = Qs[(ty*4 + i)*FA_PAD + d];
            #pragma unroll
            for (int j = 0; j < 4; j++) kb[j] = Ks[(tx*4 + j)*FA_PAD + d];
            #pragma unroll
            for (int i = 0; i < 4; i++) {
                #pragma unroll
                for (int j = 0; j < 4; j++)
                    s[i][j] = fmaf(qa[i], kb[j], s[i][j]);
            }
        }

        if (kt == qt) {
            #pragma unroll
            for (int i = 0; i < 4; i++) {
                #pragma unroll
                for (int j = 0; j < 4; j++) {
                    if (tx*4 + j > ty*4 + i) s[i][j] = -1e30f;
                }
            }
        }

        #pragma unroll
        for (int i = 0; i < 4; i++) {
            float rm = fmaxf(fmaxf(s[i][0], s[i][1]), fmaxf(s[i][2], s[i][3]));
            #pragma unroll
            for (int off = 8; off > 0; off >>= 1)
                rm = fmaxf(rm, __shfl_xor_sync(0xffffffffu, rm, off));
            float mn = fmaxf(m[i], rm);
            float corr = __expf(m[i] - mn);
            float ps = 0.f;
            #pragma unroll
            for (int j = 0; j < 4; j++) {
                float p = __expf(s[i][j] - mn);
                Ps[(ty*4 + i)*FA_PAD + tx*4 + j] = p;
                ps += p;
            }
            #pragma unroll
            for (int off = 8; off > 0; off >>= 1)
                ps += __shfl_xor_sync(0xffffffffu, ps, off);
            l[i] = l[i] * corr + ps;
            m[i] = mn;
            #pragma unroll
            for (int j = 0; j < 4; j++) o[i][j] *= corr;
        }
        __syncthreads();

        #pragma unroll 8
        for (int kk = 0; kk < 64; kk++) {
            float p[4], vv[4];
            #pragma unroll
            for (int i = 0; i < 4; i++) p[i]  = Ps[(ty*4 + i)*FA_PAD + kk];
            #pragma unroll
            for (int j = 0; j < 4; j++) vv[j] = Vs[kk*FA_PAD + tx*4 + j];
            #pragma unroll
            for (int i = 0; i < 4; i++) {
                #pragma unroll
                for (int j = 0; j < 4; j++)
                    o[i][j] = fmaf(p[i], vv[j], o[i][j]);
            }
        }
    }

    #pragma unroll
    for (int i = 0; i < 4; i++) {
        float invl = 1.0f / l[i];
        size_t orow = ((size_t)b * SS + qt * 64 + ty*4 + i) * DD + h * DHD + tx*4;
        #pragma unroll
        for (int j = 0; j < 4; j++)
            out[orow + j] = o[i][j] * invl;
    }
}

// ---------------- INL integrator: fused elementwise -------------------------
__global__ void __launch_bounds__(256) inl_k(
    const float* __restrict__ xs0, const float* __restrict__ ul,
    const float* __restrict__ al,  const float* __restrict__ bl,
    const float* __restrict__ gl,  const float* __restrict__ x1,
    float* __restrict__ x2)
{
    size_t i = (size_t)blockIdx.x * blockDim.x + threadIdx.x;
    float xs = xs0[i];
    float u  = ul[i];
    float av = al[i];
    float alpha = 1.0f / (1.0f + expf(-av));
    float bv = bl[i];
    float beta = (bv > 20.0f) ? bv : log1pf(expf(bv));
    float gv = gl[i];
    float g = 1.0f / (1.0f + expf(-gv));
    float vs = 0.0f;
    #pragma unroll
    for (int t = 0; t < 5; t++) {
        vs += 0.1f * (alpha * (0.0f - xs) - beta * vs + u);
        xs += 0.1f * g * vs;
    }
    x2[i] = x1[i] + xs;
}

// ---------------- launch ----------------------------------------------------
extern "C" void kernel_launch(void* const* d_in, const int* in_sizes, int n_in,
                              void* d_out, int out_size)
{
    const float* x          = (const float*)d_in[0];
    const float* ln_attn_w  = (const float*)d_in[1];
    const float* ln_attn_b  = (const float*)d_in[2];
    const float* attn_in_w  = (const float*)d_in[3];
    const float* attn_in_b  = (const float*)d_in[4];
    const float* attn_out_w = (const float*)d_in[5];
    const float* attn_out_b = (const float*)d_in[6];
    const float* ln1_w      = (const float*)d_in[7];
    const float* ln1_b      = (const float*)d_in[8];
    const float* ln2_w      = (const float*)d_in[9];
    const float* ln2_b      = (const float*)d_in[10];
    const float* inl_u_w    = (const float*)d_in[11];
    const float* inl_u_b    = (const float*)d_in[12];
    const float* inl_a_w    = (const float*)d_in[13];
    const float* inl_a_b    = (const float*)d_in[14];
    const float* inl_b_w    = (const float*)d_in[15];
    const float* inl_b_b    = (const float*)d_in[16];
    const float* inl_g_w    = (const float*)d_in[17];
    const float* inl_g_b    = (const float*)d_in[18];
    const float* ff1_w      = (const float*)d_in[19];
    const float* ff1_b      = (const float*)d_in[20];
    const float* ff2_w      = (const float*)d_in[21];
    const float* ff2_b      = (const float*)d_in[22];
    float* out = (float*)d_out;

    float* xn   = 0;
    float* qkv  = 0;
    float* att  = 0;
    float* ctx  = 0;
    float* x1   = 0;
    float* u    = 0;
    float* al   = 0;
    float* be   = 0;
    float* ga   = 0;
    float* x2   = 0;
    float* hbuf = 0;
    float* ffh  = 0;
    cudaGetSymbolAddress((void**)&xn,   g_xn);
    cudaGetSymbolAddress((void**)&qkv,  g_qkv);
    cudaGetSymbolAddress((void**)&att,  g_att);
    cudaGetSymbolAddress((void**)&ctx,  g_ctx);
    cudaGetSymbolAddress((void**)&x1,   g_x1);
    cudaGetSymbolAddress((void**)&u,    g_u);
    cudaGetSymbolAddress((void**)&al,   g_al);
    cudaGetSymbolAddress((void**)&be,   g_be);
    cudaGetSymbolAddress((void**)&ga,   g_ga);
    cudaGetSymbolAddress((void**)&x2,   g_x2);
    cudaGetSymbolAddress((void**)&hbuf, g_h);
    cudaGetSymbolAddress((void**)&ffh,  g_ffh);

    cudaFuncSetAttribute(gemm_tc<0>,
        cudaFuncAttributeMaxDynamicSharedMemorySize, TC_SMEM);
    cudaFuncSetAttribute(gemm_tc<1>,
        cudaFuncAttributeMaxDynamicSharedMemorySize, TC_SMEM);
    cudaFuncSetAttribute(gemm_tc<2>,
        cudaFuncAttributeMaxDynamicSharedMemorySize, TC_SMEM);
    cudaFuncSetAttribute(gemm_tc<3>,
        cudaFuncAttributeMaxDynamicSharedMemorySize, TC_SMEM);
    cudaFuncSetAttribute(flash_attn_k,
        cudaFuncAttributeMaxDynamicSharedMemorySize, FA_SMEM);

    // 1) pre-attn LN
    layernorm_k<<<ROWS, 256>>>(x, ln_attn_w, ln_attn_b, xn);

    // 2) QKV projection
    gemm_tc<0><<<dim3(3*DD/TBN, ROWS/TBM), 256, TC_SMEM>>>(
        xn, attn_in_w, attn_in_b, qkv, ROWS, 3*DD, DD, (const float*)0, (float*)0);

    // 3) causal flash attention
    flash_attn_k<<<dim3(SS/64, HH, BB), 256, FA_SMEM>>>(qkv, att);

    // 4) out-projection; ctx = proj, x1 = x + proj
    gemm_tc<1><<<dim3(DD/TBN, ROWS/TBM), 256, TC_SMEM>>>(
        att, attn_out_w, attn_out_b, ctx, ROWS, DD, DD, x, x1);

    // 5) LN1(x1) -> xs0 (reuse xn)
    layernorm_k<<<ROWS, 256>>>(x1, ln1_w, ln1_b, xn);

    // 6) INL controller projections
    gemm_tc<0><<<dim3(DD/TBN, ROWS/TBM), 256, TC_SMEM>>>(
        ctx, inl_u_w, inl_u_b, u,  ROWS, DD, DD, (const float*)0, (float*)0);
    gemm_tc<0><<<dim3(DD/TBN, ROWS/TBM), 256, TC_SMEM>>>(
        ctx, inl_a_w, inl_a_b, al, ROWS, DD, DD, (const float*)0, (float*)0);
    gemm_tc<0><<<dim3(DD/TBN, ROWS/TBM), 256, TC_SMEM>>>(
        ctx, inl_b_w, inl_b_b, be, ROWS, DD, DD, (const float*)0, (float*)0);
    gemm_tc<0><<<dim3(DD/TBN, ROWS/TBM), 256, TC_SMEM>>>(
        ctx, inl_g_w, inl_g_b, ga, ROWS, DD, DD, (const float*)0, (float*)0);

    // 7) fused INL dynamics: x2 = x1 + xs(5 steps)
    inl_k<<<(ROWS*(size_t)DD)/256, 256>>>(xn, u, al, be, ga, x1, x2);

    // 8) LN2(x2) -> h
    layernorm_k<<<ROWS, 256>>>(x2, ln2_w, ln2_b, hbuf);

    // 9) FF1 + exact GELU
    gemm_tc<2><<<dim3(FFD/TBN, ROWS/TBM), 256, TC_SMEM>>>(
        hbuf, ff1_w, ff1_b, ffh, ROWS, FFD, DD, (const float*)0, (float*)0);

    // 10) FF2 + bias + residual -> out
    gemm_tc<3><<<dim3(DD/TBN, ROWS/TBM), 256, TC_SMEM>>>(
        ffh, ff2_w, ff2_b, out, ROWS, DD, FFD, x2, (float*)0);
}

// round 7
// speedup vs baseline: 2.5050x; 1.2315x over previous
#include <cuda_runtime.h>
#include <cuda_bf16.h>
#include <cstdint>
#include <math.h>

// Problem constants
#define BB   4
#define SS   2048
#define DD   1024
#define HH   16
#define DHD  64
#define FFD  4096
#define ROWS (BB*SS)

// ---------------- scratch (device globals; no allocation allowed) ----------
// bf16 hi/lo planes for GEMM A-inputs
__device__ __nv_bfloat16 g_xn_hi [(size_t)ROWS*DD];
__device__ __nv_bfloat16 g_xn_lo [(size_t)ROWS*DD];
__device__ __nv_bfloat16 g_att_hi[(size_t)ROWS*DD];
__device__ __nv_bfloat16 g_att_lo[(size_t)ROWS*DD];
__device__ __nv_bfloat16 g_ctx_hi[(size_t)ROWS*DD];
__device__ __nv_bfloat16 g_ctx_lo[(size_t)ROWS*DD];
__device__ __nv_bfloat16 g_h_hi  [(size_t)ROWS*DD];
__device__ __nv_bfloat16 g_h_lo  [(size_t)ROWS*DD];
__device__ __nv_bfloat16 g_ffh_hi[(size_t)ROWS*FFD];
__device__ __nv_bfloat16 g_ffh_lo[(size_t)ROWS*FFD];
// weight planes (all weights concatenated):
//  [0,3M) attn_in | [3M,4M) attn_out | [4M,5M) inl_u | [5M,6M) inl_a
//  [6M,7M) inl_b | [7M,8M) inl_g | [8M,12M) ff1 | [12M,16M) ff2
#define W_TOTAL ((size_t)16*1024*1024)
#define WOFF_ATTNIN  ((size_t)0)
#define WOFF_ATTNOUT ((size_t)3*1024*1024)
#define WOFF_INL     ((size_t)4*1024*1024)
#define WOFF_FF1     ((size_t)8*1024*1024)
#define WOFF_FF2     ((size_t)12*1024*1024)
__device__ __nv_bfloat16 g_w_hi[W_TOTAL];
__device__ __nv_bfloat16 g_w_lo[W_TOTAL];
__device__ float g_bcat[4*DD];
// fp32 intermediates
__device__ float g_qkv[(size_t)ROWS*3*DD];
__device__ float g_x1 [(size_t)ROWS*DD];
__device__ float g_xs0[(size_t)ROWS*DD];
__device__ float g_inl[(size_t)ROWS*4*DD];
__device__ float g_x2 [(size_t)ROWS*DD];

// ---------------- helpers ---------------------------------------------------
__device__ __forceinline__ void wplane2(__nv_bfloat16* hi, __nv_bfloat16* lo,
                                        size_t idx, float v0, float v1)
{
    __nv_bfloat162 h = __floats2bfloat162_rn(v0, v1);
    float h0 = __bfloat162float(h.x);
    float h1 = __bfloat162float(h.y);
    __nv_bfloat162 l = __floats2bfloat162_rn(v0 - h0, v1 - h1);
    *reinterpret_cast<__nv_bfloat162*>(hi + idx) = h;
    *reinterpret_cast<__nv_bfloat162*>(lo + idx) = l;
}

// ---------------- weight conversion (all weights, one kernel) --------------
__global__ void __launch_bounds__(256) conv_w_k(
    const float* __restrict__ attn_in_w, const float* __restrict__ attn_out_w,
    const float* __restrict__ inl_u_w,   const float* __restrict__ inl_a_w,
    const float* __restrict__ inl_b_w,   const float* __restrict__ inl_g_w,
    const float* __restrict__ ff1_w,     const float* __restrict__ ff2_w)
{
    size_t e = ((size_t)blockIdx.x * 256 + threadIdx.x) * 2;  // element idx
    const float* src;
    size_t off;
    if      (e < WOFF_ATTNOUT) { src = attn_in_w;  off = e - WOFF_ATTNIN; }
    else if (e < WOFF_INL)     { src = attn_out_w; off = e - WOFF_ATTNOUT; }
    else if (e < WOFF_INL + (size_t)1024*1024)   { src = inl_u_w; off = e - WOFF_INL; }
    else if (e < WOFF_INL + (size_t)2*1024*1024) { src = inl_a_w; off = e - WOFF_INL - (size_t)1024*1024; }
    else if (e < WOFF_INL + (size_t)3*1024*1024) { src = inl_b_w; off = e - WOFF_INL - (size_t)2*1024*1024; }
    else if (e < WOFF_FF1)     { src = inl_g_w; off = e - WOFF_INL - (size_t)3*1024*1024; }
    else if (e < WOFF_FF2)     { src = ff1_w;   off = e - WOFF_FF1; }
    else                       { src = ff2_w;   off = e - WOFF_FF2; }
    float2 v = *reinterpret_cast<const float2*>(src + off);
    wplane2(g_w_hi, g_w_lo, e, v.x, v.y);
}

__global__ void bias_cat_k(const float* __restrict__ ub, const float* __restrict__ ab,
                           const float* __restrict__ bb, const float* __restrict__ gb)
{
    int i = blockIdx.x * 256 + threadIdx.x;   // 0..4095
    int sel = i >> 10;
    int c = i & 1023;
    float v;
    if (sel == 0) v = ub[c];
    else if (sel == 1) v = ab[c];
    else if (sel == 2) v = bb[c];
    else v = gb[c];
    g_bcat[i] = v;
}

// ---------------- LayerNorm (fp32 out) --------------------------------------
__global__ void __launch_bounds__(256) layernorm_f(
    const float* __restrict__ x, const float* __restrict__ w,
    const float* __restrict__ b, float* __restrict__ y)
{
    int row = blockIdx.x;
    const float* xr = x + (size_t)row * DD;
    int tid = threadIdx.x;
    float4 v = *reinterpret_cast<const float4*>(xr + tid * 4);
    float s  = v.x + v.y + v.z + v.w;
    float ss = v.x*v.x + v.y*v.y + v.z*v.z + v.w*v.w;
    #pragma unroll
    for (int off = 16; off > 0; off >>= 1) {
        s  += __shfl_xor_sync(0xffffffffu, s,  off);
        ss += __shfl_xor_sync(0xffffffffu, ss, off);
    }
    __shared__ float sh_s[8];
    __shared__ float sh_ss[8];
    int wid = tid >> 5;
    int lane = tid & 31;
    if (lane == 0) { sh_s[wid] = s; sh_ss[wid] = ss; }
    __syncthreads();
    float ts = 0.f, tss = 0.f;
    #pragma unroll
    for (int i = 0; i < 8; i++) { ts += sh_s[i]; tss += sh_ss[i]; }
    float mu   = ts * (1.0f / DD);
    float var  = tss * (1.0f / DD) - mu * mu;
    float rstd = rsqrtf(var + 1e-5f);
    float4 wv = *reinterpret_cast<const float4*>(w + tid * 4);
    float4 bv = *reinterpret_cast<const float4*>(b + tid * 4);
    float4 o;
    o.x = (v.x - mu) * rstd * wv.x + bv.x;
    o.y = (v.y - mu) * rstd * wv.y + bv.y;
    o.z = (v.z - mu) * rstd * wv.z + bv.z;
    o.w = (v.w - mu) * rstd * wv.w + bv.w;
    *reinterpret_cast<float4*>(y + (size_t)row * DD + tid * 4) = o;
}

// ---------------- LayerNorm (bf16 hi/lo plane out) --------------------------
__global__ void __launch_bounds__(256) layernorm_p(
    const float* __restrict__ x, const float* __restrict__ w,
    const float* __restrict__ b,
    __nv_bfloat16* __restrict__ yhi, __nv_bfloat16* __restrict__ ylo)
{
    int row = blockIdx.x;
    const float* xr = x + (size_t)row * DD;
    int tid = threadIdx.x;
    float4 v = *reinterpret_cast<const float4*>(xr + tid * 4);
    float s  = v.x + v.y + v.z + v.w;
    float ss = v.x*v.x + v.y*v.y + v.z*v.z + v.w*v.w;
    #pragma unroll
    for (int off = 16; off > 0; off >>= 1) {
        s  += __shfl_xor_sync(0xffffffffu, s,  off);
        ss += __shfl_xor_sync(0xffffffffu, ss, off);
    }
    __shared__ float sh_s[8];
    __shared__ float sh_ss[8];
    int wid = tid >> 5;
    int lane = tid & 31;
    if (lane == 0) { sh_s[wid] = s; sh_ss[wid] = ss; }
    __syncthreads();
    float ts = 0.f, tss = 0.f;
    #pragma unroll
    for (int i = 0; i < 8; i++) { ts += sh_s[i]; tss += sh_ss[i]; }
    float mu   = ts * (1.0f / DD);
    float var  = tss * (1.0f / DD) - mu * mu;
    float rstd = rsqrtf(var + 1e-5f);
    float4 wv = *reinterpret_cast<const float4*>(w + tid * 4);
    float4 bv = *reinterpret_cast<const float4*>(b + tid * 4);
    float o0 = (v.x - mu) * rstd * wv.x + bv.x;
    float o1 = (v.y - mu) * rstd * wv.y + bv.y;
    float o2 = (v.z - mu) * rstd * wv.z + bv.z;
    float o3 = (v.w - mu) * rstd * wv.w + bv.w;
    size_t base = (size_t)row * DD + tid * 4;
    wplane2(yhi, ylo, base,     o0, o1);
    wplane2(yhi, ylo, base + 2, o2, o3);
}

// ============================================================================
// Tensor-core GEMM on pre-split bf16 hi/lo planes.
// C[M,N] = A[M,K] @ B[N,K]^T (fp32-accurate via hi*hi + hi*lo + lo*hi)
// Block tile 128x128x32, 128 threads (4 warps 2x2), warp tile 64x64.
// cp.async double-buffered smem; XOR-swizzled 64B rows.
// EPI: 0 fp32+bias; 1 planes(v+bias) + C2=res+v; 2 planes(GELU(v+bias));
//      3 fp32 = v+bias+res.
// ============================================================================
#define STG_U4 2048              // 4 planes * 512 chunks of 16B
#define GEM_SMEM (2 * STG_U4 * 16)

#define CP16(d, s) asm volatile("cp.async.cg.shared.global [%0], [%1], 16;\n" :: "r"(d), "l"(s))
#define CP_COMMIT() asm volatile("cp.async.commit_group;\n" ::)
#define CP_WAIT1() asm volatile("cp.async.wait_group 1;\n" ::)

__device__ __forceinline__ void ldsm4(unsigned &r0, unsigned &r1,
                                      unsigned &r2, unsigned &r3,
                                      unsigned addr)
{
    asm volatile(
        "ldmatrix.sync.aligned.m8n8.x4.shared.b16 {%0,%1,%2,%3}, [%4];\n"
        : "=r"(r0), "=r"(r1), "=r"(r2), "=r"(r3)
        : "r"(addr));
}

__device__ __forceinline__ void mma16816(float* c,
    unsigned a0, unsigned a1, unsigned a2, unsigned a3,
    unsigned b0, unsigned b1)
{
    asm volatile(
        "mma.sync.aligned.m16n8k16.row.col.f32.bf16.bf16.f32 "
        "{%0,%1,%2,%3}, {%4,%5,%6,%7}, {%8,%9}, {%0,%1,%2,%3};\n"
        : "+f"(c[0]), "+f"(c[1]), "+f"(c[2]), "+f"(c[3])
        : "r"(a0), "r"(a1), "r"(a2), "r"(a3), "r"(b0), "r"(b1));
}

template<int EPI>
__global__ void __launch_bounds__(128) gemm_bf(
    const __nv_bfloat16* __restrict__ Ahi, const __nv_bfloat16* __restrict__ Alo,
    const __nv_bfloat16* __restrict__ Bhi, const __nv_bfloat16* __restrict__ Blo,
    const float* __restrict__ bias, int M, int N, int K,
    float* __restrict__ C, const float* __restrict__ res, float* __restrict__ C2,
    __nv_bfloat16* __restrict__ Chi, __nv_bfloat16* __restrict__ Clo)
{
    extern __shared__ uint4 sm4[];
    const int tid  = threadIdx.x;
    const int lane = tid & 31;
    const int warp = tid >> 5;
    const int wm   = warp >> 1;     // 0..1
    const int wn   = warp & 1;      // 0..1
    const int bm   = blockIdx.y * 128;
    const int bn   = blockIdx.x * 128;

    const unsigned smem_base =
        (unsigned)__cvta_generic_to_shared((void*)sm4);

    float acc[4][8][4];
    #pragma unroll
    for (int i = 0; i < 4; i++) {
        #pragma unroll
        for (int j = 0; j < 8; j++) {
            #pragma unroll
            for (int q = 0; q < 4; q++) acc[i][j][q] = 0.f;
        }
    }

    // reader lane constants (validated mapping from R5 kernel)
    const int ar      = lane & 15;
    const int acolsel = lane >> 4;
    const int br      = (lane & 7) | ((lane >> 4) << 3);
    const int bcolsel = (lane >> 3) & 1;

    const int nk = K / 32;

    // ---- stage loader: 2048 cp.async chunks / 128 threads = 16 each ----
    // plane: 0 Ahi, 1 Alo, 2 Bhi, 3 Blo. Each plane 128 rows x 4 chunks.
    #define LOAD_STAGE(stg, k0)                                                 \
    {                                                                           \
        _Pragma("unroll")                                                       \
        for (int it = 0; it < 16; it++) {                                       \
            int c   = tid + it * 128;                                           \
            int rem = c & 511;                                                  \
            int row = rem >> 2;                                                 \
            int col = rem & 3;                                                  \
            int sw  = col ^ ((row >> 1) & 3);                                   \
            unsigned daddr = smem_base +                                        \
                (unsigned)((((stg) * STG_U4) + ((c >> 9) << 9) + row * 4 + sw) << 4); \
            const __nv_bfloat16* gp;                                            \
            size_t goff;                                                        \
            if (it < 4)       { gp = Ahi; goff = (size_t)(bm + row) * K + (k0) + col * 8; } \
            else if (it < 8)  { gp = Alo; goff = (size_t)(bm + row) * K + (k0) + col * 8; } \
            else if (it < 12) { gp = Bhi; goff = (size_t)(bn + row) * K + (k0) + col * 8; } \
            else              { gp = Blo; goff = (size_t)(bn + row) * K + (k0) + col * 8; } \
            CP16(daddr, gp + goff);                                             \
        }                                                                       \
    }

    LOAD_STAGE(0, 0);
    CP_COMMIT();
    LOAD_STAGE(1, 32);
    CP_COMMIT();

    for (int kt = 0; kt < nk; kt++) {
        CP_WAIT1();
        __syncthreads();
        const int stOff = (kt & 1) * STG_U4;

        #pragma unroll
        for (int s = 0; s < 2; s++) {
            unsigned ahi[4][4];
            unsigned alo[4][4];
            #pragma unroll
            for (int i = 0; i < 4; i++) {
                int row = wm * 64 + i * 16 + ar;
                int chunk = 2 * s + acolsel;
                int sw = chunk ^ ((row >> 1) & 3);
                unsigned ad = smem_base +
                    (unsigned)((stOff + row * 4 + sw) << 4);
                ldsm4(ahi[i][0], ahi[i][1], ahi[i][2], ahi[i][3], ad);
                ldsm4(alo[i][0], alo[i][1], alo[i][2], alo[i][3],
                      ad + (unsigned)(512 << 4));
            }
            #pragma unroll
            for (int p = 0; p < 4; p++) {
                int row = wn * 64 + p * 16 + br;
                int chunk = 2 * s + bcolsel;
                int sw = chunk ^ ((row >> 1) & 3);
                unsigned bd = smem_base +
                    (unsigned)((stOff + 1024 + row * 4 + sw) << 4);
                unsigned bh0, bh1, bh2, bh3;
                unsigned bl0, bl1, bl2, bl3;
                ldsm4(bh0, bh1, bh2, bh3, bd);
                ldsm4(bl0, bl1, bl2, bl3, bd + (unsigned)(512 << 4));
                #pragma unroll
                for (int i = 0; i < 4; i++) {
                    mma16816(acc[i][2*p],
                             ahi[i][0], ahi[i][1], ahi[i][2], ahi[i][3], bh0, bh1);
                    mma16816(acc[i][2*p],
                             ahi[i][0], ahi[i][1], ahi[i][2], ahi[i][3], bl0, bl1);
                    mma16816(acc[i][2*p],
                             alo[i][0], alo[i][1], alo[i][2], alo[i][3], bh0, bh1);
                    mma16816(acc[i][2*p+1],
                             ahi[i][0], ahi[i][1], ahi[i][2], ahi[i][3], bh2, bh3);
                    mma16816(acc[i][2*p+1],
                             ahi[i][0], ahi[i][1], ahi[i][2], ahi[i][3], bl2, bl3);
                    mma16816(acc[i][2*p+1],
                             alo[i][0], alo[i][1], alo[i][2], alo[i][3], bh2, bh3);
                }
            }
        }
        __syncthreads();
        if (kt + 2 < nk) {
            LOAD_STAGE(kt & 1, (kt + 2) * 32);
        }
        CP_COMMIT();
    }
    #undef LOAD_STAGE

    // ---- epilogue ----
    const int rg = lane >> 2;
    const int q2 = (lane & 3) * 2;
    #pragma unroll
    for (int i = 0; i < 4; i++) {
        int r0 = bm + wm * 64 + i * 16 + rg;
        int r1 = r0 + 8;
        #pragma unroll
        for (int j = 0; j < 8; j++) {
            int col = bn + wn * 64 + j * 8 + q2;
            float b0 = bias[col];
            float b1 = bias[col + 1];
            float v0 = acc[i][j][0] + b0;
            float v1 = acc[i][j][1] + b1;
            float v2 = acc[i][j][2] + b0;
            float v3 = acc[i][j][3] + b1;
            size_t p0 = (size_t)r0 * N + col;
            size_t p1 = (size_t)r1 * N + col;
            if (EPI == 0) {
                C[p0] = v0; C[p0 + 1] = v1;
                C[p1] = v2; C[p1 + 1] = v3;
            }
            if (EPI == 1) {
                wplane2(Chi, Clo, p0, v0, v1);
                wplane2(Chi, Clo, p1, v2, v3);
                C2[p0]     = res[p0]     + v0;
                C2[p0 + 1] = res[p0 + 1] + v1;
                C2[p1]     = res[p1]     + v2;
                C2[p1 + 1] = res[p1 + 1] + v3;
            }
            if (EPI == 2) {
                v0 = 0.5f * v0 * (1.0f + erff(v0 * 0.70710678118654752f));
                v1 = 0.5f * v1 * (1.0f + erff(v1 * 0.70710678118654752f));
                v2 = 0.5f * v2 * (1.0f + erff(v2 * 0.70710678118654752f));
                v3 = 0.5f * v3 * (1.0f + erff(v3 * 0.70710678118654752f));
                wplane2(Chi, Clo, p0, v0, v1);
                wplane2(Chi, Clo, p1, v2, v3);
            }
            if (EPI == 3) {
                C[p0]     = v0 + res[p0];
                C[p0 + 1] = v1 + res[p0 + 1];
                C[p1]     = v2 + res[p1];
                C[p1 + 1] = v3 + res[p1 + 1];
            }
        }
    }
}

// ---------------- Causal flash attention, fp32, dh=64 ----------------------
#define FA_PAD 65
#define FA_SMEM (4 * 64 * FA_PAD * (int)sizeof(float))

__global__ void __launch_bounds__(256) flash_attn_k(
    const float* __restrict__ qkv,
    __nv_bfloat16* __restrict__ outhi, __nv_bfloat16* __restrict__ outlo)
{
    extern __shared__ float sm[];
    float* Qs = sm;
    float* Ks = sm + 64 * FA_PAD;
    float* Vs = sm + 2 * 64 * FA_PAD;
    float* Ps = sm + 3 * 64 * FA_PAD;

    int qt = blockIdx.x;
    int h  = blockIdx.y;
    int b  = blockIdx.z;
    int tid = threadIdx.x;
    int tx = tid & 15;
    int ty = tid >> 4;

    const size_t rstride = 3 * DD;
    const float* Qbase = qkv + ((size_t)b * SS + qt * 64) * rstride + h * DHD;
    const float* Kbase = qkv + (size_t)b * SS * rstride + DD     + h * DHD;
    const float* Vbase = qkv + (size_t)b * SS * rstride + 2 * DD + h * DHD;
    const float scale = 0.125f;

    for (int i = tid; i < 64 * 16; i += 256) {
        int r = i >> 4;
        int c = (i & 15) << 2;
        float4 v = *reinterpret_cast<const float4*>(Qbase + (size_t)r * rstride + c);
        Qs[r*FA_PAD + c+0] = v.x * scale;
        Qs[r*FA_PAD + c+1] = v.y * scale;
        Qs[r*FA_PAD + c+2] = v.z * scale;
        Qs[r*FA_PAD + c+3] = v.w * scale;
    }

    float m[4], l[4], o[4][4];
    #pragma unroll
    for (int i = 0; i < 4; i++) {
        m[i] = -INFINITY;
        l[i] = 0.f;
        #pragma unroll
        for (int j = 0; j < 4; j++) o[i][j] = 0.f;
    }

    int nkt = qt + 1;
    for (int kt = 0; kt < nkt; kt++) {
        __syncthreads();
        for (int i = tid; i < 64 * 16; i += 256) {
            int r = i >> 4;
            int c = (i & 15) << 2;
            size_t goff = (size_t)(kt * 64 + r) * rstride + c;
            float4 kv = *reinterpret_cast<const float4*>(Kbase + goff);
            Ks[r*FA_PAD + c+0] = kv.x;
            Ks[r*FA_PAD + c+1] = kv.y;
            Ks[r*FA_PAD + c+2] = kv.z;
            Ks[r*FA_PAD + c+3] = kv.w;
            float4 vv = *reinterpret_cast<const float4*>(Vbase + goff);
            Vs[r*FA_PAD + c+0] = vv.x;
            Vs[r*FA_PAD + c+1] = vv.y;
            Vs[r*FA_PAD + c+2] = vv.z;
            Vs[r*FA_PAD + c+3] = vv.w;
        }
        __syncthreads();

        float s[4][4];
        #pragma unroll
        for (int i = 0; i < 4; i++) {
            #pragma unroll
            for (int j = 0; j < 4; j++) s[i][j] = 0.f;
        }

        #pragma unroll 8
        for (int d = 0; d < 64; d++) {
            float qa[4], kb[4];
            #pragma unroll
            for (int i = 0; i < 4; i++) qa[i] = Qs[(ty*4 + i)*FA_PAD + d];
            #pragma unroll
            for (int j = 0; j < 4; j++) kb[j] = Ks[(tx*4 + j)*FA_PAD + d];
            #pragma unroll
            for (int i = 0; i < 4; i++) {
                #pragma unroll
                for (int j = 0; j < 4; j++)
                    s[i][j] = fmaf(qa[i], kb[j], s[i][j]);
            }
        }

        if (kt == qt) {
            #pragma unroll
            for (int i = 0; i < 4; i++) {
                #pragma unroll
                for (int j = 0; j < 4; j++) {
                    if (tx*4 + j > ty*4 + i) s[i][j] = -1e30f;
                }
            }
        }

        #pragma unroll
        for (int i = 0; i < 4; i++) {
            float rm = fmaxf(fmaxf(s[i][0], s[i][1]), fmaxf(s[i][2], s[i][3]));
            #pragma unroll
            for (int off = 8; off > 0; off >>= 1)
                rm = fmaxf(rm, __shfl_xor_sync(0xffffffffu, rm, off));
            float mn = fmaxf(m[i], rm);
            float corr = __expf(m[i] - mn);
            float ps = 0.f;
            #pragma unroll
            for (int j = 0; j < 4; j++) {
                float p = __expf(s[i][j] - mn);
                Ps[(ty*4 + i)*FA_PAD + tx*4 + j] = p;
                ps += p;
            }
            #pragma unroll
            for (int off = 8; off > 0; off >>= 1)
                ps += __shfl_xor_sync(0xffffffffu, ps, off);
            l[i] = l[i] * corr + ps;
            m[i] = mn;
            #pragma unroll
            for (int j = 0; j < 4; j++) o[i][j] *= corr;
        }
        __syncthreads();

        #pragma unroll 8
        for (int kk = 0; kk < 64; kk++) {
            float p[4], vv[4];
            #pragma unroll
            for (int i = 0; i < 4; i++) p[i]  = Ps[(ty*4 + i)*FA_PAD + kk];
            #pragma unroll
            for (int j = 0; j < 4; j++) vv[j] = Vs[kk*FA_PAD + tx*4 + j];
            #pragma unroll
            for (int i = 0; i < 4; i++) {
                #pragma unroll
                for (int j = 0; j < 4; j++)
                    o[i][j] = fmaf(p[i], vv[j], o[i][j]);
            }
        }
    }

    #pragma unroll
    for (int i = 0; i < 4; i++) {
        float invl = 1.0f / l[i];
        size_t orow = ((size_t)b * SS + qt * 64 + ty*4 + i) * DD + h * DHD + tx*4;
        wplane2(outhi, outlo, orow,     o[i][0] * invl, o[i][1] * invl);
        wplane2(outhi, outlo, orow + 2, o[i][2] * invl, o[i][3] * invl);
    }
}

// ---------------- INL integrator: fused elementwise -------------------------
__global__ void __launch_bounds__(256) inl_k(
    const float* __restrict__ xs0, const float* __restrict__ inl,
    const float* __restrict__ x1,  float* __restrict__ x2)
{
    size_t i = (size_t)blockIdx.x * blockDim.x + threadIdx.x;
    size_t row = i >> 10;
    size_t col = i & 1023;
    size_t base = row * (size_t)(4*DD) + col;
    float xs = xs0[i];
    float u  = inl[base];
    float av = inl[base + DD];
    float bv = inl[base + 2*DD];
    float gv = inl[base + 3*DD];
    float alpha = 1.0f / (1.0f + expf(-av));
    float beta  = (bv > 20.0f) ? bv : log1pf(expf(bv));
    float g     = 1.0f / (1.0f + expf(-gv));
    float vs = 0.0f;
    #pragma unroll
    for (int t = 0; t < 5; t++) {
        vs += 0.1f * (alpha * (0.0f - xs) - beta * vs + u);
        xs += 0.1f * g * vs;
    }
    x2[i] = x1[i] + xs;
}

// ---------------- launch ----------------------------------------------------
extern "C" void kernel_launch(void* const* d_in, const int* in_sizes, int n_in,
                              void* d_out, int out_size)
{
    const float* x          = (const float*)d_in[0];
    const float* ln_attn_w  = (const float*)d_in[1];
    const float* ln_attn_b  = (const float*)d_in[2];
    const float* attn_in_w  = (const float*)d_in[3];
    const float* attn_in_b  = (const float*)d_in[4];
    const float* attn_out_w = (const float*)d_in[5];
    const float* attn_out_b = (const float*)d_in[6];
    const float* ln1_w      = (const float*)d_in[7];
    const float* ln1_b      = (const float*)d_in[8];
    const float* ln2_w      = (const float*)d_in[9];
    const float* ln2_b      = (const float*)d_in[10];
    const float* inl_u_w    = (const float*)d_in[11];
    const float* inl_u_b    = (const float*)d_in[12];
    const float* inl_a_w    = (const float*)d_in[13];
    const float* inl_a_b    = (const float*)d_in[14];
    const float* inl_b_w    = (const float*)d_in[15];
    const float* inl_b_b    = (const float*)d_in[16];
    const float* inl_g_w    = (const float*)d_in[17];
    const float* inl_g_b    = (const float*)d_in[18];
    const float* ff1_w      = (const float*)d_in[19];
    const float* ff1_b      = (const float*)d_in[20];
    const float* ff2_w      = (const float*)d_in[21];
    const float* ff2_b      = (const float*)d_in[22];
    float* out = (float*)d_out;

    __nv_bfloat16 *xn_hi = 0, *xn_lo = 0, *att_hi = 0, *att_lo = 0;
    __nv_bfloat16 *ctx_hi = 0, *ctx_lo = 0, *h_hi = 0, *h_lo = 0;
    __nv_bfloat16 *ffh_hi = 0, *ffh_lo = 0, *w_hi = 0, *w_lo = 0;
    float *qkv = 0, *x1 = 0, *xs0 = 0, *inl = 0, *x2 = 0, *bcat = 0;
    cudaGetSymbolAddress((void**)&xn_hi,  g_xn_hi);
    cudaGetSymbolAddress((void**)&xn_lo,  g_xn_lo);
    cudaGetSymbolAddress((void**)&att_hi, g_att_hi);
    cudaGetSymbolAddress((void**)&att_lo, g_att_lo);
    cudaGetSymbolAddress((void**)&ctx_hi, g_ctx_hi);
    cudaGetSymbolAddress((void**)&ctx_lo, g_ctx_lo);
    cudaGetSymbolAddress((void**)&h_hi,   g_h_hi);
    cudaGetSymbolAddress((void**)&h_lo,   g_h_lo);
    cudaGetSymbolAddress((void**)&ffh_hi, g_ffh_hi);
    cudaGetSymbolAddress((void**)&ffh_lo, g_ffh_lo);
    cudaGetSymbolAddress((void**)&w_hi,   g_w_hi);
    cudaGetSymbolAddress((void**)&w_lo,   g_w_lo);
    cudaGetSymbolAddress((void**)&qkv,    g_qkv);
    cudaGetSymbolAddress((void**)&x1,     g_x1);
    cudaGetSymbolAddress((void**)&xs0,    g_xs0);
    cudaGetSymbolAddress((void**)&inl,    g_inl);
    cudaGetSymbolAddress((void**)&x2,     g_x2);
    cudaGetSymbolAddress((void**)&bcat,   g_bcat);

    cudaFuncSetAttribute(gemm_bf<0>,
        cudaFuncAttributeMaxDynamicSharedMemorySize, GEM_SMEM);
    cudaFuncSetAttribute(gemm_bf<1>,
        cudaFuncAttributeMaxDynamicSharedMemorySize, GEM_SMEM);
    cudaFuncSetAttribute(gemm_bf<2>,
        cudaFuncAttributeMaxDynamicSharedMemorySize, GEM_SMEM);
    cudaFuncSetAttribute(gemm_bf<3>,
        cudaFuncAttributeMaxDynamicSharedMemorySize, GEM_SMEM);
    cudaFuncSetAttribute(flash_attn_k,
        cudaFuncAttributeMaxDynamicSharedMemorySize, FA_SMEM);

    // 0) weight plane conversion + bias concat
    conv_w_k<<<(int)(W_TOTAL / 512), 256>>>(
        attn_in_w, attn_out_w, inl_u_w, inl_a_w, inl_b_w, inl_g_w, ff1_w, ff2_w);
    bias_cat_k<<<16, 256>>>(inl_u_b, inl_a_b, inl_b_b, inl_g_b);

    // 1) pre-attn LN -> xn planes
    layernorm_p<<<ROWS, 256>>>(x, ln_attn_w, ln_attn_b, xn_hi, xn_lo);

    // 2) QKV projection (fp32 out)
    gemm_bf<0><<<dim3(3*DD/128, ROWS/128), 128, GEM_SMEM>>>(
        xn_hi, xn_lo, w_hi + WOFF_ATTNIN, w_lo + WOFF_ATTNIN,
        attn_in_b, ROWS, 3*DD, DD, qkv, (const float*)0, (float*)0,
        (__nv_bfloat16*)0, (__nv_bfloat16*)0);

    // 3) causal flash attention -> att planes
    flash_attn_k<<<dim3(SS/64, HH, BB), 256, FA_SMEM>>>(qkv, att_hi, att_lo);

    // 4) out-projection: ctx planes = proj+bias, x1 = x + proj+bias
    gemm_bf<1><<<dim3(DD/128, ROWS/128), 128, GEM_SMEM>>>(
        att_hi, att_lo, w_hi + WOFF_ATTNOUT, w_lo + WOFF_ATTNOUT,
        attn_out_b, ROWS, DD, DD, (float*)0, x, x1, ctx_hi, ctx_lo);

    // 5) LN1(x1) -> xs0 fp32
    layernorm_f<<<ROWS, 256>>>(x1, ln1_w, ln1_b, xs0);

    // 6) fused INL controller projections: [ROWS, 4096] fp32
    gemm_bf<0><<<dim3(4*DD/128, ROWS/128), 128, GEM_SMEM>>>(
        ctx_hi, ctx_lo, w_hi + WOFF_INL, w_lo + WOFF_INL,
        bcat, ROWS, 4*DD, DD, inl, (const float*)0, (float*)0,
        (__nv_bfloat16*)0, (__nv_bfloat16*)0);

    // 7) fused INL dynamics: x2 = x1 + xs(5 steps)
    inl_k<<<(ROWS*(size_t)DD)/256, 256>>>(xs0, inl, x1, x2);

    // 8) LN2(x2) -> h planes
    layernorm_p<<<ROWS, 256>>>(x2, ln2_w, ln2_b, h_hi, h_lo);

    // 9) FF1 + exact GELU -> ffh planes
    gemm_bf<2><<<dim3(FFD/128, ROWS/128), 128, GEM_SMEM>>>(
        h_hi, h_lo, w_hi + WOFF_FF1, w_lo + WOFF_FF1,
        ff1_b, ROWS, FFD, DD, (float*)0, (const float*)0, (float*)0,
        ffh_hi, ffh_lo);

    // 10) FF2 + bias + residual -> out
    gemm_bf<3><<<dim3(DD/128, ROWS/128), 128, GEM_SMEM>>>(
        ffh_hi, ffh_lo, w_hi + WOFF_FF2, w_lo + WOFF_FF2,
        ff2_b, ROWS, DD, FFD, out, x2, (float*)0,
        (__nv_bfloat16*)0, (__nv_bfloat16*)0);
}

// round 8
// speedup vs baseline: 3.4208x; 1.3656x over previous
#include <cuda_runtime.h>
#include <cuda_bf16.h>
#include <cstdint>
#include <math.h>

// Problem constants
#define BB   4
#define SS   2048
#define DD   1024
#define HH   16
#define DHD  64
#define FFD  4096
#define ROWS (BB*SS)

// ---------------- scratch (device globals; no allocation allowed) ----------
__device__ __nv_bfloat16 g_xn_hi [(size_t)ROWS*DD];
__device__ __nv_bfloat16 g_xn_lo [(size_t)ROWS*DD];
__device__ __nv_bfloat16 g_qkv_hi[(size_t)ROWS*3*DD];
__device__ __nv_bfloat16 g_qkv_lo[(size_t)ROWS*3*DD];
__device__ __nv_bfloat16 g_att_hi[(size_t)ROWS*DD];
__device__ __nv_bfloat16 g_att_lo[(size_t)ROWS*DD];
__device__ __nv_bfloat16 g_ctx_hi[(size_t)ROWS*DD];
__device__ __nv_bfloat16 g_ctx_lo[(size_t)ROWS*DD];
__device__ __nv_bfloat16 g_h_hi  [(size_t)ROWS*DD];
__device__ __nv_bfloat16 g_h_lo  [(size_t)ROWS*DD];
__device__ __nv_bfloat16 g_ffh_hi[(size_t)ROWS*FFD];
__device__ __nv_bfloat16 g_ffh_lo[(size_t)ROWS*FFD];
// weight planes (all weights concatenated)
#define W_TOTAL ((size_t)16*1024*1024)
#define WOFF_ATTNIN  ((size_t)0)
#define WOFF_ATTNOUT ((size_t)3*1024*1024)
#define WOFF_INL     ((size_t)4*1024*1024)
#define WOFF_FF1     ((size_t)8*1024*1024)
#define WOFF_FF2     ((size_t)12*1024*1024)
__device__ __nv_bfloat16 g_w_hi[W_TOTAL];
__device__ __nv_bfloat16 g_w_lo[W_TOTAL];
__device__ float g_bcat[4*DD];
// fp32 intermediates
__device__ float g_x1 [(size_t)ROWS*DD];
__device__ float g_xs0[(size_t)ROWS*DD];
__device__ float g_inl[(size_t)ROWS*4*DD];
__device__ float g_x2 [(size_t)ROWS*DD];

// ---------------- helpers ---------------------------------------------------
__device__ __forceinline__ void wplane2(__nv_bfloat16* hi, __nv_bfloat16* lo,
                                        size_t idx, float v0, float v1)
{
    __nv_bfloat162 h = __floats2bfloat162_rn(v0, v1);
    float h0 = __bfloat162float(h.x);
    float h1 = __bfloat162float(h.y);
    __nv_bfloat162 l = __floats2bfloat162_rn(v0 - h0, v1 - h1);
    *reinterpret_cast<__nv_bfloat162*>(hi + idx) = h;
    *reinterpret_cast<__nv_bfloat162*>(lo + idx) = l;
}

__device__ __forceinline__ void bsplit2u(float x, float y,
                                         unsigned &h, unsigned &l)
{
    __nv_bfloat162 hb = __floats2bfloat162_rn(x, y);
    float hx = __bfloat162float(hb.x);
    float hy = __bfloat162float(hb.y);
    __nv_bfloat162 lb = __floats2bfloat162_rn(x - hx, y - hy);
    h = *reinterpret_cast<unsigned*>(&hb);
    l = *reinterpret_cast<unsigned*>(&lb);
}

// ---------------- weight conversion (all weights, one kernel) --------------
__global__ void __launch_bounds__(256) conv_w_k(
    const float* __restrict__ attn_in_w, const float* __restrict__ attn_out_w,
    const float* __restrict__ inl_u_w,   const float* __restrict__ inl_a_w,
    const float* __restrict__ inl_b_w,   const float* __restrict__ inl_g_w,
    const float* __restrict__ ff1_w,     const float* __restrict__ ff2_w)
{
    size_t e = ((size_t)blockIdx.x * 256 + threadIdx.x) * 2;
    const float* src;
    size_t off;
    if      (e < WOFF_ATTNOUT) { src = attn_in_w;  off = e - WOFF_ATTNIN; }
    else if (e < WOFF_INL)     { src = attn_out_w; off = e - WOFF_ATTNOUT; }
    else if (e < WOFF_INL + (size_t)1024*1024)   { src = inl_u_w; off = e - WOFF_INL; }
    else if (e < WOFF_INL + (size_t)2*1024*1024) { src = inl_a_w; off = e - WOFF_INL - (size_t)1024*1024; }
    else if (e < WOFF_INL + (size_t)3*1024*1024) { src = inl_b_w; off = e - WOFF_INL - (size_t)2*1024*1024; }
    else if (e < WOFF_FF1)     { src = inl_g_w; off = e - WOFF_INL - (size_t)3*1024*1024; }
    else if (e < WOFF_FF2)     { src = ff1_w;   off = e - WOFF_FF1; }
    else                       { src = ff2_w;   off = e - WOFF_FF2; }
    float2 v = *reinterpret_cast<const float2*>(src + off);
    wplane2(g_w_hi, g_w_lo, e, v.x, v.y);
}

__global__ void bias_cat_k(const float* __restrict__ ub, const float* __restrict__ ab,
                           const float* __restrict__ bb, const float* __restrict__ gb)
{
    int i = blockIdx.x * 256 + threadIdx.x;
    int sel = i >> 10;
    int c = i & 1023;
    float v;
    if (sel == 0) v = ub[c];
    else if (sel == 1) v = ab[c];
    else if (sel == 2) v = bb[c];
    else v = gb[c];
    g_bcat[i] = v;
}

// ---------------- LayerNorm (fp32 out) --------------------------------------
__global__ void __launch_bounds__(256) layernorm_f(
    const float* __restrict__ x, const float* __restrict__ w,
    const float* __restrict__ b, float* __restrict__ y)
{
    int row = blockIdx.x;
    const float* xr = x + (size_t)row * DD;
    int tid = threadIdx.x;
    float4 v = *reinterpret_cast<const float4*>(xr + tid * 4);
    float s  = v.x + v.y + v.z + v.w;
    float ss = v.x*v.x + v.y*v.y + v.z*v.z + v.w*v.w;
    #pragma unroll
    for (int off = 16; off > 0; off >>= 1) {
        s  += __shfl_xor_sync(0xffffffffu, s,  off);
        ss += __shfl_xor_sync(0xffffffffu, ss, off);
    }
    __shared__ float sh_s[8];
    __shared__ float sh_ss[8];
    int wid = tid >> 5;
    int lane = tid & 31;
    if (lane == 0) { sh_s[wid] = s; sh_ss[wid] = ss; }
    __syncthreads();
    float ts = 0.f, tss = 0.f;
    #pragma unroll
    for (int i = 0; i < 8; i++) { ts += sh_s[i]; tss += sh_ss[i]; }
    float mu   = ts * (1.0f / DD);
    float var  = tss * (1.0f / DD) - mu * mu;
    float rstd = rsqrtf(var + 1e-5f);
    float4 wv = *reinterpret_cast<const float4*>(w + tid * 4);
    float4 bv = *reinterpret_cast<const float4*>(b + tid * 4);
    float4 o;
    o.x = (v.x - mu) * rstd * wv.x + bv.x;
    o.y = (v.y - mu) * rstd * wv.y + bv.y;
    o.z = (v.z - mu) * rstd * wv.z + bv.z;
    o.w = (v.w - mu) * rstd * wv.w + bv.w;
    *reinterpret_cast<float4*>(y + (size_t)row * DD + tid * 4) = o;
}

// ---------------- LayerNorm (bf16 hi/lo plane out) --------------------------
__global__ void __launch_bounds__(256) layernorm_p(
    const float* __restrict__ x, const float* __restrict__ w,
    const float* __restrict__ b,
    __nv_bfloat16* __restrict__ yhi, __nv_bfloat16* __restrict__ ylo)
{
    int row = blockIdx.x;
    const float* xr = x + (size_t)row * DD;
    int tid = threadIdx.x;
    float4 v = *reinterpret_cast<const float4*>(xr + tid * 4);
    float s  = v.x + v.y + v.z + v.w;
    float ss = v.x*v.x + v.y*v.y + v.z*v.z + v.w*v.w;
    #pragma unroll
    for (int off = 16; off > 0; off >>= 1) {
        s  += __shfl_xor_sync(0xffffffffu, s,  off);
        ss += __shfl_xor_sync(0xffffffffu, ss, off);
    }
    __shared__ float sh_s[8];
    __shared__ float sh_ss[8];
    int wid = tid >> 5;
    int lane = tid & 31;
    if (lane == 0) { sh_s[wid] = s; sh_ss[wid] = ss; }
    __syncthreads();
    float ts = 0.f, tss = 0.f;
    #pragma unroll
    for (int i = 0; i < 8; i++) { ts += sh_s[i]; tss += sh_ss[i]; }
    float mu   = ts * (1.0f / DD);
    float var  = tss * (1.0f / DD) - mu * mu;
    float rstd = rsqrtf(var + 1e-5f);
    float4 wv = *reinterpret_cast<const float4*>(w + tid * 4);
    float4 bv = *reinterpret_cast<const float4*>(b + tid * 4);
    float o0 = (v.x - mu) * rstd * wv.x + bv.x;
    float o1 = (v.y - mu) * rstd * wv.y + bv.y;
    float o2 = (v.z - mu) * rstd * wv.z + bv.z;
    float o3 = (v.w - mu) * rstd * wv.w + bv.w;
    size_t base = (size_t)row * DD + tid * 4;
    wplane2(yhi, ylo, base,     o0, o1);
    wplane2(yhi, ylo, base + 2, o2, o3);
}

// ============================================================================
// mma / ldmatrix wrappers
// ============================================================================
#define CP16(d, s) asm volatile("cp.async.cg.shared.global [%0], [%1], 16;\n" :: "r"(d), "l"(s))
#define CP_COMMIT() asm volatile("cp.async.commit_group;\n" ::)
#define CP_WAIT1() asm volatile("cp.async.wait_group 1;\n" ::)

__device__ __forceinline__ void ldsm4(unsigned &r0, unsigned &r1,
                                      unsigned &r2, unsigned &r3,
                                      unsigned addr)
{
    asm volatile(
        "ldmatrix.sync.aligned.m8n8.x4.shared.b16 {%0,%1,%2,%3}, [%4];\n"
        : "=r"(r0), "=r"(r1), "=r"(r2), "=r"(r3)
        : "r"(addr));
}

__device__ __forceinline__ void ldsm4t(unsigned &r0, unsigned &r1,
                                       unsigned &r2, unsigned &r3,
                                       unsigned addr)
{
    asm volatile(
        "ldmatrix.sync.aligned.m8n8.x4.trans.shared.b16 {%0,%1,%2,%3}, [%4];\n"
        : "=r"(r0), "=r"(r1), "=r"(r2), "=r"(r3)
        : "r"(addr));
}

__device__ __forceinline__ void mma16816(float* c,
    unsigned a0, unsigned a1, unsigned a2, unsigned a3,
    unsigned b0, unsigned b1)
{
    asm volatile(
        "mma.sync.aligned.m16n8k16.row.col.f32.bf16.bf16.f32 "
        "{%0,%1,%2,%3}, {%4,%5,%6,%7}, {%8,%9}, {%0,%1,%2,%3};\n"
        : "+f"(c[0]), "+f"(c[1]), "+f"(c[2]), "+f"(c[3])
        : "r"(a0), "r"(a1), "r"(a2), "r"(a3), "r"(b0), "r"(b1));
}

// ============================================================================
// Tensor-core GEMM on pre-split bf16 hi/lo planes. (same as R6 + EPI 4)
// EPI: 0 fp32+bias; 1 planes(v+bias)+C2=res+v; 2 planes(GELU(v+bias));
//      3 fp32 v+bias+res; 4 planes(v+bias) only.
// ============================================================================
#define STG_U4 2048
#define GEM_SMEM (2 * STG_U4 * 16)

template<int EPI>
__global__ void __launch_bounds__(128) gemm_bf(
    const __nv_bfloat16* __restrict__ Ahi, const __nv_bfloat16* __restrict__ Alo,
    const __nv_bfloat16* __restrict__ Bhi, const __nv_bfloat16* __restrict__ Blo,
    const float* __restrict__ bias, int M, int N, int K,
    float* __restrict__ C, const float* __restrict__ res, float* __restrict__ C2,
    __nv_bfloat16* __restrict__ Chi, __nv_bfloat16* __restrict__ Clo)
{
    extern __shared__ uint4 sm4[];
    const int tid  = threadIdx.x;
    const int lane = tid & 31;
    const int warp = tid >> 5;
    const int wm   = warp >> 1;
    const int wn   = warp & 1;
    const int bm   = blockIdx.y * 128;
    const int bn   = blockIdx.x * 128;

    const unsigned smem_base =
        (unsigned)__cvta_generic_to_shared((void*)sm4);

    float acc[4][8][4];
    #pragma unroll
    for (int i = 0; i < 4; i++) {
        #pragma unroll
        for (int j = 0; j < 8; j++) {
            #pragma unroll
            for (int q = 0; q < 4; q++) acc[i][j][q] = 0.f;
        }
    }

    const int ar      = lane & 15;
    const int acolsel = lane >> 4;
    const int br      = (lane & 7) | ((lane >> 4) << 3);
    const int bcolsel = (lane >> 3) & 1;

    const int nk = K / 32;

    #define LOAD_STAGE(stg, k0)                                                 \
    {                                                                           \
        _Pragma("unroll")                                                       \
        for (int it = 0; it < 16; it++) {                                       \
            int c   = tid + it * 128;                                           \
            int rem = c & 511;                                                  \
            int row = rem >> 2;                                                  \
            int col = rem & 3;                                                   \
            int sw  = col ^ ((row >> 1) & 3);                                    \
            unsigned daddr = smem_base +                                         \
                (unsigned)((((stg) * STG_U4) + ((c >> 9) << 9) + row * 4 + sw) << 4); \
            const __nv_bfloat16* gp;                                             \
            size_t goff;                                                         \
            if (it < 4)       { gp = Ahi; goff = (size_t)(bm + row) * K + (k0) + col * 8; } \
            else if (it < 8)  { gp = Alo; goff = (size_t)(bm + row) * K + (k0) + col * 8; } \
            else if (it < 12) { gp = Bhi; goff = (size_t)(bn + row) * K + (k0) + col * 8; } \
            else              { gp = Blo; goff = (size_t)(bn + row) * K + (k0) + col * 8; } \
            CP16(daddr, gp + goff);                                              \
        }                                                                        \
    }

    LOAD_STAGE(0, 0);
    CP_COMMIT();
    LOAD_STAGE(1, 32);
    CP_COMMIT();

    for (int kt = 0; kt < nk; kt++) {
        CP_WAIT1();
        __syncthreads();
        const int stOff = (kt & 1) * STG_U4;

        #pragma unroll
        for (int s = 0; s < 2; s++) {
            unsigned ahi[4][4];
            unsigned alo[4][4];
            #pragma unroll
            for (int i = 0; i < 4; i++) {
                int row = wm * 64 + i * 16 + ar;
                int chunk = 2 * s + acolsel;
                int sw = chunk ^ ((row >> 1) & 3);
                unsigned ad = smem_base +
                    (unsigned)((stOff + row * 4 + sw) << 4);
                ldsm4(ahi[i][0], ahi[i][1], ahi[i][2], ahi[i][3], ad);
                ldsm4(alo[i][0], alo[i][1], alo[i][2], alo[i][3],
                      ad + (unsigned)(512 << 4));
            }
            #pragma unroll
            for (int p = 0; p < 4; p++) {
                int row = wn * 64 + p * 16 + br;
                int chunk = 2 * s + bcolsel;
                int sw = chunk ^ ((row >> 1) & 3);
                unsigned bd = smem_base +
                    (unsigned)((stOff + 1024 + row * 4 + sw) << 4);
                unsigned bh0, bh1, bh2, bh3;
                unsigned bl0, bl1, bl2, bl3;
                ldsm4(bh0, bh1, bh2, bh3, bd);
                ldsm4(bl0, bl1, bl2, bl3, bd + (unsigned)(512 << 4));
                #pragma unroll
                for (int i = 0; i < 4; i++) {
                    mma16816(acc[i][2*p],
                             ahi[i][0], ahi[i][1], ahi[i][2], ahi[i][3], bh0, bh1);
                    mma16816(acc[i][2*p],
                             ahi[i][0], ahi[i][1], ahi[i][2], ahi[i][3], bl0, bl1);
                    mma16816(acc[i][2*p],
                             alo[i][0], alo[i][1], alo[i][2], alo[i][3], bh0, bh1);
                    mma16816(acc[i][2*p+1],
                             ahi[i][0], ahi[i][1], ahi[i][2], ahi[i][3], bh2, bh3);
                    mma16816(acc[i][2*p+1],
                             ahi[i][0], ahi[i][1], ahi[i][2], ahi[i][3], bl2, bl3);
                    mma16816(acc[i][2*p+1],
                             alo[i][0], alo[i][1], alo[i][2], alo[i][3], bh2, bh3);
                }
            }
        }
        __syncthreads();
        if (kt + 2 < nk) {
            LOAD_STAGE(kt & 1, (kt + 2) * 32);
        }
        CP_COMMIT();
    }
    #undef LOAD_STAGE

    const int rg = lane >> 2;
    const int q2 = (lane & 3) * 2;
    #pragma unroll
    for (int i = 0; i < 4; i++) {
        int r0 = bm + wm * 64 + i * 16 + rg;
        int r1 = r0 + 8;
        #pragma unroll
        for (int j = 0; j < 8; j++) {
            int col = bn + wn * 64 + j * 8 + q2;
            float b0 = bias[col];
            float b1 = bias[col + 1];
            float v0 = acc[i][j][0] + b0;
            float v1 = acc[i][j][1] + b1;
            float v2 = acc[i][j][2] + b0;
            float v3 = acc[i][j][3] + b1;
            size_t p0 = (size_t)r0 * N + col;
            size_t p1 = (size_t)r1 * N + col;
            if (EPI == 0) {
                C[p0] = v0; C[p0 + 1] = v1;
                C[p1] = v2; C[p1 + 1] = v3;
            }
            if (EPI == 1) {
                wplane2(Chi, Clo, p0, v0, v1);
                wplane2(Chi, Clo, p1, v2, v3);
                C2[p0]     = res[p0]     + v0;
                C2[p0 + 1] = res[p0 + 1] + v1;
                C2[p1]     = res[p1]     + v2;
                C2[p1 + 1] = res[p1 + 1] + v3;
            }
            if (EPI == 2) {
                v0 = 0.5f * v0 * (1.0f + erff(v0 * 0.70710678118654752f));
                v1 = 0.5f * v1 * (1.0f + erff(v1 * 0.70710678118654752f));
                v2 = 0.5f * v2 * (1.0f + erff(v2 * 0.70710678118654752f));
                v3 = 0.5f * v3 * (1.0f + erff(v3 * 0.70710678118654752f));
                wplane2(Chi, Clo, p0, v0, v1);
                wplane2(Chi, Clo, p1, v2, v3);
            }
            if (EPI == 3) {
                C[p0]     = v0 + res[p0];
                C[p0 + 1] = v1 + res[p0 + 1];
                C[p1]     = v2 + res[p1];
                C[p1 + 1] = v3 + res[p1 + 1];
            }
            if (EPI == 4) {
                wplane2(Chi, Clo, p0, v0, v1);
                wplane2(Chi, Clo, p1, v2, v3);
            }
        }
    }
}

// ============================================================================
// Tensor-core causal flash attention, bf16 hi/lo split, dh=64.
// Block: 64 queries x (head, batch); 128 threads = 4 warps, warp owns m16.
// smem (uint4 chunks): Qhi[512] Qlo[512] | 2 stages x {Khi,Klo,Vhi,Vlo}[512 each]
// ============================================================================
#define FA_Q_HI 0
#define FA_Q_LO 512
#define FA_STG  1024          // per-stage: K_HI +0, K_LO +512, V_HI +1024, V_LO +1536
#define FA_SMEM (5120 * 16)   // 80 KB

__global__ void __launch_bounds__(128) flash_attn_tc(
    const __nv_bfloat16* __restrict__ qhi, const __nv_bfloat16* __restrict__ qlo,
    __nv_bfloat16* __restrict__ outhi, __nv_bfloat16* __restrict__ outlo)
{
    extern __shared__ uint4 sm4[];
    const int tid  = threadIdx.x;
    const int lane = tid & 31;
    const int warp = tid >> 5;
    const int qt = blockIdx.x;
    const int h  = blockIdx.y;
    const int b  = blockIdx.z;
    const unsigned smem_base =
        (unsigned)__cvta_generic_to_shared((void*)sm4);

    const size_t rstr = 3 * DD;
    const size_t qrow0  = (size_t)b * SS + (size_t)qt * 64;
    const size_t kvrow0 = (size_t)b * SS;

    // ---- Q tile load (once) ----
    #pragma unroll
    for (int it = 0; it < 8; it++) {
        int c = tid + it * 128;
        int plane = c >> 9;          // 0 hi, 1 lo
        int rem = c & 511;
        int row = rem >> 3;
        int ch  = rem & 7;
        int sw  = ch ^ (row & 7);
        unsigned d = smem_base + (unsigned)((plane * 512 + row * 8 + sw) << 4);
        const __nv_bfloat16* src = (plane ? qlo : qhi);
        CP16(d, src + (qrow0 + row) * rstr + h * 64 + ch * 8);
    }
    CP_COMMIT();

    const int nkt = qt + 1;

    #define LOAD_KV(stg, kt_)                                                   \
    {                                                                           \
        size_t krow = kvrow0 + (size_t)(kt_) * 64;                              \
        _Pragma("unroll")                                                       \
        for (int it = 0; it < 16; it++) {                                       \
            int c = tid + it * 128;                                             \
            int plane = c >> 9;   /* 0 Khi 1 Klo 2 Vhi 3 Vlo */                 \
            int rem = c & 511;                                                  \
            int row = rem >> 3;                                                 \
            int ch  = rem & 7;                                                  \
            int sw  = ch ^ (row & 7);                                           \
            unsigned d = smem_base +                                            \
                (unsigned)((FA_STG + (stg) * 2048 + plane * 512 + row * 8 + sw) << 4); \
            const __nv_bfloat16* gp = (plane & 1) ? qlo : qhi;                  \
            size_t off = (krow + row) * rstr +                                  \
                         ((plane >> 1) ? 2 * DD : DD) + h * 64 + ch * 8;        \
            CP16(d, gp + off);                                                  \
        }                                                                       \
    }

    LOAD_KV(0, 0);
    CP_COMMIT();
    if (nkt > 1) { LOAD_KV(1, 1); }
    CP_COMMIT();

    const int g = lane >> 2;
    const int q = lane & 3;

    float m0 = -INFINITY, m1 = -INFINITY;
    float l0 = 0.f, l1 = 0.f;
    float ov[8][4];
    #pragma unroll
    for (int j = 0; j < 8; j++) {
        #pragma unroll
        for (int k = 0; k < 4; k++) ov[j][k] = 0.f;
    }

    for (int kt = 0; kt < nkt; kt++) {
        CP_WAIT1();
        __syncthreads();
        const unsigned stg = smem_base +
            (unsigned)((FA_STG + (kt & 1) * 2048) << 4);

        // ---- S = Q @ K^T ----
        float ss[8][4];
        #pragma unroll
        for (int j = 0; j < 8; j++) {
            #pragma unroll
            for (int k = 0; k < 4; k++) ss[j][k] = 0.f;
        }

        #pragma unroll
        for (int t = 0; t < 4; t++) {
            int arow = warp * 16 + (lane & 15);
            int ach  = 2 * t + (lane >> 4);
            int asw  = ach ^ (arow & 7);
            unsigned aaddr = smem_base + (unsigned)((arow * 8 + asw) << 4);
            unsigned qh0, qh1, qh2, qh3, ql0, ql1, ql2, ql3;
            ldsm4(qh0, qh1, qh2, qh3, aaddr);
            ldsm4(ql0, ql1, ql2, ql3, aaddr + (unsigned)(512 << 4));

            #pragma unroll
            for (int pb = 0; pb < 4; pb++) {
                int brow = pb * 16 + ((lane & 7) | ((lane >> 4) << 3));
                int bch  = 2 * t + ((lane >> 3) & 1);
                int bsw  = bch ^ (brow & 7);
                unsigned baddr = stg + (unsigned)((brow * 8 + bsw) << 4);
                unsigned kh0, kh1, kh2, kh3, kl0, kl1, kl2, kl3;
                ldsm4(kh0, kh1, kh2, kh3, baddr);
                ldsm4(kl0, kl1, kl2, kl3, baddr + (unsigned)(512 << 4));
                mma16816(ss[2*pb],   qh0, qh1, qh2, qh3, kh0, kh1);
                mma16816(ss[2*pb],   ql0, ql1, ql2, ql3, kh0, kh1);
                mma16816(ss[2*pb],   qh0, qh1, qh2, qh3, kl0, kl1);
                mma16816(ss[2*pb+1], qh0, qh1, qh2, qh3, kh2, kh3);
                mma16816(ss[2*pb+1], ql0, ql1, ql2, ql3, kh2, kh3);
                mma16816(ss[2*pb+1], qh0, qh1, qh2, qh3, kl2, kl3);
            }
        }

        // ---- scale + causal mask ----
        #pragma unroll
        for (int j = 0; j < 8; j++) {
            ss[j][0] *= 0.125f; ss[j][1] *= 0.125f;
            ss[j][2] *= 0.125f; ss[j][3] *= 0.125f;
        }
        if (kt == qt) {
            int qr0 = warp * 16 + g;
            int qr1 = qr0 + 8;
            #pragma unroll
            for (int j = 0; j < 8; j++) {
                int k0 = 8 * j + 2 * q;
                int k1 = k0 + 1;
                if (k0 > qr0) ss[j][0] = -1e30f;
                if (k1 > qr0) ss[j][1] = -1e30f;
                if (k0 > qr1) ss[j][2] = -1e30f;
                if (k1 > qr1) ss[j][3] = -1e30f;
            }
        }

        // ---- online softmax (quad reductions) ----
        float rm0 = -1e30f, rm1 = -1e30f;
        #pragma unroll
        for (int j = 0; j < 8; j++) {
            rm0 = fmaxf(rm0, fmaxf(ss[j][0], ss[j][1]));
            rm1 = fmaxf(rm1, fmaxf(ss[j][2], ss[j][3]));
        }
        rm0 = fmaxf(rm0, __shfl_xor_sync(0xffffffffu, rm0, 1));
        rm0 = fmaxf(rm0, __shfl_xor_sync(0xffffffffu, rm0, 2));
        rm1 = fmaxf(rm1, __shfl_xor_sync(0xffffffffu, rm1, 1));
        rm1 = fmaxf(rm1, __shfl_xor_sync(0xffffffffu, rm1, 2));
        float mn0 = fmaxf(m0, rm0);
        float mn1 = fmaxf(m1, rm1);
        float corr0 = __expf(m0 - mn0);
        float corr1 = __expf(m1 - mn1);
        m0 = mn0; m1 = mn1;

        float ps0 = 0.f, ps1 = 0.f;
        #pragma unroll
        for (int j = 0; j < 8; j++) {
            ss[j][0] = __expf(ss[j][0] - mn0);
            ss[j][1] = __expf(ss[j][1] - mn0);
            ss[j][2] = __expf(ss[j][2] - mn1);
            ss[j][3] = __expf(ss[j][3] - mn1);
            ps0 += ss[j][0] + ss[j][1];
            ps1 += ss[j][2] + ss[j][3];
        }
        ps0 += __shfl_xor_sync(0xffffffffu, ps0, 1);
        ps0 += __shfl_xor_sync(0xffffffffu, ps0, 2);
        ps1 += __shfl_xor_sync(0xffffffffu, ps1, 1);
        ps1 += __shfl_xor_sync(0xffffffffu, ps1, 2);
        l0 = l0 * corr0 + ps0;
        l1 = l1 * corr1 + ps1;
        #pragma unroll
        for (int j = 0; j < 8; j++) {
            ov[j][0] *= corr0; ov[j][1] *= corr0;
            ov[j][2] *= corr1; ov[j][3] *= corr1;
        }

        // ---- O += P @ V ----
        #pragma unroll
        for (int t = 0; t < 4; t++) {
            unsigned ph0, ph1, ph2, ph3, pl0, pl1, pl2, pl3;
            bsplit2u(ss[2*t][0],   ss[2*t][1],   ph0, pl0);
            bsplit2u(ss[2*t][2],   ss[2*t][3],   ph1, pl1);
            bsplit2u(ss[2*t+1][0], ss[2*t+1][1], ph2, pl2);
            bsplit2u(ss[2*t+1][2], ss[2*t+1][3], ph3, pl3);

            #pragma unroll
            for (int jd2 = 0; jd2 < 4; jd2++) {
                int vrow = 16 * t + (lane & 7) + ((lane >> 3) & 1) * 8;
                int vch  = jd2 * 2 + (lane >> 4);
                int vsw  = vch ^ (vrow & 7);
                unsigned vaddr = stg + (unsigned)((1024 + vrow * 8 + vsw) << 4);
                unsigned vh0, vh1, vh2, vh3, vl0, vl1, vl2, vl3;
                ldsm4t(vh0, vh1, vh2, vh3, vaddr);
                ldsm4t(vl0, vl1, vl2, vl3, vaddr + (unsigned)(512 << 4));
                mma16816(ov[2*jd2],   ph0, ph1, ph2, ph3, vh0, vh1);
                mma16816(ov[2*jd2],   pl0, pl1, pl2, pl3, vh0, vh1);
                mma16816(ov[2*jd2],   ph0, ph1, ph2, ph3, vl0, vl1);
                mma16816(ov[2*jd2+1], ph0, ph1, ph2, ph3, vh2, vh3);
                mma16816(ov[2*jd2+1], pl0, pl1, pl2, pl3, vh2, vh3);
                mma16816(ov[2*jd2+1], ph0, ph1, ph2, ph3, vl2, vl3);
            }
        }

        __syncthreads();
        if (kt + 2 < nkt) { LOAD_KV(kt & 1, kt + 2); }
        CP_COMMIT();
    }
    #undef LOAD_KV

    // ---- epilogue: O / l -> hi/lo planes at [row, h*64 + dh] ----
    float invl0 = 1.0f / l0;
    float invl1 = 1.0f / l1;
    #pragma unroll
    for (int jd = 0; jd < 8; jd++) {
        size_t p0 = (qrow0 + warp * 16 + g) * DD + h * 64 + 8 * jd + 2 * q;
        size_t p1 = p0 + (size_t)8 * DD;
        wplane2(outhi, outlo, p0, ov[jd][0] * invl0, ov[jd][1] * invl0);
        wplane2(outhi, outlo, p1, ov[jd][2] * invl1, ov[jd][3] * invl1);
    }
}

// ---------------- INL integrator: fused elementwise -------------------------
__global__ void __launch_bounds__(256) inl_k(
    const float* __restrict__ xs0, const float* __restrict__ inl,
    const float* __restrict__ x1,  float* __restrict__ x2)
{
    size_t i = (size_t)blockIdx.x * blockDim.x + threadIdx.x;
    size_t row = i >> 10;
    size_t col = i & 1023;
    size_t base = row * (size_t)(4*DD) + col;
    float xs = xs0[i];
    float u  = inl[base];
    float av = inl[base + DD];
    float bv = inl[base + 2*DD];
    float gv = inl[base + 3*DD];
    float alpha = 1.0f / (1.0f + expf(-av));
    float beta  = (bv > 20.0f) ? bv : log1pf(expf(bv));
    float g     = 1.0f / (1.0f + expf(-gv));
    float vs = 0.0f;
    #pragma unroll
    for (int t = 0; t < 5; t++) {
        vs += 0.1f * (alpha * (0.0f - xs) - beta * vs + u);
        xs += 0.1f * g * vs;
    }
    x2[i] = x1[i] + xs;
}

// ---------------- launch ----------------------------------------------------
extern "C" void kernel_launch(void* const* d_in, const int* in_sizes, int n_in,
                              void* d_out, int out_size)
{
    const float* x          = (const float*)d_in[0];
    const float* ln_attn_w  = (const float*)d_in[1];
    const float* ln_attn_b  = (const float*)d_in[2];
    const float* attn_in_w  = (const float*)d_in[3];
    const float* attn_in_b  = (const float*)d_in[4];
    const float* attn_out_w = (const float*)d_in[5];
    const float* attn_out_b = (const float*)d_in[6];
    const float* ln1_w      = (const float*)d_in[7];
    const float* ln1_b      = (const float*)d_in[8];
    const float* ln2_w      = (const float*)d_in[9];
    const float* ln2_b      = (const float*)d_in[10];
    const float* inl_u_w    = (const float*)d_in[11];
    const float* inl_u_b    = (const float*)d_in[12];
    const float* inl_a_w    = (const float*)d_in[13];
    const float* inl_a_b    = (const float*)d_in[14];
    const float* inl_b_w    = (const float*)d_in[15];
    const float* inl_b_b    = (const float*)d_in[16];
    const float* inl_g_w    = (const float*)d_in[17];
    const float* inl_g_b    = (const float*)d_in[18];
    const float* ff1_w      = (const float*)d_in[19];
    const float* ff1_b      = (const float*)d_in[20];
    const float* ff2_w      = (const float*)d_in[21];
    const float* ff2_b      = (const float*)d_in[22];
    float* out = (float*)d_out;

    __nv_bfloat16 *xn_hi = 0, *xn_lo = 0, *qkv_hi = 0, *qkv_lo = 0;
    __nv_bfloat16 *att_hi = 0, *att_lo = 0;
    __nv_bfloat16 *ctx_hi = 0, *ctx_lo = 0, *h_hi = 0, *h_lo = 0;
    __nv_bfloat16 *ffh_hi = 0, *ffh_lo = 0, *w_hi = 0, *w_lo = 0;
    float *x1 = 0, *xs0 = 0, *inl = 0, *x2 = 0, *bcat = 0;
    cudaGetSymbolAddress((void**)&xn_hi,  g_xn_hi);
    cudaGetSymbolAddress((void**)&xn_lo,  g_xn_lo);
    cudaGetSymbolAddress((void**)&qkv_hi, g_qkv_hi);
    cudaGetSymbolAddress((void**)&qkv_lo, g_qkv_lo);
    cudaGetSymbolAddress((void**)&att_hi, g_att_hi);
    cudaGetSymbolAddress((void**)&att_lo, g_att_lo);
    cudaGetSymbolAddress((void**)&ctx_hi, g_ctx_hi);
    cudaGetSymbolAddress((void**)&ctx_lo, g_ctx_lo);
    cudaGetSymbolAddress((void**)&h_hi,   g_h_hi);
    cudaGetSymbolAddress((void**)&h_lo,   g_h_lo);
    cudaGetSymbolAddress((void**)&ffh_hi, g_ffh_hi);
    cudaGetSymbolAddress((void**)&ffh_lo, g_ffh_lo);
    cudaGetSymbolAddress((void**)&w_hi,   g_w_hi);
    cudaGetSymbolAddress((void**)&w_lo,   g_w_lo);
    cudaGetSymbolAddress((void**)&x1,     g_x1);
    cudaGetSymbolAddress((void**)&xs0,    g_xs0);
    cudaGetSymbolAddress((void**)&inl,    g_inl);
    cudaGetSymbolAddress((void**)&x2,     g_x2);
    cudaGetSymbolAddress((void**)&bcat,   g_bcat);

    cudaFuncSetAttribute(gemm_bf<0>,
        cudaFuncAttributeMaxDynamicSharedMemorySize, GEM_SMEM);
    cudaFuncSetAttribute(gemm_bf<1>,
        cudaFuncAttributeMaxDynamicSharedMemorySize, GEM_SMEM);
    cudaFuncSetAttribute(gemm_bf<2>,
        cudaFuncAttributeMaxDynamicSharedMemorySize, GEM_SMEM);
    cudaFuncSetAttribute(gemm_bf<3>,
        cudaFuncAttributeMaxDynamicSharedMemorySize, GEM_SMEM);
    cudaFuncSetAttribute(gemm_bf<4>,
        cudaFuncAttributeMaxDynamicSharedMemorySize, GEM_SMEM);
    cudaFuncSetAttribute(flash_attn_tc,
        cudaFuncAttributeMaxDynamicSharedMemorySize, FA_SMEM);

    // 0) weight plane conversion + bias concat
    conv_w_k<<<(int)(W_TOTAL / 512), 256>>>(
        attn_in_w, attn_out_w, inl_u_w, inl_a_w, inl_b_w, inl_g_w, ff1_w, ff2_w);
    bias_cat_k<<<16, 256>>>(inl_u_b, inl_a_b, inl_b_b, inl_g_b);

    // 1) pre-attn LN -> xn planes
    layernorm_p<<<ROWS, 256>>>(x, ln_attn_w, ln_attn_b, xn_hi, xn_lo);

    // 2) QKV projection -> qkv planes
    gemm_bf<4><<<dim3(3*DD/128, ROWS/128), 128, GEM_SMEM>>>(
        xn_hi, xn_lo, w_hi + WOFF_ATTNIN, w_lo + WOFF_ATTNIN,
        attn_in_b, ROWS, 3*DD, DD, (float*)0, (const float*)0, (float*)0,
        qkv_hi, qkv_lo);

    // 3) tensor-core causal flash attention -> att planes
    flash_attn_tc<<<dim3(SS/64, HH, BB), 128, FA_SMEM>>>(
        qkv_hi, qkv_lo, att_hi, att_lo);

    // 4) out-projection: ctx planes = proj+bias, x1 = x + proj+bias
    gemm_bf<1><<<dim3(DD/128, ROWS/128), 128, GEM_SMEM>>>(
        att_hi, att_lo, w_hi + WOFF_ATTNOUT, w_lo + WOFF_ATTNOUT,
        attn_out_b, ROWS, DD, DD, (float*)0, x, x1, ctx_hi, ctx_lo);

    // 5) LN1(x1) -> xs0 fp32
    layernorm_f<<<ROWS, 256>>>(x1, ln1_w, ln1_b, xs0);

    // 6) fused INL controller projections: [ROWS, 4096] fp32
    gemm_bf<0><<<dim3(4*DD/128, ROWS/128), 128, GEM_SMEM>>>(
        ctx_hi, ctx_lo, w_hi + WOFF_INL, w_lo + WOFF_INL,
        bcat, ROWS, 4*DD, DD, inl, (const float*)0, (float*)0,
        (__nv_bfloat16*)0, (__nv_bfloat16*)0);

    // 7) fused INL dynamics: x2 = x1 + xs(5 steps)
    inl_k<<<(ROWS*(size_t)DD)/256, 256>>>(xs0, inl, x1, x2);

    // 8) LN2(x2) -> h planes
    layernorm_p<<<ROWS, 256>>>(x2, ln2_w, ln2_b, h_hi, h_lo);

    // 9) FF1 + exact GELU -> ffh planes
    gemm_bf<2><<<dim3(FFD/128, ROWS/128), 128, GEM_SMEM>>>(
        h_hi, h_lo, w_hi + WOFF_FF1, w_lo + WOFF_FF1,
        ff1_b, ROWS, FFD, DD, (float*)0, (const float*)0, (float*)0,
        ffh_hi, ffh_lo);

    // 10) FF2 + bias + residual -> out
    gemm_bf<3><<<dim3(DD/128, ROWS/128), 128, GEM_SMEM>>>(
        ffh_hi, ffh_lo, w_hi + WOFF_FF2, w_lo + WOFF_FF2,
        ff2_b, ROWS, DD, FFD, out, x2, (float*)0,
        (__nv_bfloat16*)0, (__nv_bfloat16*)0);
}

// round 12
// speedup vs baseline: 4.6511x; 1.3597x over previous
#include <cuda_runtime.h>
#include <cuda_fp16.h>
#include <cstdint>
#include <math.h>

// Problem constants
#define BB   4
#define SS   2048
#define DD   1024
#define HH   16
#define DHD  64
#define FFD  4096
#define ROWS (BB*SS)

// ---------------- scratch (device globals; no allocation allowed) ----------
// fp16 hi/lo planes for GEMM A-inputs (activations)
__device__ __half g_xn_hi [(size_t)ROWS*DD];
__device__ __half g_xn_lo [(size_t)ROWS*DD];
__device__ __half g_qkv_hi[(size_t)ROWS*3*DD];
__device__ __half g_qkv_lo[(size_t)ROWS*3*DD];
__device__ __half g_att_hi[(size_t)ROWS*DD];
__device__ __half g_att_lo[(size_t)ROWS*DD];
__device__ __half g_ctx_hi[(size_t)ROWS*DD];
__device__ __half g_ctx_lo[(size_t)ROWS*DD];
__device__ __half g_h_hi  [(size_t)ROWS*DD];
__device__ __half g_h_lo  [(size_t)ROWS*DD];
__device__ __half g_ffh_hi[(size_t)ROWS*FFD];
__device__ __half g_ffh_lo[(size_t)ROWS*FFD];
// weight planes (hi only; B operand uses fp16 rounding):
#define W_TOTAL ((size_t)16*1024*1024)
#define WOFF_ATTNIN  ((size_t)0)
#define WOFF_ATTNOUT ((size_t)3*1024*1024)
#define WOFF_INL     ((size_t)4*1024*1024)
#define WOFF_FF1     ((size_t)8*1024*1024)
#define WOFF_FF2     ((size_t)12*1024*1024)
__device__ __half g_w_hi[W_TOTAL];
__device__ float g_bcat[4*DD];
// fp32 intermediates
__device__ float g_x1 [(size_t)ROWS*DD];
__device__ float g_xs0[(size_t)ROWS*DD];
__device__ float g_inl[(size_t)ROWS*4*DD];
__device__ float g_x2 [(size_t)ROWS*DD];

// ---------------- helpers ---------------------------------------------------
__device__ __forceinline__ void wplane2(__half* hi, __half* lo,
                                        size_t idx, float v0, float v1)
{
    __half2 h = __floats2half2_rn(v0, v1);
    float2 hf = __half22float2(h);
    __half2 l = __floats2half2_rn(v0 - hf.x, v1 - hf.y);
    *reinterpret_cast<__half2*>(hi + idx) = h;
    *reinterpret_cast<__half2*>(lo + idx) = l;
}

__device__ __forceinline__ void hsplit2u(float x, float y,
                                         unsigned &h, unsigned &l)
{
    __half2 hb = __floats2half2_rn(x, y);
    float2 hf = __half22float2(hb);
    __half2 lb = __floats2half2_rn(x - hf.x, y - hf.y);
    h = *reinterpret_cast<unsigned*>(&hb);
    l = *reinterpret_cast<unsigned*>(&lb);
}

// ---------------- weight conversion (hi plane only) -------------------------
__global__ void __launch_bounds__(256) conv_w_k(
    const float* __restrict__ attn_in_w, const float* __restrict__ attn_out_w,
    const float* __restrict__ inl_u_w,   const float* __restrict__ inl_a_w,
    const float* __restrict__ inl_b_w,   const float* __restrict__ inl_g_w,
    const float* __restrict__ ff1_w,     const float* __restrict__ ff2_w)
{
    size_t e = ((size_t)blockIdx.x * 256 + threadIdx.x) * 2;
    const float* src;
    size_t off;
    if      (e < WOFF_ATTNOUT) { src = attn_in_w;  off = e - WOFF_ATTNIN; }
    else if (e < WOFF_INL)     { src = attn_out_w; off = e - WOFF_ATTNOUT; }
    else if (e < WOFF_INL + (size_t)1024*1024)   { src = inl_u_w; off = e - WOFF_INL; }
    else if (e < WOFF_INL + (size_t)2*1024*1024) { src = inl_a_w; off = e - WOFF_INL - (size_t)1024*1024; }
    else if (e < WOFF_INL + (size_t)3*1024*1024) { src = inl_b_w; off = e - WOFF_INL - (size_t)2*1024*1024; }
    else if (e < WOFF_FF1)     { src = inl_g_w; off = e - WOFF_INL - (size_t)3*1024*1024; }
    else if (e < WOFF_FF2)     { src = ff1_w;   off = e - WOFF_FF1; }
    else                       { src = ff2_w;   off = e - WOFF_FF2; }
    float2 v = *reinterpret_cast<const float2*>(src + off);
    __half2 h = __floats2half2_rn(v.x, v.y);
    *reinterpret_cast<__half2*>(g_w_hi + e) = h;
}

__global__ void bias_cat_k(const float* __restrict__ ub, const float* __restrict__ ab,
                           const float* __restrict__ bb, const float* __restrict__ gb)
{
    int i = blockIdx.x * 256 + threadIdx.x;
    int sel = i >> 10;
    int c = i & 1023;
    float v;
    if (sel == 0) v = ub[c];
    else if (sel == 1) v = ab[c];
    else if (sel == 2) v = bb[c];
    else v = gb[c];
    g_bcat[i] = v;
}

// ---------------- LayerNorm (fp32 out) --------------------------------------
__global__ void __launch_bounds__(256) layernorm_f(
    const float* __restrict__ x, const float* __restrict__ w,
    const float* __restrict__ b, float* __restrict__ y)
{
    int row = blockIdx.x;
    const float* xr = x + (size_t)row * DD;
    int tid = threadIdx.x;
    float4 v = *reinterpret_cast<const float4*>(xr + tid * 4);
    float s  = v.x + v.y + v.z + v.w;
    float ss = v.x*v.x + v.y*v.y + v.z*v.z + v.w*v.w;
    #pragma unroll
    for (int off = 16; off > 0; off >>= 1) {
        s  += __shfl_xor_sync(0xffffffffu, s,  off);
        ss += __shfl_xor_sync(0xffffffffu, ss, off);
    }
    __shared__ float sh_s[8];
    __shared__ float sh_ss[8];
    int wid = tid >> 5;
    int lane = tid & 31;
    if (lane == 0) { sh_s[wid] = s; sh_ss[wid] = ss; }
    __syncthreads();
    float ts = 0.f, tss = 0.f;
    #pragma unroll
    for (int i = 0; i < 8; i++) { ts += sh_s[i]; tss += sh_ss[i]; }
    float mu   = ts * (1.0f / DD);
    float var  = tss * (1.0f / DD) - mu * mu;
    float rstd = rsqrtf(var + 1e-5f);
    float4 wv = *reinterpret_cast<const float4*>(w + tid * 4);
    float4 bv = *reinterpret_cast<const float4*>(b + tid * 4);
    float4 o;
    o.x = (v.x - mu) * rstd * wv.x + bv.x;
    o.y = (v.y - mu) * rstd * wv.y + bv.y;
    o.z = (v.z - mu) * rstd * wv.z + bv.z;
    o.w = (v.w - mu) * rstd * wv.w + bv.w;
    *reinterpret_cast<float4*>(y + (size_t)row * DD + tid * 4) = o;
}

// ---------------- LayerNorm (fp16 hi/lo plane out) --------------------------
__global__ void __launch_bounds__(256) layernorm_p(
    const float* __restrict__ x, const float* __restrict__ w,
    const float* __restrict__ b,
    __half* __restrict__ yhi, __half* __restrict__ ylo)
{
    int row = blockIdx.x;
    const float* xr = x + (size_t)row * DD;
    int tid = threadIdx.x;
    float4 v = *reinterpret_cast<const float4*>(xr + tid * 4);
    float s  = v.x + v.y + v.z + v.w;
    float ss = v.x*v.x + v.y*v.y + v.z*v.z + v.w*v.w;
    #pragma unroll
    for (int off = 16; off > 0; off >>= 1) {
        s  += __shfl_xor_sync(0xffffffffu, s,  off);
        ss += __shfl_xor_sync(0xffffffffu, ss, off);
    }
    __shared__ float sh_s[8];
    __shared__ float sh_ss[8];
    int wid = tid >> 5;
    int lane = tid & 31;
    if (lane == 0) { sh_s[wid] = s; sh_ss[wid] = ss; }
    __syncthreads();
    float ts = 0.f, tss = 0.f;
    #pragma unroll
    for (int i = 0; i < 8; i++) { ts += sh_s[i]; tss += sh_ss[i]; }
    float mu   = ts * (1.0f / DD);
    float var  = tss * (1.0f / DD) - mu * mu;
    float rstd = rsqrtf(var + 1e-5f);
    float4 wv = *reinterpret_cast<const float4*>(w + tid * 4);
    float4 bv = *reinterpret_cast<const float4*>(b + tid * 4);
    float o0 = (v.x - mu) * rstd * wv.x + bv.x;
    float o1 = (v.y - mu) * rstd * wv.y + bv.y;
    float o2 = (v.z - mu) * rstd * wv.z + bv.z;
    float o3 = (v.w - mu) * rstd * wv.w + bv.w;
    size_t base = (size_t)row * DD + tid * 4;
    wplane2(yhi, ylo, base,     o0, o1);
    wplane2(yhi, ylo, base + 2, o2, o3);
}

// ============================================================================
// asm wrappers
// ============================================================================
#define CP16(d, s) asm volatile("cp.async.cg.shared.global [%0], [%1], 16;\n" :: "r"(d), "l"(s))
#define CP_COMMIT() asm volatile("cp.async.commit_group;\n" ::)
#define CP_WAIT1() asm volatile("cp.async.wait_group 1;\n" ::)
#define CP_WAIT2() asm volatile("cp.async.wait_group 2;\n" ::)

__device__ __forceinline__ void ldsm4(unsigned &r0, unsigned &r1,
                                      unsigned &r2, unsigned &r3,
                                      unsigned addr)
{
    asm volatile(
        "ldmatrix.sync.aligned.m8n8.x4.shared.b16 {%0,%1,%2,%3}, [%4];\n"
        : "=r"(r0), "=r"(r1), "=r"(r2), "=r"(r3)
        : "r"(addr));
}

__device__ __forceinline__ void ldsm4t(unsigned &r0, unsigned &r1,
                                       unsigned &r2, unsigned &r3,
                                       unsigned addr)
{
    asm volatile(
        "ldmatrix.sync.aligned.m8n8.x4.trans.shared.b16 {%0,%1,%2,%3}, [%4];\n"
        : "=r"(r0), "=r"(r1), "=r"(r2), "=r"(r3)
        : "r"(addr));
}

__device__ __forceinline__ void mmaf16(float* c,
    unsigned a0, unsigned a1, unsigned a2, unsigned a3,
    unsigned b0, unsigned b1)
{
    asm volatile(
        "mma.sync.aligned.m16n8k16.row.col.f32.f16.f16.f32 "
        "{%0,%1,%2,%3}, {%4,%5,%6,%7}, {%8,%9}, {%0,%1,%2,%3};\n"
        : "+f"(c[0]), "+f"(c[1]), "+f"(c[2]), "+f"(c[3])
        : "r"(a0), "r"(a1), "r"(a2), "r"(a3), "r"(b0), "r"(b1));
}

// ============================================================================
// fp16 2-term tensor-core GEMM: C[M,N] = (Ahi+Alo) @ Bhi[N,K]^T, fp32 accum.
// Block tile 128x128x32, 128 threads (4 warps 2x2), warp tile 64x64.
// 3-stage cp.async; 24KB/stage (Ahi,Alo,Bhi).
// EPI: 0 fp32+bias; 1 planes(v+bias)+C2=res+v; 2 planes(GELU(v+bias));
//      3 fp32 v+bias+res; 4 planes(v+bias).
// ============================================================================
#define STG_CHUNK 1536
#define GEM_SMEM (3 * STG_CHUNK * 16)   // 73728

template<int EPI>
__global__ void __launch_bounds__(128, 2) gemm_f16(
    const __half* __restrict__ Ahi, const __half* __restrict__ Alo,
    const __half* __restrict__ Bhi,
    const float* __restrict__ bias, int M, int N, int K,
    float* __restrict__ C, const float* __restrict__ res, float* __restrict__ C2,
    __half* __restrict__ Chi, __half* __restrict__ Clo)
{
    extern __shared__ uint4 sm4[];
    const int tid  = threadIdx.x;
    const int lane = tid & 31;
    const int warp = tid >> 5;
    const int wm   = warp >> 1;
    const int wn   = warp & 1;
    const int bm   = blockIdx.y * 128;
    const int bn   = blockIdx.x * 128;

    const unsigned sbase =
        (unsigned)__cvta_generic_to_shared((void*)sm4);

    float acc[4][8][4];
    #pragma unroll
    for (int i = 0; i < 4; i++) {
        #pragma unroll
        for (int j = 0; j < 8; j++) {
            #pragma unroll
            for (int q = 0; q < 4; q++) acc[i][j][q] = 0.f;
        }
    }

    const int ar      = lane & 15;
    const int acolsel = lane >> 4;
    const int br      = (lane & 7) | ((lane >> 4) << 3);
    const int bcolsel = (lane >> 3) & 1;

    const int nk = K / 32;

    // stage loader: 1536 chunks / 128 threads = 12 each.
    // plane: 0 Ahi, 1 Alo, 2 Bhi; each plane 128 rows x 4 chunks (64B rows)
    #define LOAD_STAGE(stg, kt_)                                                \
    {                                                                           \
        int k0 = (kt_) * 32;                                                    \
        _Pragma("unroll")                                                       \
        for (int it = 0; it < 12; it++) {                                       \
            int c   = tid + it * 128;                                           \
            int plane = c >> 9;                                                 \
            int rem = c & 511;                                                  \
            int row = rem >> 2;                                                 \
            int col = rem & 3;                                                  \
            int sw  = col ^ ((row >> 1) & 3);                                   \
            unsigned daddr = sbase +                                            \
                (unsigned)((((stg) * STG_CHUNK) + plane * 512 + row * 4 + sw) << 4); \
            const __half* gp;                                                   \
            size_t goff;                                                        \
            if (plane == 0)      { gp = Ahi; goff = (size_t)(bm + row) * K + k0 + col * 8; } \
            else if (plane == 1) { gp = Alo; goff = (size_t)(bm + row) * K + k0 + col * 8; } \
            else                 { gp = Bhi; goff = (size_t)(bn + row) * K + k0 + col * 8; } \
            CP16(daddr, gp + goff);                                             \
        }                                                                       \
    }

    LOAD_STAGE(0, 0);
    CP_COMMIT();
    LOAD_STAGE(1, 1);
    CP_COMMIT();
    LOAD_STAGE(2, 2);
    CP_COMMIT();

    int stg = 0;
    for (int kt = 0; kt < nk; kt++) {
        CP_WAIT2();
        __syncthreads();
        const int stOff = stg * STG_CHUNK;

        #pragma unroll
        for (int s = 0; s < 2; s++) {
            unsigned ahi[4][4];
            unsigned alo[4][4];
            #pragma unroll
            for (int i = 0; i < 4; i++) {
                int row = wm * 64 + i * 16 + ar;
                int chunk = 2 * s + acolsel;
                int sw = chunk ^ ((row >> 1) & 3);
                unsigned ad = sbase +
                    (unsigned)((stOff + row * 4 + sw) << 4);
                ldsm4(ahi[i][0], ahi[i][1], ahi[i][2], ahi[i][3], ad);
                ldsm4(alo[i][0], alo[i][1], alo[i][2], alo[i][3],
                      ad + (unsigned)(512 << 4));
            }
            #pragma unroll
            for (int p = 0; p < 4; p++) {
                int row = wn * 64 + p * 16 + br;
                int chunk = 2 * s + bcolsel;
                int sw = chunk ^ ((row >> 1) & 3);
                unsigned bd = sbase +
                    (unsigned)((stOff + 1024 + row * 4 + sw) << 4);
                unsigned bh0, bh1, bh2, bh3;
                ldsm4(bh0, bh1, bh2, bh3, bd);
                #pragma unroll
                for (int i = 0; i < 4; i++) {
                    mmaf16(acc[i][2*p],
                           ahi[i][0], ahi[i][1], ahi[i][2], ahi[i][3], bh0, bh1);
                    mmaf16(acc[i][2*p],
                           alo[i][0], alo[i][1], alo[i][2], alo[i][3], bh0, bh1);
                    mmaf16(acc[i][2*p+1],
                           ahi[i][0], ahi[i][1], ahi[i][2], ahi[i][3], bh2, bh3);
                    mmaf16(acc[i][2*p+1],
                           alo[i][0], alo[i][1], alo[i][2], alo[i][3], bh2, bh3);
                }
            }
        }
        __syncthreads();
        if (kt + 3 < nk) {
            LOAD_STAGE(stg, kt + 3);
        }
        CP_COMMIT();
        stg = (stg == 2) ? 0 : stg + 1;
    }
    #undef LOAD_STAGE

    const int rg = lane >> 2;
    const int q2 = (lane & 3) * 2;
    #pragma unroll
    for (int i = 0; i < 4; i++) {
        int r0 = bm + wm * 64 + i * 16 + rg;
        int r1 = r0 + 8;
        #pragma unroll
        for (int j = 0; j < 8; j++) {
            int col = bn + wn * 64 + j * 8 + q2;
            float b0 = bias[col];
            float b1 = bias[col + 1];
            float v0 = acc[i][j][0] + b0;
            float v1 = acc[i][j][1] + b1;
            float v2 = acc[i][j][2] + b0;
            float v3 = acc[i][j][3] + b1;
            size_t p0 = (size_t)r0 * N + col;
            size_t p1 = (size_t)r1 * N + col;
            if (EPI == 0) {
                C[p0] = v0; C[p0 + 1] = v1;
                C[p1] = v2; C[p1 + 1] = v3;
            }
            if (EPI == 1) {
                wplane2(Chi, Clo, p0, v0, v1);
                wplane2(Chi, Clo, p1, v2, v3);
                C2[p0]     = res[p0]     + v0;
                C2[p0 + 1] = res[p0 + 1] + v1;
                C2[p1]     = res[p1]     + v2;
                C2[p1 + 1] = res[p1 + 1] + v3;
            }
            if (EPI == 2) {
                v0 = 0.5f * v0 * (1.0f + erff(v0 * 0.70710678118654752f));
                v1 = 0.5f * v1 * (1.0f + erff(v1 * 0.70710678118654752f));
                v2 = 0.5f * v2 * (1.0f + erff(v2 * 0.70710678118654752f));
                v3 = 0.5f * v3 * (1.0f + erff(v3 * 0.70710678118654752f));
                wplane2(Chi, Clo, p0, v0, v1);
                wplane2(Chi, Clo, p1, v2, v3);
            }
            if (EPI == 3) {
                C[p0]     = v0 + res[p0];
                C[p0 + 1] = v1 + res[p0 + 1];
                C[p1]     = v2 + res[p1];
                C[p1 + 1] = v3 + res[p1 + 1];
            }
            if (EPI == 4) {
                wplane2(Chi, Clo, p0, v0, v1);
                wplane2(Chi, Clo, p1, v2, v3);
            }
        }
    }
}

// ============================================================================
// Tensor-core causal flash attention, fp16 2-term (Q,P split; K,V hi-only).
// Block: 64 queries x (head, batch); 128 threads = 4 warps, warp owns m16.
// smem chunks: Qhi[512] Qlo[512] | 2 stages x {Khi[512], Vhi[512]}
// ============================================================================
#define FA_SMEM (3072 * 16)   // 48 KB

__global__ void __launch_bounds__(128) flash_attn_tc(
    const __half* __restrict__ qhi, const __half* __restrict__ qlo,
    __half* __restrict__ outhi, __half* __restrict__ outlo)
{
    extern __shared__ uint4 sm4[];
    const int tid  = threadIdx.x;
    const int lane = tid & 31;
    const int warp = tid >> 5;
    const int qt = blockIdx.x;
    const int h  = blockIdx.y;
    const int b  = blockIdx.z;
    const unsigned smem_base =
        (unsigned)__cvta_generic_to_shared((void*)sm4);

    const size_t rstr = 3 * DD;
    const size_t qrow0  = (size_t)b * SS + (size_t)qt * 64;
    const size_t kvrow0 = (size_t)b * SS;

    // ---- Q tile load (hi+lo) ----
    #pragma unroll
    for (int it = 0; it < 8; it++) {
        int c = tid + it * 128;
        int plane = c >> 9;
        int rem = c & 511;
        int row = rem >> 3;
        int ch  = rem & 7;
        int sw  = ch ^ (row & 7);
        unsigned d = smem_base + (unsigned)((plane * 512 + row * 8 + sw) << 4);
        const __half* src = (plane ? qlo : qhi);
        CP16(d, src + (qrow0 + row) * rstr + h * 64 + ch * 8);
    }
    CP_COMMIT();

    const int nkt = qt + 1;

    // KV stage: Khi at +0, Vhi at +512 chunks; stage stride 1024 chunks
    #define LOAD_KV(stg_, kt_)                                                  \
    {                                                                           \
        size_t krow = kvrow0 + (size_t)(kt_) * 64;                              \
        _Pragma("unroll")                                                       \
        for (int it = 0; it < 8; it++) {                                        \
            int c = tid + it * 128;                                             \
            int plane = c >> 9;   /* 0 Khi, 1 Vhi */                            \
            int rem = c & 511;                                                  \
            int row = rem >> 3;                                                 \
            int ch  = rem & 7;                                                  \
            int sw  = ch ^ (row & 7);                                           \
            unsigned d = smem_base +                                            \
                (unsigned)((1024 + (stg_) * 1024 + plane * 512 + row * 8 + sw) << 4); \
            size_t off = (krow + row) * rstr +                                  \
                         (plane ? 2 * DD : DD) + h * 64 + ch * 8;               \
            CP16(d, qhi + off);                                                 \
        }                                                                       \
    }

    LOAD_KV(0, 0);
    CP_COMMIT();
    if (nkt > 1) { LOAD_KV(1, 1); }
    CP_COMMIT();

    const int g = lane >> 2;
    const int q = lane & 3;

    float m0 = -INFINITY, m1 = -INFINITY;
    float l0 = 0.f, l1 = 0.f;
    float ov[8][4];
    #pragma unroll
    for (int j = 0; j < 8; j++) {
        #pragma unroll
        for (int k = 0; k < 4; k++) ov[j][k] = 0.f;
    }

    for (int kt = 0; kt < nkt; kt++) {
        CP_WAIT1();
        __syncthreads();
        const unsigned stg = smem_base +
            (unsigned)((1024 + (kt & 1) * 1024) << 4);

        // ---- S = Q @ K^T (2-term) ----
        float ss[8][4];
        #pragma unroll
        for (int j = 0; j < 8; j++) {
            #pragma unroll
            for (int k = 0; k < 4; k++) ss[j][k] = 0.f;
        }

        #pragma unroll
        for (int t = 0; t < 4; t++) {
            int arow = warp * 16 + (lane & 15);
            int ach  = 2 * t + (lane >> 4);
            int asw  = ach ^ (arow & 7);
            unsigned aaddr = smem_base + (unsigned)((arow * 8 + asw) << 4);
            unsigned qh0, qh1, qh2, qh3, ql0, ql1, ql2, ql3;
            ldsm4(qh0, qh1, qh2, qh3, aaddr);
            ldsm4(ql0, ql1, ql2, ql3, aaddr + (unsigned)(512 << 4));

            #pragma unroll
            for (int pb = 0; pb < 4; pb++) {
                int brow = pb * 16 + ((lane & 7) | ((lane >> 4) << 3));
                int bch  = 2 * t + ((lane >> 3) & 1);
                int bsw  = bch ^ (brow & 7);
                unsigned baddr = stg + (unsigned)((brow * 8 + bsw) << 4);
                unsigned kh0, kh1, kh2, kh3;
                ldsm4(kh0, kh1, kh2, kh3, baddr);
                mmaf16(ss[2*pb],   qh0, qh1, qh2, qh3, kh0, kh1);
                mmaf16(ss[2*pb],   ql0, ql1, ql2, ql3, kh0, kh1);
                mmaf16(ss[2*pb+1], qh0, qh1, qh2, qh3, kh2, kh3);
                mmaf16(ss[2*pb+1], ql0, ql1, ql2, ql3, kh2, kh3);
            }
        }

        // ---- scale + causal mask ----
        #pragma unroll
        for (int j = 0; j < 8; j++) {
            ss[j][0] *= 0.125f; ss[j][1] *= 0.125f;
            ss[j][2] *= 0.125f; ss[j][3] *= 0.125f;
        }
        if (kt == qt) {
            int qr0 = warp * 16 + g;
            int qr1 = qr0 + 8;
            #pragma unroll
            for (int j = 0; j < 8; j++) {
                int k0 = 8 * j + 2 * q;
                int k1 = k0 + 1;
                if (k0 > qr0) ss[j][0] = -1e30f;
                if (k1 > qr0) ss[j][1] = -1e30f;
                if (k0 > qr1) ss[j][2] = -1e30f;
                if (k1 > qr1) ss[j][3] = -1e30f;
            }
        }

        // ---- online softmax ----
        float rm0 = -1e30f, rm1 = -1e30f;
        #pragma unroll
        for (int j = 0; j < 8; j++) {
            rm0 = fmaxf(rm0, fmaxf(ss[j][0], ss[j][1]));
            rm1 = fmaxf(rm1, fmaxf(ss[j][2], ss[j][3]));
        }
        rm0 = fmaxf(rm0, __shfl_xor_sync(0xffffffffu, rm0, 1));
        rm0 = fmaxf(rm0, __shfl_xor_sync(0xffffffffu, rm0, 2));
        rm1 = fmaxf(rm1, __shfl_xor_sync(0xffffffffu, rm1, 1));
        rm1 = fmaxf(rm1, __shfl_xor_sync(0xffffffffu, rm1, 2));
        float mn0 = fmaxf(m0, rm0);
        float mn1 = fmaxf(m1, rm1);
        float corr0 = __expf(m0 - mn0);
        float corr1 = __expf(m1 - mn1);
        m0 = mn0; m1 = mn1;

        float ps0 = 0.f, ps1 = 0.f;
        #pragma unroll
        for (int j = 0; j < 8; j++) {
            ss[j][0] = __expf(ss[j][0] - mn0);
            ss[j][1] = __expf(ss[j][1] - mn0);
            ss[j][2] = __expf(ss[j][2] - mn1);
            ss[j][3] = __expf(ss[j][3] - mn1);
            ps0 += ss[j][0] + ss[j][1];
            ps1 += ss[j][2] + ss[j][3];
        }
        ps0 += __shfl_xor_sync(0xffffffffu, ps0, 1);
        ps0 += __shfl_xor_sync(0xffffffffu, ps0, 2);
        ps1 += __shfl_xor_sync(0xffffffffu, ps1, 1);
        ps1 += __shfl_xor_sync(0xffffffffu, ps1, 2);
        l0 = l0 * corr0 + ps0;
        l1 = l1 * corr1 + ps1;
        #pragma unroll
        for (int j = 0; j < 8; j++) {
            ov[j][0] *= corr0; ov[j][1] *= corr0;
            ov[j][2] *= corr1; ov[j][3] *= corr1;
        }

        // ---- O += P @ V (P split, V hi-only) ----
        #pragma unroll
        for (int t = 0; t < 4; t++) {
            unsigned ph0, ph1, ph2, ph3, pl0, pl1, pl2, pl3;
            hsplit2u(ss[2*t][0],   ss[2*t][1],   ph0, pl0);
            hsplit2u(ss[2*t][2],   ss[2*t][3],   ph1, pl1);
            hsplit2u(ss[2*t+1][0], ss[2*t+1][1], ph2, pl2);
            hsplit2u(ss[2*t+1][2], ss[2*t+1][3], ph3, pl3);

            #pragma unroll
            for (int jd2 = 0; jd2 < 4; jd2++) {
                int vrow = 16 * t + (lane & 7) + ((lane >> 3) & 1) * 8;
                int vch  = jd2 * 2 + (lane >> 4);
                int vsw  = vch ^ (vrow & 7);
                unsigned vaddr = stg + (unsigned)((512 + vrow * 8 + vsw) << 4);
                unsigned vh0, vh1, vh2, vh3;
                ldsm4t(vh0, vh1, vh2, vh3, vaddr);
                mmaf16(ov[2*jd2],   ph0, ph1, ph2, ph3, vh0, vh1);
                mmaf16(ov[2*jd2],   pl0, pl1, pl2, pl3, vh0, vh1);
                mmaf16(ov[2*jd2+1], ph0, ph1, ph2, ph3, vh2, vh3);
                mmaf16(ov[2*jd2+1], pl0, pl1, pl2, pl3, vh2, vh3);
            }
        }

        __syncthreads();
        if (kt + 2 < nkt) { LOAD_KV(kt & 1, kt + 2); }
        CP_COMMIT();
    }
    #undef LOAD_KV

    float invl0 = 1.0f / l0;
    float invl1 = 1.0f / l1;
    #pragma unroll
    for (int jd = 0; jd < 8; jd++) {
        size_t p0 = (qrow0 + warp * 16 + g) * DD + h * 64 + 8 * jd + 2 * q;
        size_t p1 = p0 + (size_t)8 * DD;
        wplane2(outhi, outlo, p0, ov[jd][0] * invl0, ov[jd][1] * invl0);
        wplane2(outhi, outlo, p1, ov[jd][2] * invl1, ov[jd][3] * invl1);
    }
}

// ---------------- INL integrator: fused elementwise -------------------------
__global__ void __launch_bounds__(256) inl_k(
    const float* __restrict__ xs0, const float* __restrict__ inl,
    const float* __restrict__ x1,  float* __restrict__ x2)
{
    size_t i = (size_t)blockIdx.x * blockDim.x + threadIdx.x;
    size_t row = i >> 10;
    size_t col = i & 1023;
    size_t base = row * (size_t)(4*DD) + col;
    float xs = xs0[i];
    float u  = inl[base];
    float av = inl[base + DD];
    float bv = inl[base + 2*DD];
    float gv = inl[base + 3*DD];
    float alpha = 1.0f / (1.0f + expf(-av));
    float beta  = (bv > 20.0f) ? bv : log1pf(expf(bv));
    float g     = 1.0f / (1.0f + expf(-gv));
    float vs = 0.0f;
    #pragma unroll
    for (int t = 0; t < 5; t++) {
        vs += 0.1f * (alpha * (0.0f - xs) - beta * vs + u);
        xs += 0.1f * g * vs;
    }
    x2[i] = x1[i] + xs;
}

// ---------------- launch ----------------------------------------------------
extern "C" void kernel_launch(void* const* d_in, const int* in_sizes, int n_in,
                              void* d_out, int out_size)
{
    const float* x          = (const float*)d_in[0];
    const float* ln_attn_w  = (const float*)d_in[1];
    const float* ln_attn_b  = (const float*)d_in[2];
    const float* attn_in_w  = (const float*)d_in[3];
    const float* attn_in_b  = (const float*)d_in[4];
    const float* attn_out_w = (const float*)d_in[5];
    const float* attn_out_b = (const float*)d_in[6];
    const float* ln1_w      = (const float*)d_in[7];
    const float* ln1_b      = (const float*)d_in[8];
    const float* ln2_w      = (const float*)d_in[9];
    const float* ln2_b      = (const float*)d_in[10];
    const float* inl_u_w    = (const float*)d_in[11];
    const float* inl_u_b    = (const float*)d_in[12];
    const float* inl_a_w    = (const float*)d_in[13];
    const float* inl_a_b    = (const float*)d_in[14];
    const float* inl_b_w    = (const float*)d_in[15];
    const float* inl_b_b    = (const float*)d_in[16];
    const float* inl_g_w    = (const float*)d_in[17];
    const float* inl_g_b    = (const float*)d_in[18];
    const float* ff1_w      = (const float*)d_in[19];
    const float* ff1_b      = (const float*)d_in[20];
    const float* ff2_w      = (const float*)d_in[21];
    const float* ff2_b      = (const float*)d_in[22];
    float* out = (float*)d_out;

    __half *xn_hi = 0, *xn_lo = 0, *qkv_hi = 0, *qkv_lo = 0;
    __half *att_hi = 0, *att_lo = 0;
    __half *ctx_hi = 0, *ctx_lo = 0, *h_hi = 0, *h_lo = 0;
    __half *ffh_hi = 0, *ffh_lo = 0, *w_hi = 0;
    float *x1 = 0, *xs0 = 0, *inl = 0, *x2 = 0, *bcat = 0;
    cudaGetSymbolAddress((void**)&xn_hi,  g_xn_hi);
    cudaGetSymbolAddress((void**)&xn_lo,  g_xn_lo);
    cudaGetSymbolAddress((void**)&qkv_hi, g_qkv_hi);
    cudaGetSymbolAddress((void**)&qkv_lo, g_qkv_lo);
    cudaGetSymbolAddress((void**)&att_hi, g_att_hi);
    cudaGetSymbolAddress((void**)&att_lo, g_att_lo);
    cudaGetSymbolAddress((void**)&ctx_hi, g_ctx_hi);
    cudaGetSymbolAddress((void**)&ctx_lo, g_ctx_lo);
    cudaGetSymbolAddress((void**)&h_hi,   g_h_hi);
    cudaGetSymbolAddress((void**)&h_lo,   g_h_lo);
    cudaGetSymbolAddress((void**)&ffh_hi, g_ffh_hi);
    cudaGetSymbolAddress((void**)&ffh_lo, g_ffh_lo);
    cudaGetSymbolAddress((void**)&w_hi,   g_w_hi);
    cudaGetSymbolAddress((void**)&x1,     g_x1);
    cudaGetSymbolAddress((void**)&xs0,    g_xs0);
    cudaGetSymbolAddress((void**)&inl,    g_inl);
    cudaGetSymbolAddress((void**)&x2,     g_x2);
    cudaGetSymbolAddress((void**)&bcat,   g_bcat);

    cudaFuncSetAttribute(gemm_f16<0>,
        cudaFuncAttributeMaxDynamicSharedMemorySize, GEM_SMEM);
    cudaFuncSetAttribute(gemm_f16<1>,
        cudaFuncAttributeMaxDynamicSharedMemorySize, GEM_SMEM);
    cudaFuncSetAttribute(gemm_f16<2>,
        cudaFuncAttributeMaxDynamicSharedMemorySize, GEM_SMEM);
    cudaFuncSetAttribute(gemm_f16<3>,
        cudaFuncAttributeMaxDynamicSharedMemorySize, GEM_SMEM);
    cudaFuncSetAttribute(gemm_f16<4>,
        cudaFuncAttributeMaxDynamicSharedMemorySize, GEM_SMEM);
    cudaFuncSetAttribute(flash_attn_tc,
        cudaFuncAttributeMaxDynamicSharedMemorySize, FA_SMEM);

    // 0) weight plane conversion + bias concat
    conv_w_k<<<(int)(W_TOTAL / 512), 256>>>(
        attn_in_w, attn_out_w, inl_u_w, inl_a_w, inl_b_w, inl_g_w, ff1_w, ff2_w);
    bias_cat_k<<<16, 256>>>(inl_u_b, inl_a_b, inl_b_b, inl_g_b);

    // 1) pre-attn LN -> xn planes
    layernorm_p<<<ROWS, 256>>>(x, ln_attn_w, ln_attn_b, xn_hi, xn_lo);

    // 2) QKV projection -> qkv planes
    gemm_f16<4><<<dim3(3*DD/128, ROWS/128), 128, GEM_SMEM>>>(
        xn_hi, xn_lo, w_hi + WOFF_ATTNIN,
        attn_in_b, ROWS, 3*DD, DD, (float*)0, (const float*)0, (float*)0,
        qkv_hi, qkv_lo);

    // 3) tensor-core causal flash attention -> att planes
    flash_attn_tc<<<dim3(SS/64, HH, BB), 128, FA_SMEM>>>(
        qkv_hi, qkv_lo, att_hi, att_lo);

    // 4) out-projection: ctx planes = proj+bias, x1 = x + proj+bias
    gemm_f16<1><<<dim3(DD/128, ROWS/128), 128, GEM_SMEM>>>(
        att_hi, att_lo, w_hi + WOFF_ATTNOUT,
        attn_out_b, ROWS, DD, DD, (float*)0, x, x1, ctx_hi, ctx_lo);

    // 5) LN1(x1) -> xs0 fp32
    layernorm_f<<<ROWS, 256>>>(x1, ln1_w, ln1_b, xs0);

    // 6) fused INL controller projections: [ROWS, 4096] fp32
    gemm_f16<0><<<dim3(4*DD/128, ROWS/128), 128, GEM_SMEM>>>(
        ctx_hi, ctx_lo, w_hi + WOFF_INL,
        bcat, ROWS, 4*DD, DD, inl, (const float*)0, (float*)0,
        (__half*)0, (__half*)0);

    // 7) fused INL dynamics: x2 = x1 + xs(5 steps)
    inl_k<<<(ROWS*(size_t)DD)/256, 256>>>(xs0, inl, x1, x2);

    // 8) LN2(x2) -> h planes
    layernorm_p<<<ROWS, 256>>>(x2, ln2_w, ln2_b, h_hi, h_lo);

    // 9) FF1 + exact GELU -> ffh planes
    gemm_f16<2><<<dim3(FFD/128, ROWS/128), 128, GEM_SMEM>>>(
        h_hi, h_lo, w_hi + WOFF_FF1,
        ff1_b, ROWS, FFD, DD, (float*)0, (const float*)0, (float*)0,
        ffh_hi, ffh_lo);

    // 10) FF2 + bias + residual -> out
    gemm_f16<3><<<dim3(DD/128, ROWS/128), 128, GEM_SMEM>>>(
        ffh_hi, ffh_lo, w_hi + WOFF_FF2,
        ff2_b, ROWS, DD, FFD, out, x2, (float*)0,
        (__half*)0, (__half*)0);
}

// round 14
// speedup vs baseline: 7.6054x; 1.6352x over previous
#include <cuda_runtime.h>
#include <cuda_fp16.h>
#include <cstdint>
#include <math.h>

// Problem constants
#define BB   4
#define SS   2048
#define DD   1024
#define HH   16
#define DHD  64
#define FFD  4096
#define ROWS (BB*SS)

// ---------------- scratch (device globals; no allocation allowed) ----------
// fp16 planes. Only qkv needs a lo plane (attention Q error control).
__device__ __half g_xn_hi [(size_t)ROWS*DD];
__device__ __half g_qkv_hi[(size_t)ROWS*3*DD];
__device__ __half g_qkv_lo[(size_t)ROWS*3*DD];
__device__ __half g_att_hi[(size_t)ROWS*DD];
__device__ __half g_ctx_hi[(size_t)ROWS*DD];
__device__ __half g_h_hi  [(size_t)ROWS*DD];
__device__ __half g_ffh_hi[(size_t)ROWS*FFD];
// weight planes (hi only)
#define W_TOTAL ((size_t)16*1024*1024)
#define WOFF_ATTNIN  ((size_t)0)
#define WOFF_ATTNOUT ((size_t)3*1024*1024)
#define WOFF_INL     ((size_t)4*1024*1024)
#define WOFF_FF1     ((size_t)8*1024*1024)
#define WOFF_FF2     ((size_t)12*1024*1024)
__device__ __half g_w_hi[W_TOTAL];
__device__ float g_bcat[4*DD];
// fp32 intermediates
__device__ float g_x1 [(size_t)ROWS*DD];
__device__ float g_xs0[(size_t)ROWS*DD];
__device__ float g_inl[(size_t)ROWS*4*DD];
__device__ float g_x2 [(size_t)ROWS*DD];

// ---------------- helpers ---------------------------------------------------
__device__ __forceinline__ void wplane2(__half* hi, __half* lo,
                                        size_t idx, float v0, float v1)
{
    __half2 h = __floats2half2_rn(v0, v1);
    float2 hf = __half22float2(h);
    __half2 l = __floats2half2_rn(v0 - hf.x, v1 - hf.y);
    *reinterpret_cast<__half2*>(hi + idx) = h;
    *reinterpret_cast<__half2*>(lo + idx) = l;
}

__device__ __forceinline__ void whi2(__half* hi, size_t idx, float v0, float v1)
{
    __half2 h = __floats2half2_rn(v0, v1);
    *reinterpret_cast<__half2*>(hi + idx) = h;
}

__device__ __forceinline__ void hsplit2u(float x, float y,
                                         unsigned &h, unsigned &l)
{
    __half2 hb = __floats2half2_rn(x, y);
    float2 hf = __half22float2(hb);
    __half2 lb = __floats2half2_rn(x - hf.x, y - hf.y);
    h = *reinterpret_cast<unsigned*>(&hb);
    l = *reinterpret_cast<unsigned*>(&lb);
}

// ---------------- weight conversion (hi plane only) -------------------------
__global__ void __launch_bounds__(256) conv_w_k(
    const float* __restrict__ attn_in_w, const float* __restrict__ attn_out_w,
    const float* __restrict__ inl_u_w,   const float* __restrict__ inl_a_w,
    const float* __restrict__ inl_b_w,   const float* __restrict__ inl_g_w,
    const float* __restrict__ ff1_w,     const float* __restrict__ ff2_w)
{
    size_t e = ((size_t)blockIdx.x * 256 + threadIdx.x) * 2;
    const float* src;
    size_t off;
    if      (e < WOFF_ATTNOUT) { src = attn_in_w;  off = e - WOFF_ATTNIN; }
    else if (e < WOFF_INL)     { src = attn_out_w; off = e - WOFF_ATTNOUT; }
    else if (e < WOFF_INL + (size_t)1024*1024)   { src = inl_u_w; off = e - WOFF_INL; }
    else if (e < WOFF_INL + (size_t)2*1024*1024) { src = inl_a_w; off = e - WOFF_INL - (size_t)1024*1024; }
    else if (e < WOFF_INL + (size_t)3*1024*1024) { src = inl_b_w; off = e - WOFF_INL - (size_t)2*1024*1024; }
    else if (e < WOFF_FF1)     { src = inl_g_w; off = e - WOFF_INL - (size_t)3*1024*1024; }
    else if (e < WOFF_FF2)     { src = ff1_w;   off = e - WOFF_FF1; }
    else                       { src = ff2_w;   off = e - WOFF_FF2; }
    float2 v = *reinterpret_cast<const float2*>(src + off);
    __half2 h = __floats2half2_rn(v.x, v.y);
    *reinterpret_cast<__half2*>(g_w_hi + e) = h;
}

__global__ void bias_cat_k(const float* __restrict__ ub, const float* __restrict__ ab,
                           const float* __restrict__ bb, const float* __restrict__ gb)
{
    int i = blockIdx.x * 256 + threadIdx.x;
    int sel = i >> 10;
    int c = i & 1023;
    float v;
    if (sel == 0) v = ub[c];
    else if (sel == 1) v = ab[c];
    else if (sel == 2) v = bb[c];
    else v = gb[c];
    g_bcat[i] = v;
}

// ---------------- LayerNorm (fp32 out) --------------------------------------
__global__ void __launch_bounds__(256) layernorm_f(
    const float* __restrict__ x, const float* __restrict__ w,
    const float* __restrict__ b, float* __restrict__ y)
{
    int row = blockIdx.x;
    const float* xr = x + (size_t)row * DD;
    int tid = threadIdx.x;
    float4 v = *reinterpret_cast<const float4*>(xr + tid * 4);
    float s  = v.x + v.y + v.z + v.w;
    float ss = v.x*v.x + v.y*v.y + v.z*v.z + v.w*v.w;
    #pragma unroll
    for (int off = 16; off > 0; off >>= 1) {
        s  += __shfl_xor_sync(0xffffffffu, s,  off);
        ss += __shfl_xor_sync(0xffffffffu, ss, off);
    }
    __shared__ float sh_s[8];
    __shared__ float sh_ss[8];
    int wid = tid >> 5;
    int lane = tid & 31;
    if (lane == 0) { sh_s[wid] = s; sh_ss[wid] = ss; }
    __syncthreads();
    float ts = 0.f, tss = 0.f;
    #pragma unroll
    for (int i = 0; i < 8; i++) { ts += sh_s[i]; tss += sh_ss[i]; }
    float mu   = ts * (1.0f / DD);
    float var  = tss * (1.0f / DD) - mu * mu;
    float rstd = rsqrtf(var + 1e-5f);
    float4 wv = *reinterpret_cast<const float4*>(w + tid * 4);
    float4 bv = *reinterpret_cast<const float4*>(b + tid * 4);
    float4 o;
    o.x = (v.x - mu) * rstd * wv.x + bv.x;
    o.y = (v.y - mu) * rstd * wv.y + bv.y;
    o.z = (v.z - mu) * rstd * wv.z + bv.z;
    o.w = (v.w - mu) * rstd * wv.w + bv.w;
    *reinterpret_cast<float4*>(y + (size_t)row * DD + tid * 4) = o;
}

// ---------------- LayerNorm (fp16 hi plane out) ------------------------------
__global__ void __launch_bounds__(256) layernorm_h(
    const float* __restrict__ x, const float* __restrict__ w,
    const float* __restrict__ b, __half* __restrict__ yhi)
{
    int row = blockIdx.x;
    const float* xr = x + (size_t)row * DD;
    int tid = threadIdx.x;
    float4 v = *reinterpret_cast<const float4*>(xr + tid * 4);
    float s  = v.x + v.y + v.z + v.w;
    float ss = v.x*v.x + v.y*v.y + v.z*v.z + v.w*v.w;
    #pragma unroll
    for (int off = 16; off > 0; off >>= 1) {
        s  += __shfl_xor_sync(0xffffffffu, s,  off);
        ss += __shfl_xor_sync(0xffffffffu, ss, off);
    }
    __shared__ float sh_s[8];
    __shared__ float sh_ss[8];
    int wid = tid >> 5;
    int lane = tid & 31;
    if (lane == 0) { sh_s[wid] = s; sh_ss[wid] = ss; }
    __syncthreads();
    float ts = 0.f, tss = 0.f;
    #pragma unroll
    for (int i = 0; i < 8; i++) { ts += sh_s[i]; tss += sh_ss[i]; }
    float mu   = ts * (1.0f / DD);
    float var  = tss * (1.0f / DD) - mu * mu;
    float rstd = rsqrtf(var + 1e-5f);
    float4 wv = *reinterpret_cast<const float4*>(w + tid * 4);
    float4 bv = *reinterpret_cast<const float4*>(b + tid * 4);
    float o0 = (v.x - mu) * rstd * wv.x + bv.x;
    float o1 = (v.y - mu) * rstd * wv.y + bv.y;
    float o2 = (v.z - mu) * rstd * wv.z + bv.z;
    float o3 = (v.w - mu) * rstd * wv.w + bv.w;
    size_t base = (size_t)row * DD + tid * 4;
    whi2(yhi, base,     o0, o1);
    whi2(yhi, base + 2, o2, o3);
}

// ============================================================================
// asm wrappers
// ============================================================================
#define CP16(d, s) asm volatile("cp.async.cg.shared.global [%0], [%1], 16;\n" :: "r"(d), "l"(s))
#define CP_COMMIT() asm volatile("cp.async.commit_group;\n" ::)
#define CP_WAIT1() asm volatile("cp.async.wait_group 1;\n" ::)
#define CP_WAIT2() asm volatile("cp.async.wait_group 2;\n" ::)

__device__ __forceinline__ void ldsm4(unsigned &r0, unsigned &r1,
                                      unsigned &r2, unsigned &r3,
                                      unsigned addr)
{
    asm volatile(
        "ldmatrix.sync.aligned.m8n8.x4.shared.b16 {%0,%1,%2,%3}, [%4];\n"
        : "=r"(r0), "=r"(r1), "=r"(r2), "=r"(r3)
        : "r"(addr));
}

__device__ __forceinline__ void ldsm4t(unsigned &r0, unsigned &r1,
                                       unsigned &r2, unsigned &r3,
                                       unsigned addr)
{
    asm volatile(
        "ldmatrix.sync.aligned.m8n8.x4.trans.shared.b16 {%0,%1,%2,%3}, [%4];\n"
        : "=r"(r0), "=r"(r1), "=r"(r2), "=r"(r3)
        : "r"(addr));
}

__device__ __forceinline__ void mmaf16(float* c,
    unsigned a0, unsigned a1, unsigned a2, unsigned a3,
    unsigned b0, unsigned b1)
{
    asm volatile(
        "mma.sync.aligned.m16n8k16.row.col.f32.f16.f16.f32 "
        "{%0,%1,%2,%3}, {%4,%5,%6,%7}, {%8,%9}, {%0,%1,%2,%3};\n"
        : "+f"(c[0]), "+f"(c[1]), "+f"(c[2]), "+f"(c[3])
        : "r"(a0), "r"(a1), "r"(a2), "r"(a3), "r"(b0), "r"(b1));
}

// ============================================================================
// fp16 1-term tensor-core GEMM: C[M,N] = Ahi @ Bhi[N,K]^T, fp32 accum.
// Block tile 128x128x32, 128 threads (4 warps 2x2), warp tile 64x64.
// 4-stage cp.async (16KB/stage), single __syncthreads per k-tile
// (loads-before-compute into the slot freed last iteration).
// EPI: 0 fp32+bias; 1 hi(v+bias)+C2=res+v; 2 hi(GELU(v+bias));
//      3 fp32 v+bias+res; 4 hi+lo planes(v+bias).
// ============================================================================
#define STG_CHUNK 1024
#define GEM_STAGES 4
#define GEM_SMEM (GEM_STAGES * STG_CHUNK * 16)   // 65536

template<int EPI>
__global__ void __launch_bounds__(128, 2) gemm_f16(
    const __half* __restrict__ Ahi,
    const __half* __restrict__ Bhi,
    const float* __restrict__ bias, int M, int N, int K,
    float* __restrict__ C, const float* __restrict__ res, float* __restrict__ C2,
    __half* __restrict__ Chi, __half* __restrict__ Clo)
{
    extern __shared__ uint4 sm4[];
    const int tid  = threadIdx.x;
    const int lane = tid & 31;
    const int warp = tid >> 5;
    const int wm   = warp >> 1;
    const int wn   = warp & 1;
    const int bm   = blockIdx.y * 128;
    const int bn   = blockIdx.x * 128;

    const unsigned sbase =
        (unsigned)__cvta_generic_to_shared((void*)sm4);

    float acc[4][8][4];
    #pragma unroll
    for (int i = 0; i < 4; i++) {
        #pragma unroll
        for (int j = 0; j < 8; j++) {
            #pragma unroll
            for (int q = 0; q < 4; q++) acc[i][j][q] = 0.f;
        }
    }

    const int ar      = lane & 15;
    const int acolsel = lane >> 4;
    const int br      = (lane & 7) | ((lane >> 4) << 3);
    const int bcolsel = (lane >> 3) & 1;

    const int nk = K / 32;

    // stage loader: 1024 chunks / 128 threads = 8 each.
    // plane: 0 Ahi, 1 Bhi; each plane 128 rows x 4 chunks (64B rows)
    #define LOAD_STAGE(stg, kt_)                                                \
    {                                                                           \
        int k0 = (kt_) * 32;                                                    \
        _Pragma("unroll")                                                       \
        for (int it = 0; it < 8; it++) {                                        \
            int c   = tid + it * 128;                                           \
            int plane = c >> 9;                                                 \
            int rem = c & 511;                                                  \
            int row = rem >> 2;                                                 \
            int col = rem & 3;                                                  \
            int sw  = col ^ ((row >> 1) & 3);                                   \
            unsigned daddr = sbase +                                            \
                (unsigned)((((stg) * STG_CHUNK) + plane * 512 + row * 4 + sw) << 4); \
            const __half* gp;                                                   \
            size_t goff;                                                        \
            if (plane == 0) { gp = Ahi; goff = (size_t)(bm + row) * K + k0 + col * 8; } \
            else            { gp = Bhi; goff = (size_t)(bn + row) * K + k0 + col * 8; } \
            CP16(daddr, gp + goff);                                             \
        }                                                                       \
    }

    LOAD_STAGE(0, 0);
    CP_COMMIT();
    LOAD_STAGE(1, 1);
    CP_COMMIT();
    LOAD_STAGE(2, 2);
    CP_COMMIT();

    for (int kt = 0; kt < nk; kt++) {
        CP_WAIT2();
        __syncthreads();

        // prefetch tile kt+3 into slot (kt+3)&3 (freed in iteration kt-1)
        if (kt + 3 < nk) {
            LOAD_STAGE((kt + 3) & 3, kt + 3);
        }
        CP_COMMIT();

        const int stOff = (kt & 3) * STG_CHUNK;
        #pragma unroll
        for (int s = 0; s < 2; s++) {
            unsigned ahi[4][4];
            #pragma unroll
            for (int i = 0; i < 4; i++) {
                int row = wm * 64 + i * 16 + ar;
                int chunk = 2 * s + acolsel;
                int sw = chunk ^ ((row >> 1) & 3);
                unsigned ad = sbase +
                    (unsigned)((stOff + row * 4 + sw) << 4);
                ldsm4(ahi[i][0], ahi[i][1], ahi[i][2], ahi[i][3], ad);
            }
            #pragma unroll
            for (int p = 0; p < 4; p++) {
                int row = wn * 64 + p * 16 + br;
                int chunk = 2 * s + bcolsel;
                int sw = chunk ^ ((row >> 1) & 3);
                unsigned bd = sbase +
                    (unsigned)((stOff + 512 + row * 4 + sw) << 4);
                unsigned bh0, bh1, bh2, bh3;
                ldsm4(bh0, bh1, bh2, bh3, bd);
                #pragma unroll
                for (int i = 0; i < 4; i++) {
                    mmaf16(acc[i][2*p],
                           ahi[i][0], ahi[i][1], ahi[i][2], ahi[i][3], bh0, bh1);
                    mmaf16(acc[i][2*p+1],
                           ahi[i][0], ahi[i][1], ahi[i][2], ahi[i][3], bh2, bh3);
                }
            }
        }
    }
    #undef LOAD_STAGE

    const int rg = lane >> 2;
    const int q2 = (lane & 3) * 2;
    #pragma unroll
    for (int i = 0; i < 4; i++) {
        int r0 = bm + wm * 64 + i * 16 + rg;
        int r1 = r0 + 8;
        #pragma unroll
        for (int j = 0; j < 8; j++) {
            int col = bn + wn * 64 + j * 8 + q2;
            float b0 = bias[col];
            float b1 = bias[col + 1];
            float v0 = acc[i][j][0] + b0;
            float v1 = acc[i][j][1] + b1;
            float v2 = acc[i][j][2] + b0;
            float v3 = acc[i][j][3] + b1;
            size_t p0 = (size_t)r0 * N + col;
            size_t p1 = (size_t)r1 * N + col;
            if (EPI == 0) {
                C[p0] = v0; C[p0 + 1] = v1;
                C[p1] = v2; C[p1 + 1] = v3;
            }
            if (EPI == 1) {
                whi2(Chi, p0, v0, v1);
                whi2(Chi, p1, v2, v3);
                C2[p0]     = res[p0]     + v0;
                C2[p0 + 1] = res[p0 + 1] + v1;
                C2[p1]     = res[p1]     + v2;
                C2[p1 + 1] = res[p1 + 1] + v3;
            }
            if (EPI == 2) {
                v0 = 0.5f * v0 * (1.0f + erff(v0 * 0.70710678118654752f));
                v1 = 0.5f * v1 * (1.0f + erff(v1 * 0.70710678118654752f));
                v2 = 0.5f * v2 * (1.0f + erff(v2 * 0.70710678118654752f));
                v3 = 0.5f * v3 * (1.0f + erff(v3 * 0.70710678118654752f));
                whi2(Chi, p0, v0, v1);
                whi2(Chi, p1, v2, v3);
            }
            if (EPI == 3) {
                C[p0]     = v0 + res[p0];
                C[p0 + 1] = v1 + res[p0 + 1];
                C[p1]     = v2 + res[p1];
                C[p1 + 1] = v3 + res[p1 + 1];
            }
            if (EPI == 4) {
                wplane2(Chi, Clo, p0, v0, v1);
                wplane2(Chi, Clo, p1, v2, v3);
            }
        }
    }
}

// ============================================================================
// Tensor-core causal flash attention, fp16 2-term (Q,P split; K,V hi-only).
// Block: 64 queries x (head, batch); 128 threads = 4 warps, warp owns m16.
// smem chunks: Qhi[512] Qlo[512] | 2 stages x {Khi[512], Vhi[512]}
// ============================================================================
#define FA_SMEM (3072 * 16)   // 48 KB

__global__ void __launch_bounds__(128) flash_attn_tc(
    const __half* __restrict__ qhi, const __half* __restrict__ qlo,
    __half* __restrict__ outhi)
{
    extern __shared__ uint4 sm4[];
    const int tid  = threadIdx.x;
    const int lane = tid & 31;
    const int warp = tid >> 5;
    const int qt = blockIdx.x;
    const int h  = blockIdx.y;
    const int b  = blockIdx.z;
    const unsigned smem_base =
        (unsigned)__cvta_generic_to_shared((void*)sm4);

    const size_t rstr = 3 * DD;
    const size_t qrow0  = (size_t)b * SS + (size_t)qt * 64;
    const size_t kvrow0 = (size_t)b * SS;

    // ---- Q tile load (hi+lo) ----
    #pragma unroll
    for (int it = 0; it < 8; it++) {
        int c = tid + it * 128;
        int plane = c >> 9;
        int rem = c & 511;
        int row = rem >> 3;
        int ch  = rem & 7;
        int sw  = ch ^ (row & 7);
        unsigned d = smem_base + (unsigned)((plane * 512 + row * 8 + sw) << 4);
        const __half* src = (plane ? qlo : qhi);
        CP16(d, src + (qrow0 + row) * rstr + h * 64 + ch * 8);
    }
    CP_COMMIT();

    const int nkt = qt + 1;

    #define LOAD_KV(stg_, kt_)                                                  \
    {                                                                           \
        size_t krow = kvrow0 + (size_t)(kt_) * 64;                              \
        _Pragma("unroll")                                                       \
        for (int it = 0; it < 8; it++) {                                        \
            int c = tid + it * 128;                                             \
            int plane = c >> 9;   /* 0 Khi, 1 Vhi */                            \
            int rem = c & 511;                                                  \
            int row = rem >> 3;                                                 \
            int ch  = rem & 7;                                                  \
            int sw  = ch ^ (row & 7);                                           \
            unsigned d = smem_base +                                            \
                (unsigned)((1024 + (stg_) * 1024 + plane * 512 + row * 8 + sw) << 4); \
            size_t off = (krow + row) * rstr +                                  \
                         (plane ? 2 * DD : DD) + h * 64 + ch * 8;               \
            CP16(d, qhi + off);                                                 \
        }                                                                       \
    }

    LOAD_KV(0, 0);
    CP_COMMIT();
    if (nkt > 1) { LOAD_KV(1, 1); }
    CP_COMMIT();

    const int g = lane >> 2;
    const int q = lane & 3;

    float m0 = -INFINITY, m1 = -INFINITY;
    float l0 = 0.f, l1 = 0.f;
    float ov[8][4];
    #pragma unroll
    for (int j = 0; j < 8; j++) {
        #pragma unroll
        for (int k = 0; k < 4; k++) ov[j][k] = 0.f;
    }

    for (int kt = 0; kt < nkt; kt++) {
        CP_WAIT1();
        __syncthreads();
        const unsigned stg = smem_base +
            (unsigned)((1024 + (kt & 1) * 1024) << 4);

        float ss[8][4];
        #pragma unroll
        for (int j = 0; j < 8; j++) {
            #pragma unroll
            for (int k = 0; k < 4; k++) ss[j][k] = 0.f;
        }

        #pragma unroll
        for (int t = 0; t < 4; t++) {
            int arow = warp * 16 + (lane & 15);
            int ach  = 2 * t + (lane >> 4);
            int asw  = ach ^ (arow & 7);
            unsigned aaddr = smem_base + (unsigned)((arow * 8 + asw) << 4);
            unsigned qh0, qh1, qh2, qh3, ql0, ql1, ql2, ql3;
            ldsm4(qh0, qh1, qh2, qh3, aaddr);
            ldsm4(ql0, ql1, ql2, ql3, aaddr + (unsigned)(512 << 4));

            #pragma unroll
            for (int pb = 0; pb < 4; pb++) {
                int brow = pb * 16 + ((lane & 7) | ((lane >> 4) << 3));
                int bch  = 2 * t + ((lane >> 3) & 1);
                int bsw  = bch ^ (brow & 7);
                unsigned baddr = stg + (unsigned)((brow * 8 + bsw) << 4);
                unsigned kh0, kh1, kh2, kh3;
                ldsm4(kh0, kh1, kh2, kh3, baddr);
                mmaf16(ss[2*pb],   qh0, qh1, qh2, qh3, kh0, kh1);
                mmaf16(ss[2*pb],   ql0, ql1, ql2, ql3, kh0, kh1);
                mmaf16(ss[2*pb+1], qh0, qh1, qh2, qh3, kh2, kh3);
                mmaf16(ss[2*pb+1], ql0, ql1, ql2, ql3, kh2, kh3);
            }
        }

        #pragma unroll
        for (int j = 0; j < 8; j++) {
            ss[j][0] *= 0.125f; ss[j][1] *= 0.125f;
            ss[j][2] *= 0.125f; ss[j][3] *= 0.125f;
        }
        if (kt == qt) {
            int qr0 = warp * 16 + g;
            int qr1 = qr0 + 8;
            #pragma unroll
            for (int j = 0; j < 8; j++) {
                int k0 = 8 * j + 2 * q;
                int k1 = k0 + 1;
                if (k0 > qr0) ss[j][0] = -1e30f;
                if (k1 > qr0) ss[j][1] = -1e30f;
                if (k0 > qr1) ss[j][2] = -1e30f;
                if (k1 > qr1) ss[j][3] = -1e30f;
            }
        }

        float rm0 = -1e30f, rm1 = -1e30f;
        #pragma unroll
        for (int j = 0; j < 8; j++) {
            rm0 = fmaxf(rm0, fmaxf(ss[j][0], ss[j][1]));
            rm1 = fmaxf(rm1, fmaxf(ss[j][2], ss[j][3]));
        }
        rm0 = fmaxf(rm0, __shfl_xor_sync(0xffffffffu, rm0, 1));
        rm0 = fmaxf(rm0, __shfl_xor_sync(0xffffffffu, rm0, 2));
        rm1 = fmaxf(rm1, __shfl_xor_sync(0xffffffffu, rm1, 1));
        rm1 = fmaxf(rm1, __shfl_xor_sync(0xffffffffu, rm1, 2));
        float mn0 = fmaxf(m0, rm0);
        float mn1 = fmaxf(m1, rm1);
        float corr0 = __expf(m0 - mn0);
        float corr1 = __expf(m1 - mn1);
        m0 = mn0; m1 = mn1;

        float ps0 = 0.f, ps1 = 0.f;
        #pragma unroll
        for (int j = 0; j < 8; j++) {
            ss[j][0] = __expf(ss[j][0] - mn0);
            ss[j][1] = __expf(ss[j][1] - mn0);
            ss[j][2] = __expf(ss[j][2] - mn1);
            ss[j][3] = __expf(ss[j][3] - mn1);
            ps0 += ss[j][0] + ss[j][1];
            ps1 += ss[j][2] + ss[j][3];
        }
        ps0 += __shfl_xor_sync(0xffffffffu, ps0, 1);
        ps0 += __shfl_xor_sync(0xffffffffu, ps0, 2);
        ps1 += __shfl_xor_sync(0xffffffffu, ps1, 1);
        ps1 += __shfl_xor_sync(0xffffffffu, ps1, 2);
        l0 = l0 * corr0 + ps0;
        l1 = l1 * corr1 + ps1;
        #pragma unroll
        for (int j = 0; j < 8; j++) {
            ov[j][0] *= corr0; ov[j][1] *= corr0;
            ov[j][2] *= corr1; ov[j][3] *= corr1;
        }

        #pragma unroll
        for (int t = 0; t < 4; t++) {
            unsigned ph0, ph1, ph2, ph3, pl0, pl1, pl2, pl3;
            hsplit2u(ss[2*t][0],   ss[2*t][1],   ph0, pl0);
            hsplit2u(ss[2*t][2],   ss[2*t][3],   ph1, pl1);
            hsplit2u(ss[2*t+1][0], ss[2*t+1][1], ph2, pl2);
            hsplit2u(ss[2*t+1][2], ss[2*t+1][3], ph3, pl3);

            #pragma unroll
            for (int jd2 = 0; jd2 < 4; jd2++) {
                int vrow = 16 * t + (lane & 7) + ((lane >> 3) & 1) * 8;
                int vch  = jd2 * 2 + (lane >> 4);
                int vsw  = vch ^ (vrow & 7);
                unsigned vaddr = stg + (unsigned)((512 + vrow * 8 + vsw) << 4);
                unsigned vh0, vh1, vh2, vh3;
                ldsm4t(vh0, vh1, vh2, vh3, vaddr);
                mmaf16(ov[2*jd2],   ph0, ph1, ph2, ph3, vh0, vh1);
                mmaf16(ov[2*jd2],   pl0, pl1, pl2, pl3, vh0, vh1);
                mmaf16(ov[2*jd2+1], ph0, ph1, ph2, ph3, vh2, vh3);
                mmaf16(ov[2*jd2+1], pl0, pl1, pl2, pl3, vh2, vh3);
            }
        }

        __syncthreads();
        if (kt + 2 < nkt) { LOAD_KV(kt & 1, kt + 2); }
        CP_COMMIT();
    }
    #undef LOAD_KV

    float invl0 = 1.0f / l0;
    float invl1 = 1.0f / l1;
    #pragma unroll
    for (int jd = 0; jd < 8; jd++) {
        size_t p0 = (qrow0 + warp * 16 + g) * DD + h * 64 + 8 * jd + 2 * q;
        size_t p1 = p0 + (size_t)8 * DD;
        whi2(outhi, p0, ov[jd][0] * invl0, ov[jd][1] * invl0);
        whi2(outhi, p1, ov[jd][2] * invl1, ov[jd][3] * invl1);
    }
}

// ---------------- INL integrator: fused elementwise -------------------------
__global__ void __launch_bounds__(256) inl_k(
    const float* __restrict__ xs0, const float* __restrict__ inl,
    const float* __restrict__ x1,  float* __restrict__ x2)
{
    size_t i = (size_t)blockIdx.x * blockDim.x + threadIdx.x;
    size_t row = i >> 10;
    size_t col = i & 1023;
    size_t base = row * (size_t)(4*DD) + col;
    float xs = xs0[i];
    float u  = inl[base];
    float av = inl[base + DD];
    float bv = inl[base + 2*DD];
    float gv = inl[base + 3*DD];
    float alpha = 1.0f / (1.0f + expf(-av));
    float beta  = (bv > 20.0f) ? bv : log1pf(expf(bv));
    float g     = 1.0f / (1.0f + expf(-gv));
    float vs = 0.0f;
    #pragma unroll
    for (int t = 0; t < 5; t++) {
        vs += 0.1f * (alpha * (0.0f - xs) - beta * vs + u);
        xs += 0.1f * g * vs;
    }
    x2[i] = x1[i] + xs;
}

// ---------------- launch ----------------------------------------------------
extern "C" void kernel_launch(void* const* d_in, const int* in_sizes, int n_in,
                              void* d_out, int out_size)
{
    const float* x          = (const float*)d_in[0];
    const float* ln_attn_w  = (const float*)d_in[1];
    const float* ln_attn_b  = (const float*)d_in[2];
    const float* attn_in_w  = (const float*)d_in[3];
    const float* attn_in_b  = (const float*)d_in[4];
    const float* attn_out_w = (const float*)d_in[5];
    const float* attn_out_b = (const float*)d_in[6];
    const float* ln1_w      = (const float*)d_in[7];
    const float* ln1_b      = (const float*)d_in[8];
    const float* ln2_w      = (const float*)d_in[9];
    const float* ln2_b      = (const float*)d_in[10];
    const float* inl_u_w    = (const float*)d_in[11];
    const float* inl_u_b    = (const float*)d_in[12];
    const float* inl_a_w    = (const float*)d_in[13];
    const float* inl_a_b    = (const float*)d_in[14];
    const float* inl_b_w    = (const float*)d_in[15];
    const float* inl_b_b    = (const float*)d_in[16];
    const float* inl_g_w    = (const float*)d_in[17];
    const float* inl_g_b    = (const float*)d_in[18];
    const float* ff1_w      = (const float*)d_in[19];
    const float* ff1_b      = (const float*)d_in[20];
    const float* ff2_w      = (const float*)d_in[21];
    const float* ff2_b      = (const float*)d_in[22];
    float* out = (float*)d_out;

    __half *xn_hi = 0, *qkv_hi = 0, *qkv_lo = 0, *att_hi = 0;
    __half *ctx_hi = 0, *h_hi = 0, *ffh_hi = 0, *w_hi = 0;
    float *x1 = 0, *xs0 = 0, *inl = 0, *x2 = 0, *bcat = 0;
    cudaGetSymbolAddress((void**)&xn_hi,  g_xn_hi);
    cudaGetSymbolAddress((void**)&qkv_hi, g_qkv_hi);
    cudaGetSymbolAddress((void**)&qkv_lo, g_qkv_lo);
    cudaGetSymbolAddress((void**)&att_hi, g_att_hi);
    cudaGetSymbolAddress((void**)&ctx_hi, g_ctx_hi);
    cudaGetSymbolAddress((void**)&h_hi,   g_h_hi);
    cudaGetSymbolAddress((void**)&ffh_hi, g_ffh_hi);
    cudaGetSymbolAddress((void**)&w_hi,   g_w_hi);
    cudaGetSymbolAddress((void**)&x1,     g_x1);
    cudaGetSymbolAddress((void**)&xs0,    g_xs0);
    cudaGetSymbolAddress((void**)&inl,    g_inl);
    cudaGetSymbolAddress((void**)&x2,     g_x2);
    cudaGetSymbolAddress((void**)&bcat,   g_bcat);

    cudaFuncSetAttribute(gemm_f16<0>,
        cudaFuncAttributeMaxDynamicSharedMemorySize, GEM_SMEM);
    cudaFuncSetAttribute(gemm_f16<1>,
        cudaFuncAttributeMaxDynamicSharedMemorySize, GEM_SMEM);
    cudaFuncSetAttribute(gemm_f16<2>,
        cudaFuncAttributeMaxDynamicSharedMemorySize, GEM_SMEM);
    cudaFuncSetAttribute(gemm_f16<3>,
        cudaFuncAttributeMaxDynamicSharedMemorySize, GEM_SMEM);
    cudaFuncSetAttribute(gemm_f16<4>,
        cudaFuncAttributeMaxDynamicSharedMemorySize, GEM_SMEM);
    cudaFuncSetAttribute(flash_attn_tc,
        cudaFuncAttributeMaxDynamicSharedMemorySize, FA_SMEM);

    // 0) weight plane conversion + bias concat
    conv_w_k<<<(int)(W_TOTAL / 512), 256>>>(
        attn_in_w, attn_out_w, inl_u_w, inl_a_w, inl_b_w, inl_g_w, ff1_w, ff2_w);
    bias_cat_k<<<16, 256>>>(inl_u_b, inl_a_b, inl_b_b, inl_g_b);

    // 1) pre-attn LN -> xn hi plane
    layernorm_h<<<ROWS, 256>>>(x, ln_attn_w, ln_attn_b, xn_hi);

    // 2) QKV projection -> qkv hi+lo planes
    gemm_f16<4><<<dim3(3*DD/128, ROWS/128), 128, GEM_SMEM>>>(
        xn_hi, w_hi + WOFF_ATTNIN,
        attn_in_b, ROWS, 3*DD, DD, (float*)0, (const float*)0, (float*)0,
        qkv_hi, qkv_lo);

    // 3) tensor-core causal flash attention -> att hi plane
    flash_attn_tc<<<dim3(SS/64, HH, BB), 128, FA_SMEM>>>(
        qkv_hi, qkv_lo, att_hi);

    // 4) out-projection: ctx hi = proj+bias, x1 = x + proj+bias
    gemm_f16<1><<<dim3(DD/128, ROWS/128), 128, GEM_SMEM>>>(
        att_hi, w_hi + WOFF_ATTNOUT,
        attn_out_b, ROWS, DD, DD, (float*)0, x, x1, ctx_hi, (__half*)0);

    // 5) LN1(x1) -> xs0 fp32
    layernorm_f<<<ROWS, 256>>>(x1, ln1_w, ln1_b, xs0);

    // 6) fused INL controller projections: [ROWS, 4096] fp32
    gemm_f16<0><<<dim3(4*DD/128, ROWS/128), 128, GEM_SMEM>>>(
        ctx_hi, w_hi + WOFF_INL,
        bcat, ROWS, 4*DD, DD, inl, (const float*)0, (float*)0,
        (__half*)0, (__half*)0);

    // 7) fused INL dynamics: x2 = x1 + xs(5 steps)
    inl_k<<<(ROWS*(size_t)DD)/256, 256>>>(xs0, inl, x1, x2);

    // 8) LN2(x2) -> h hi plane
    layernorm_h<<<ROWS, 256>>>(x2, ln2_w, ln2_b, h_hi);

    // 9) FF1 + exact GELU -> ffh hi plane
    gemm_f16<2><<<dim3(FFD/128, ROWS/128), 128, GEM_SMEM>>>(
        h_hi, w_hi + WOFF_FF1,
        ff1_b, ROWS, FFD, DD, (float*)0, (const float*)0, (float*)0,
        ffh_hi, (__half*)0);

    // 10) FF2 + bias + residual -> out
    gemm_f16<3><<<dim3(DD/128, ROWS/128), 128, GEM_SMEM>>>(
        ffh_hi, w_hi + WOFF_FF2,
        ff2_b, ROWS, DD, FFD, out, x2, (float*)0,
        (__half*)0, (__half*)0);
}

// round 15
// speedup vs baseline: 7.9869x; 1.0502x over previous
#include <cuda_runtime.h>
#include <cuda_fp16.h>
#include <cstdint>
#include <math.h>

// Problem constants
#define BB   4
#define SS   2048
#define DD   1024
#define HH   16
#define DHD  64
#define FFD  4096
#define ROWS (BB*SS)

// ---------------- scratch (device globals; no allocation allowed) ----------
__device__ __half g_xn_hi [(size_t)ROWS*DD];
__device__ __half g_qkv_hi[(size_t)ROWS*3*DD];
__device__ __half g_qkv_lo[(size_t)ROWS*3*DD];
__device__ __half g_att_hi[(size_t)ROWS*DD];
__device__ __half g_ctx_hi[(size_t)ROWS*DD];
__device__ __half g_h_hi  [(size_t)ROWS*DD];
__device__ __half g_ffh_hi[(size_t)ROWS*FFD];
// weight planes (hi only)
#define W_TOTAL ((size_t)16*1024*1024)
#define WOFF_ATTNIN  ((size_t)0)
#define WOFF_ATTNOUT ((size_t)3*1024*1024)
#define WOFF_INL     ((size_t)4*1024*1024)
#define WOFF_FF1     ((size_t)8*1024*1024)
#define WOFF_FF2     ((size_t)12*1024*1024)
__device__ __half g_w_hi[W_TOTAL];
__device__ float g_bcat[4*DD];
// fp32 intermediates
__device__ float g_x1 [(size_t)ROWS*DD];
__device__ float g_xs0[(size_t)ROWS*DD];
__device__ float g_inl[(size_t)ROWS*4*DD];
__device__ float g_x2 [(size_t)ROWS*DD];

// ---------------- helpers ---------------------------------------------------
__device__ __forceinline__ void wplane2(__half* hi, __half* lo,
                                        size_t idx, float v0, float v1)
{
    __half2 h = __floats2half2_rn(v0, v1);
    float2 hf = __half22float2(h);
    __half2 l = __floats2half2_rn(v0 - hf.x, v1 - hf.y);
    *reinterpret_cast<__half2*>(hi + idx) = h;
    *reinterpret_cast<__half2*>(lo + idx) = l;
}

__device__ __forceinline__ void whi2(__half* hi, size_t idx, float v0, float v1)
{
    __half2 h = __floats2half2_rn(v0, v1);
    *reinterpret_cast<__half2*>(hi + idx) = h;
}

__device__ __forceinline__ void hsplit2u(float x, float y,
                                         unsigned &h, unsigned &l)
{
    __half2 hb = __floats2half2_rn(x, y);
    float2 hf = __half22float2(hb);
    __half2 lb = __floats2half2_rn(x - hf.x, y - hf.y);
    h = *reinterpret_cast<unsigned*>(&hb);
    l = *reinterpret_cast<unsigned*>(&lb);
}

// ---------------- weight conversion (hi plane only) -------------------------
__global__ void __launch_bounds__(256) conv_w_k(
    const float* __restrict__ attn_in_w, const float* __restrict__ attn_out_w,
    const float* __restrict__ inl_u_w,   const float* __restrict__ inl_a_w,
    const float* __restrict__ inl_b_w,   const float* __restrict__ inl_g_w,
    const float* __restrict__ ff1_w,     const float* __restrict__ ff2_w)
{
    size_t e = ((size_t)blockIdx.x * 256 + threadIdx.x) * 2;
    const float* src;
    size_t off;
    if      (e < WOFF_ATTNOUT) { src = attn_in_w;  off = e - WOFF_ATTNIN; }
    else if (e < WOFF_INL)     { src = attn_out_w; off = e - WOFF_ATTNOUT; }
    else if (e < WOFF_INL + (size_t)1024*1024)   { src = inl_u_w; off = e - WOFF_INL; }
    else if (e < WOFF_INL + (size_t)2*1024*1024) { src = inl_a_w; off = e - WOFF_INL - (size_t)1024*1024; }
    else if (e < WOFF_INL + (size_t)3*1024*1024) { src = inl_b_w; off = e - WOFF_INL - (size_t)2*1024*1024; }
    else if (e < WOFF_FF1)     { src = inl_g_w; off = e - WOFF_INL - (size_t)3*1024*1024; }
    else if (e < WOFF_FF2)     { src = ff1_w;   off = e - WOFF_FF1; }
    else                       { src = ff2_w;   off = e - WOFF_FF2; }
    float2 v = *reinterpret_cast<const float2*>(src + off);
    __half2 h = __floats2half2_rn(v.x, v.y);
    *reinterpret_cast<__half2*>(g_w_hi + e) = h;
}

__global__ void bias_cat_k(const float* __restrict__ ub, const float* __restrict__ ab,
                           const float* __restrict__ bb, const float* __restrict__ gb)
{
    int i = blockIdx.x * 256 + threadIdx.x;
    int sel = i >> 10;
    int c = i & 1023;
    float v;
    if (sel == 0) v = ub[c];
    else if (sel == 1) v = ab[c];
    else if (sel == 2) v = bb[c];
    else v = gb[c];
    g_bcat[i] = v;
}

// ---------------- LayerNorm (fp32 out) --------------------------------------
__global__ void __launch_bounds__(256) layernorm_f(
    const float* __restrict__ x, const float* __restrict__ w,
    const float* __restrict__ b, float* __restrict__ y)
{
    int row = blockIdx.x;
    const float* xr = x + (size_t)row * DD;
    int tid = threadIdx.x;
    float4 v = *reinterpret_cast<const float4*>(xr + tid * 4);
    float s  = v.x + v.y + v.z + v.w;
    float ss = v.x*v.x + v.y*v.y + v.z*v.z + v.w*v.w;
    #pragma unroll
    for (int off = 16; off > 0; off >>= 1) {
        s  += __shfl_xor_sync(0xffffffffu, s,  off);
        ss += __shfl_xor_sync(0xffffffffu, ss, off);
    }
    __shared__ float sh_s[8];
    __shared__ float sh_ss[8];
    int wid = tid >> 5;
    int lane = tid & 31;
    if (lane == 0) { sh_s[wid] = s; sh_ss[wid] = ss; }
    __syncthreads();
    float ts = 0.f, tss = 0.f;
    #pragma unroll
    for (int i = 0; i < 8; i++) { ts += sh_s[i]; tss += sh_ss[i]; }
    float mu   = ts * (1.0f / DD);
    float var  = tss * (1.0f / DD) - mu * mu;
    float rstd = rsqrtf(var + 1e-5f);
    float4 wv = *reinterpret_cast<const float4*>(w + tid * 4);
    float4 bv = *reinterpret_cast<const float4*>(b + tid * 4);
    float4 o;
    o.x = (v.x - mu) * rstd * wv.x + bv.x;
    o.y = (v.y - mu) * rstd * wv.y + bv.y;
    o.z = (v.z - mu) * rstd * wv.z + bv.z;
    o.w = (v.w - mu) * rstd * wv.w + bv.w;
    *reinterpret_cast<float4*>(y + (size_t)row * DD + tid * 4) = o;
}

// ---------------- LayerNorm (fp16 hi plane out) ------------------------------
__global__ void __launch_bounds__(256) layernorm_h(
    const float* __restrict__ x, const float* __restrict__ w,
    const float* __restrict__ b, __half* __restrict__ yhi)
{
    int row = blockIdx.x;
    const float* xr = x + (size_t)row * DD;
    int tid = threadIdx.x;
    float4 v = *reinterpret_cast<const float4*>(xr + tid * 4);
    float s  = v.x + v.y + v.z + v.w;
    float ss = v.x*v.x + v.y*v.y + v.z*v.z + v.w*v.w;
    #pragma unroll
    for (int off = 16; off > 0; off >>= 1) {
        s  += __shfl_xor_sync(0xffffffffu, s,  off);
        ss += __shfl_xor_sync(0xffffffffu, ss, off);
    }
    __shared__ float sh_s[8];
    __shared__ float sh_ss[8];
    int wid = tid >> 5;
    int lane = tid & 31;
    if (lane == 0) { sh_s[wid] = s; sh_ss[wid] = ss; }
    __syncthreads();
    float ts = 0.f, tss = 0.f;
    #pragma unroll
    for (int i = 0; i < 8; i++) { ts += sh_s[i]; tss += sh_ss[i]; }
    float mu   = ts * (1.0f / DD);
    float var  = tss * (1.0f / DD) - mu * mu;
    float rstd = rsqrtf(var + 1e-5f);
    float4 wv = *reinterpret_cast<const float4*>(w + tid * 4);
    float4 bv = *reinterpret_cast<const float4*>(b + tid * 4);
    float o0 = (v.x - mu) * rstd * wv.x + bv.x;
    float o1 = (v.y - mu) * rstd * wv.y + bv.y;
    float o2 = (v.z - mu) * rstd * wv.z + bv.z;
    float o3 = (v.w - mu) * rstd * wv.w + bv.w;
    size_t base = (size_t)row * DD + tid * 4;
    whi2(yhi, base,     o0, o1);
    whi2(yhi, base + 2, o2, o3);
}

// ---------------- Fused INL integrator + LN2 (one block per row) ------------
__global__ void __launch_bounds__(256) inl_ln_k(
    const float* __restrict__ xs0, const float* __restrict__ inl,
    const float* __restrict__ x1,
    const float* __restrict__ w,  const float* __restrict__ b,
    float* __restrict__ x2, __half* __restrict__ h_hi)
{
    int row = blockIdx.x;
    int tid = threadIdx.x;
    size_t rbase = (size_t)row * DD + tid * 4;
    size_t ibase = (size_t)row * (size_t)(4*DD) + tid * 4;

    float4 xsv = *reinterpret_cast<const float4*>(xs0 + rbase);
    float4 uv  = *reinterpret_cast<const float4*>(inl + ibase);
    float4 av  = *reinterpret_cast<const float4*>(inl + ibase + DD);
    float4 bv4 = *reinterpret_cast<const float4*>(inl + ibase + 2*DD);
    float4 gv  = *reinterpret_cast<const float4*>(inl + ibase + 3*DD);
    float4 x1v = *reinterpret_cast<const float4*>(x1 + rbase);

    float xs[4] = {xsv.x, xsv.y, xsv.z, xsv.w};
    float uu[4] = {uv.x, uv.y, uv.z, uv.w};
    float aa[4] = {av.x, av.y, av.z, av.w};
    float bb[4] = {bv4.x, bv4.y, bv4.z, bv4.w};
    float gg[4] = {gv.x, gv.y, gv.z, gv.w};
    float x1a[4] = {x1v.x, x1v.y, x1v.z, x1v.w};
    float out[4];

    #pragma unroll
    for (int e = 0; e < 4; e++) {
        float alpha = 1.0f / (1.0f + expf(-aa[e]));
        float beta  = (bb[e] > 20.0f) ? bb[e] : log1pf(expf(bb[e]));
        float g     = 1.0f / (1.0f + expf(-gg[e]));
        float xv = xs[e];
        float vs = 0.0f;
        #pragma unroll
        for (int t = 0; t < 5; t++) {
            vs += 0.1f * (alpha * (0.0f - xv) - beta * vs + uu[e]);
            xv += 0.1f * g * vs;
        }
        out[e] = x1a[e] + xv;
    }
    *reinterpret_cast<float4*>(x2 + rbase) =
        make_float4(out[0], out[1], out[2], out[3]);

    // ---- LN over the row ----
    float s  = out[0] + out[1] + out[2] + out[3];
    float ss = out[0]*out[0] + out[1]*out[1] + out[2]*out[2] + out[3]*out[3];
    #pragma unroll
    for (int off = 16; off > 0; off >>= 1) {
        s  += __shfl_xor_sync(0xffffffffu, s,  off);
        ss += __shfl_xor_sync(0xffffffffu, ss, off);
    }
    __shared__ float sh_s[8];
    __shared__ float sh_ss[8];
    int wid = tid >> 5;
    int lane = tid & 31;
    if (lane == 0) { sh_s[wid] = s; sh_ss[wid] = ss; }
    __syncthreads();
    float ts = 0.f, tss = 0.f;
    #pragma unroll
    for (int i = 0; i < 8; i++) { ts += sh_s[i]; tss += sh_ss[i]; }
    float mu   = ts * (1.0f / DD);
    float var  = tss * (1.0f / DD) - mu * mu;
    float rstd = rsqrtf(var + 1e-5f);
    float4 wv = *reinterpret_cast<const float4*>(w + tid * 4);
    float4 bv = *reinterpret_cast<const float4*>(b + tid * 4);
    float o0 = (out[0] - mu) * rstd * wv.x + bv.x;
    float o1 = (out[1] - mu) * rstd * wv.y + bv.y;
    float o2 = (out[2] - mu) * rstd * wv.z + bv.z;
    float o3 = (out[3] - mu) * rstd * wv.w + bv.w;
    whi2(h_hi, rbase,     o0, o1);
    whi2(h_hi, rbase + 2, o2, o3);
}

// ============================================================================
// asm wrappers
// ============================================================================
#define CP16(d, s) asm volatile("cp.async.cg.shared.global [%0], [%1], 16;\n" :: "r"(d), "l"(s))
#define CP_COMMIT() asm volatile("cp.async.commit_group;\n" ::)
#define CP_WAIT1() asm volatile("cp.async.wait_group 1;\n" ::)
#define CP_WAIT2() asm volatile("cp.async.wait_group 2;\n" ::)

__device__ __forceinline__ void ldsm4(unsigned &r0, unsigned &r1,
                                      unsigned &r2, unsigned &r3,
                                      unsigned addr)
{
    asm volatile(
        "ldmatrix.sync.aligned.m8n8.x4.shared.b16 {%0,%1,%2,%3}, [%4];\n"
        : "=r"(r0), "=r"(r1), "=r"(r2), "=r"(r3)
        : "r"(addr));
}

__device__ __forceinline__ void ldsm4t(unsigned &r0, unsigned &r1,
                                       unsigned &r2, unsigned &r3,
                                       unsigned addr)
{
    asm volatile(
        "ldmatrix.sync.aligned.m8n8.x4.trans.shared.b16 {%0,%1,%2,%3}, [%4];\n"
        : "=r"(r0), "=r"(r1), "=r"(r2), "=r"(r3)
        : "r"(addr));
}

__device__ __forceinline__ void mmaf16(float* c,
    unsigned a0, unsigned a1, unsigned a2, unsigned a3,
    unsigned b0, unsigned b1)
{
    asm volatile(
        "mma.sync.aligned.m16n8k16.row.col.f32.f16.f16.f32 "
        "{%0,%1,%2,%3}, {%4,%5,%6,%7}, {%8,%9}, {%0,%1,%2,%3};\n"
        : "+f"(c[0]), "+f"(c[1]), "+f"(c[2]), "+f"(c[3])
        : "r"(a0), "r"(a1), "r"(a2), "r"(a3), "r"(b0), "r"(b1));
}

// ============================================================================
// fp16 tensor-core GEMM: C[M,N] = Ahi @ Bhi[N,K]^T, fp32 accum.
// Block tile 128x128x32, 128 threads (4 warps 2x2), warp tile 64x64.
// 4-stage cp.async (16KB/stage), single __syncthreads per k-tile.
// Fragment software pipeline: all 8 A ldsm up front; B through a 2-deep
// register double buffer. Per-stage ldsm offsets precomputed.
// EPI: 0 fp32+bias; 1 hi(v+bias)+C2=res+v; 2 hi(GELU(v+bias));
//      3 fp32 v+bias+res; 4 hi+lo planes(v+bias).
// ============================================================================
#define STG_CHUNK 1024
#define GEM_STAGES 4
#define GEM_SMEM (GEM_STAGES * STG_CHUNK * 16)   // 65536

template<int EPI>
__global__ void __launch_bounds__(128, 2) gemm_f16(
    const __half* __restrict__ Ahi,
    const __half* __restrict__ Bhi,
    const float* __restrict__ bias, int M, int N, int K,
    float* __restrict__ C, const float* __restrict__ res, float* __restrict__ C2,
    __half* __restrict__ Chi, __half* __restrict__ Clo)
{
    extern __shared__ uint4 sm4[];
    const int tid  = threadIdx.x;
    const int lane = tid & 31;
    const int warp = tid >> 5;
    const int wm   = warp >> 1;
    const int wn   = warp & 1;
    const int bm   = blockIdx.y * 128;
    const int bn   = blockIdx.x * 128;

    const unsigned sbase =
        (unsigned)__cvta_generic_to_shared((void*)sm4);

    float acc[4][8][4];
    #pragma unroll
    for (int i = 0; i < 4; i++) {
        #pragma unroll
        for (int j = 0; j < 8; j++) {
            #pragma unroll
            for (int q = 0; q < 4; q++) acc[i][j][q] = 0.f;
        }
    }

    const int ar      = lane & 15;
    const int acolsel = lane >> 4;
    const int br      = (lane & 7) | ((lane >> 4) << 3);
    const int bcolsel = (lane >> 3) & 1;

    // ---- precomputed per-stage ldsm byte offsets ----
    unsigned aoff[2][4];
    unsigned boff[2][4];
    #pragma unroll
    for (int s = 0; s < 2; s++) {
        #pragma unroll
        for (int i = 0; i < 4; i++) {
            int row = wm * 64 + i * 16 + ar;
            int chunk = 2 * s + acolsel;
            int sw = chunk ^ ((row >> 1) & 3);
            aoff[s][i] = (unsigned)((row * 4 + sw) << 4);
        }
        #pragma unroll
        for (int p = 0; p < 4; p++) {
            int row = wn * 64 + p * 16 + br;
            int chunk = 2 * s + bcolsel;
            int sw = chunk ^ ((row >> 1) & 3);
            boff[s][p] = (unsigned)((512 + row * 4 + sw) << 4);
        }
    }

    const int nk = K / 32;

    #define LOAD_STAGE(stg, kt_)                                                \
    {                                                                           \
        int k0 = (kt_) * 32;                                                    \
        _Pragma("unroll")                                                       \
        for (int it = 0; it < 8; it++) {                                        \
            int c   = tid + it * 128;                                           \
            int plane = c >> 9;                                                 \
            int rem = c & 511;                                                  \
            int row = rem >> 2;                                                 \
            int col = rem & 3;                                                  \
            int sw  = col ^ ((row >> 1) & 3);                                   \
            unsigned daddr = sbase +                                            \
                (unsigned)((((stg) * STG_CHUNK) + plane * 512 + row * 4 + sw) << 4); \
            const __half* gp;                                                   \
            size_t goff;                                                        \
            if (plane == 0) { gp = Ahi; goff = (size_t)(bm + row) * K + k0 + col * 8; } \
            else            { gp = Bhi; goff = (size_t)(bn + row) * K + k0 + col * 8; } \
            CP16(daddr, gp + goff);                                             \
        }                                                                       \
    }

    LOAD_STAGE(0, 0);
    CP_COMMIT();
    LOAD_STAGE(1, 1);
    CP_COMMIT();
    LOAD_STAGE(2, 2);
    CP_COMMIT();

    for (int kt = 0; kt < nk; kt++) {
        CP_WAIT2();
        __syncthreads();

        if (kt + 3 < nk) {
            LOAD_STAGE((kt + 3) & 3, kt + 3);
        }
        CP_COMMIT();

        const unsigned sb = sbase + (unsigned)(((kt & 3) * STG_CHUNK) << 4);

        // all 8 A fragments (both k16 steps)
        unsigned a[2][4][4];
        #pragma unroll
        for (int s = 0; s < 2; s++) {
            #pragma unroll
            for (int i = 0; i < 4; i++) {
                ldsm4(a[s][i][0], a[s][i][1], a[s][i][2], a[s][i][3],
                      sb + aoff[s][i]);
            }
        }

        // B through 2-deep register double buffer, 1 group ahead
        unsigned bbuf[2][4];
        ldsm4(bbuf[0][0], bbuf[0][1], bbuf[0][2], bbuf[0][3], sb + boff[0][0]);
        #pragma unroll
        for (int sp = 0; sp < 8; sp++) {
            const int cur = sp & 1;
            if (sp < 7) {
                const int nsp = sp + 1;
                ldsm4(bbuf[cur ^ 1][0], bbuf[cur ^ 1][1],
                      bbuf[cur ^ 1][2], bbuf[cur ^ 1][3],
                      sb + boff[nsp >> 2][nsp & 3]);
            }
            const int s = sp >> 2;
            const int p = sp & 3;
            #pragma unroll
            for (int i = 0; i < 4; i++) {
                mmaf16(acc[i][2*p],
                       a[s][i][0], a[s][i][1], a[s][i][2], a[s][i][3],
                       bbuf[cur][0], bbuf[cur][1]);
                mmaf16(acc[i][2*p+1],
                       a[s][i][0], a[s][i][1], a[s][i][2], a[s][i][3],
                       bbuf[cur][2], bbuf[cur][3]);
            }
        }
    }
    #undef LOAD_STAGE

    const int rg = lane >> 2;
    const int q2 = (lane & 3) * 2;
    #pragma unroll
    for (int i = 0; i < 4; i++) {
        int r0 = bm + wm * 64 + i * 16 + rg;
        int r1 = r0 + 8;
        #pragma unroll
        for (int j = 0; j < 8; j++) {
            int col = bn + wn * 64 + j * 8 + q2;
            float b0 = bias[col];
            float b1 = bias[col + 1];
            float v0 = acc[i][j][0] + b0;
            float v1 = acc[i][j][1] + b1;
            float v2 = acc[i][j][2] + b0;
            float v3 = acc[i][j][3] + b1;
            size_t p0 = (size_t)r0 * N + col;
            size_t p1 = (size_t)r1 * N + col;
            if (EPI == 0) {
                C[p0] = v0; C[p0 + 1] = v1;
                C[p1] = v2; C[p1 + 1] = v3;
            }
            if (EPI == 1) {
                whi2(Chi, p0, v0, v1);
                whi2(Chi, p1, v2, v3);
                C2[p0]     = res[p0]     + v0;
                C2[p0 + 1] = res[p0 + 1] + v1;
                C2[p1]     = res[p1]     + v2;
                C2[p1 + 1] = res[p1 + 1] + v3;
            }
            if (EPI == 2) {
                v0 = 0.5f * v0 * (1.0f + erff(v0 * 0.70710678118654752f));
                v1 = 0.5f * v1 * (1.0f + erff(v1 * 0.70710678118654752f));
                v2 = 0.5f * v2 * (1.0f + erff(v2 * 0.70710678118654752f));
                v3 = 0.5f * v3 * (1.0f + erff(v3 * 0.70710678118654752f));
                whi2(Chi, p0, v0, v1);
                whi2(Chi, p1, v2, v3);
            }
            if (EPI == 3) {
                C[p0]     = v0 + res[p0];
                C[p0 + 1] = v1 + res[p0 + 1];
                C[p1]     = v2 + res[p1];
                C[p1 + 1] = v3 + res[p1 + 1];
            }
            if (EPI == 4) {
                wplane2(Chi, Clo, p0, v0, v1);
                wplane2(Chi, Clo, p1, v2, v3);
            }
        }
    }
}

// ============================================================================
// Tensor-core causal flash attention, fp16 2-term (Q,P split; K,V hi-only).
// ============================================================================
#define FA_SMEM (3072 * 16)   // 48 KB

__global__ void __launch_bounds__(128) flash_attn_tc(
    const __half* __restrict__ qhi, const __half* __restrict__ qlo,
    __half* __restrict__ outhi)
{
    extern __shared__ uint4 sm4[];
    const int tid  = threadIdx.x;
    const int lane = tid & 31;
    const int warp = tid >> 5;
    const int qt = blockIdx.x;
    const int h  = blockIdx.y;
    const int b  = blockIdx.z;
    const unsigned smem_base =
        (unsigned)__cvta_generic_to_shared((void*)sm4);

    const size_t rstr = 3 * DD;
    const size_t qrow0  = (size_t)b * SS + (size_t)qt * 64;
    const size_t kvrow0 = (size_t)b * SS;

    #pragma unroll
    for (int it = 0; it < 8; it++) {
        int c = tid + it * 128;
        int plane = c >> 9;
        int rem = c & 511;
        int row = rem >> 3;
        int ch  = rem & 7;
        int sw  = ch ^ (row & 7);
        unsigned d = smem_base + (unsigned)((plane * 512 + row * 8 + sw) << 4);
        const __half* src = (plane ? qlo : qhi);
        CP16(d, src + (qrow0 + row) * rstr + h * 64 + ch * 8);
    }
    CP_COMMIT();

    const int nkt = qt + 1;

    #define LOAD_KV(stg_, kt_)                                                  \
    {                                                                           \
        size_t krow = kvrow0 + (size_t)(kt_) * 64;                              \
        _Pragma("unroll")                                                       \
        for (int it = 0; it < 8; it++) {                                        \
            int c = tid + it * 128;                                             \
            int plane = c >> 9;   /* 0 Khi, 1 Vhi */                            \
            int rem = c & 511;                                                  \
            int row = rem >> 3;                                                 \
            int ch  = rem & 7;                                                  \
            int sw  = ch ^ (row & 7);                                           \
            unsigned d = smem_base +                                            \
                (unsigned)((1024 + (stg_) * 1024 + plane * 512 + row * 8 + sw) << 4); \
            size_t off = (krow + row) * rstr +                                  \
                         (plane ? 2 * DD : DD) + h * 64 + ch * 8;               \
            CP16(d, qhi + off);                                                 \
        }                                                                       \
    }

    LOAD_KV(0, 0);
    CP_COMMIT();
    if (nkt > 1) { LOAD_KV(1, 1); }
    CP_COMMIT();

    const int g = lane >> 2;
    const int q = lane & 3;

    float m0 = -INFINITY, m1 = -INFINITY;
    float l0 = 0.f, l1 = 0.f;
    float ov[8][4];
    #pragma unroll
    for (int j = 0; j < 8; j++) {
        #pragma unroll
        for (int k = 0; k < 4; k++) ov[j][k] = 0.f;
    }

    for (int kt = 0; kt < nkt; kt++) {
        CP_WAIT1();
        __syncthreads();
        const unsigned stg = smem_base +
            (unsigned)((1024 + (kt & 1) * 1024) << 4);

        float ss[8][4];
        #pragma unroll
        for (int j = 0; j < 8; j++) {
            #pragma unroll
            for (int k = 0; k < 4; k++) ss[j][k] = 0.f;
        }

        #pragma unroll
        for (int t = 0; t < 4; t++) {
            int arow = warp * 16 + (lane & 15);
            int ach  = 2 * t + (lane >> 4);
            int asw  = ach ^ (arow & 7);
            unsigned aaddr = smem_base + (unsigned)((arow * 8 + asw) << 4);
            unsigned qh0, qh1, qh2, qh3, ql0, ql1, ql2, ql3;
            ldsm4(qh0, qh1, qh2, qh3, aaddr);
            ldsm4(ql0, ql1, ql2, ql3, aaddr + (unsigned)(512 << 4));

            #pragma unroll
            for (int pb = 0; pb < 4; pb++) {
                int brow = pb * 16 + ((lane & 7) | ((lane >> 4) << 3));
                int bch  = 2 * t + ((lane >> 3) & 1);
                int bsw  = bch ^ (brow & 7);
                unsigned baddr = stg + (unsigned)((brow * 8 + bsw) << 4);
                unsigned kh0, kh1, kh2, kh3;
                ldsm4(kh0, kh1, kh2, kh3, baddr);
                mmaf16(ss[2*pb],   qh0, qh1, qh2, qh3, kh0, kh1);
                mmaf16(ss[2*pb],   ql0, ql1, ql2, ql3, kh0, kh1);
                mmaf16(ss[2*pb+1], qh0, qh1, qh2, qh3, kh2, kh3);
                mmaf16(ss[2*pb+1], ql0, ql1, ql2, ql3, kh2, kh3);
            }
        }

        #pragma unroll
        for (int j = 0; j < 8; j++) {
            ss[j][0] *= 0.125f; ss[j][1] *= 0.125f;
            ss[j][2] *= 0.125f; ss[j][3] *= 0.125f;
        }
        if (kt == qt) {
            int qr0 = warp * 16 + g;
            int qr1 = qr0 + 8;
            #pragma unroll
            for (int j = 0; j < 8; j++) {
                int k0 = 8 * j + 2 * q;
                int k1 = k0 + 1;
                if (k0 > qr0) ss[j][0] = -1e30f;
                if (k1 > qr0) ss[j][1] = -1e30f;
                if (k0 > qr1) ss[j][2] = -1e30f;
                if (k1 > qr1) ss[j][3] = -1e30f;
            }
        }

        float rm0 = -1e30f, rm1 = -1e30f;
        #pragma unroll
        for (int j = 0; j < 8; j++) {
            rm0 = fmaxf(rm0, fmaxf(ss[j][0], ss[j][1]));
            rm1 = fmaxf(rm1, fmaxf(ss[j][2], ss[j][3]));
        }
        rm0 = fmaxf(rm0, __shfl_xor_sync(0xffffffffu, rm0, 1));
        rm0 = fmaxf(rm0, __shfl_xor_sync(0xffffffffu, rm0, 2));
        rm1 = fmaxf(rm1, __shfl_xor_sync(0xffffffffu, rm1, 1));
        rm1 = fmaxf(rm1, __shfl_xor_sync(0xffffffffu, rm1, 2));
        float mn0 = fmaxf(m0, rm0);
        float mn1 = fmaxf(m1, rm1);
        float corr0 = __expf(m0 - mn0);
        float corr1 = __expf(m1 - mn1);
        m0 = mn0; m1 = mn1;

        float ps0 = 0.f, ps1 = 0.f;
        #pragma unroll
        for (int j = 0; j < 8; j++) {
            ss[j][0] = __expf(ss[j][0] - mn0);
            ss[j][1] = __expf(ss[j][1] - mn0);
            ss[j][2] = __expf(ss[j][2] - mn1);
            ss[j][3] = __expf(ss[j][3] - mn1);
            ps0 += ss[j][0] + ss[j][1];
            ps1 += ss[j][2] + ss[j][3];
        }
        ps0 += __shfl_xor_sync(0xffffffffu, ps0, 1);
        ps0 += __shfl_xor_sync(0xffffffffu, ps0, 2);
        ps1 += __shfl_xor_sync(0xffffffffu, ps1, 1);
        ps1 += __shfl_xor_sync(0xffffffffu, ps1, 2);
        l0 = l0 * corr0 + ps0;
        l1 = l1 * corr1 + ps1;
        #pragma unroll
        for (int j = 0; j < 8; j++) {
            ov[j][0] *= corr0; ov[j][1] *= corr0;
            ov[j][2] *= corr1; ov[j][3] *= corr1;
        }

        #pragma unroll
        for (int t = 0; t < 4; t++) {
            unsigned ph0, ph1, ph2, ph3, pl0, pl1, pl2, pl3;
            hsplit2u(ss[2*t][0],   ss[2*t][1],   ph0, pl0);
            hsplit2u(ss[2*t][2],   ss[2*t][3],   ph1, pl1);
            hsplit2u(ss[2*t+1][0], ss[2*t+1][1], ph2, pl2);
            hsplit2u(ss[2*t+1][2], ss[2*t+1][3], ph3, pl3);

            #pragma unroll
            for (int jd2 = 0; jd2 < 4; jd2++) {
                int vrow = 16 * t + (lane & 7) + ((lane >> 3) & 1) * 8;
                int vch  = jd2 * 2 + (lane >> 4);
                int vsw  = vch ^ (vrow & 7);
                unsigned vaddr = stg + (unsigned)((512 + vrow * 8 + vsw) << 4);
                unsigned vh0, vh1, vh2, vh3;
                ldsm4t(vh0, vh1, vh2, vh3, vaddr);
                mmaf16(ov[2*jd2],   ph0, ph1, ph2, ph3, vh0, vh1);
                mmaf16(ov[2*jd2],   pl0, pl1, pl2, pl3, vh0, vh1);
                mmaf16(ov[2*jd2+1], ph0, ph1, ph2, ph3, vh2, vh3);
                mmaf16(ov[2*jd2+1], pl0, pl1, pl2, pl3, vh2, vh3);
            }
        }

        __syncthreads();
        if (kt + 2 < nkt) { LOAD_KV(kt & 1, kt + 2); }
        CP_COMMIT();
    }
    #undef LOAD_KV

    float invl0 = 1.0f / l0;
    float invl1 = 1.0f / l1;
    #pragma unroll
    for (int jd = 0; jd < 8; jd++) {
        size_t p0 = (qrow0 + warp * 16 + g) * DD + h * 64 + 8 * jd + 2 * q;
        size_t p1 = p0 + (size_t)8 * DD;
        whi2(outhi, p0, ov[jd][0] * invl0, ov[jd][1] * invl0);
        whi2(outhi, p1, ov[jd][2] * invl1, ov[jd][3] * invl1);
    }
}

// ---------------- launch ----------------------------------------------------
extern "C" void kernel_launch(void* const* d_in, const int* in_sizes, int n_in,
                              void* d_out, int out_size)
{
    const float* x          = (const float*)d_in[0];
    const float* ln_attn_w  = (const float*)d_in[1];
    const float* ln_attn_b  = (const float*)d_in[2];
    const float* attn_in_w  = (const float*)d_in[3];
    const float* attn_in_b  = (const float*)d_in[4];
    const float* attn_out_w = (const float*)d_in[5];
    const float* attn_out_b = (const float*)d_in[6];
    const float* ln1_w      = (const float*)d_in[7];
    const float* ln1_b      = (const float*)d_in[8];
    const float* ln2_w      = (const float*)d_in[9];
    const float* ln2_b      = (const float*)d_in[10];
    const float* inl_u_w    = (const float*)d_in[11];
    const float* inl_u_b    = (const float*)d_in[12];
    const float* inl_a_w    = (const float*)d_in[13];
    const float* inl_a_b    = (const float*)d_in[14];
    const float* inl_b_w    = (const float*)d_in[15];
    const float* inl_b_b    = (const float*)d_in[16];
    const float* inl_g_w    = (const float*)d_in[17];
    const float* inl_g_b    = (const float*)d_in[18];
    const float* ff1_w      = (const float*)d_in[19];
    const float* ff1_b      = (const float*)d_in[20];
    const float* ff2_w      = (const float*)d_in[21];
    const float* ff2_b      = (const float*)d_in[22];
    float* out = (float*)d_out;

    __half *xn_hi = 0, *qkv_hi = 0, *qkv_lo = 0, *att_hi = 0;
    __half *ctx_hi = 0, *h_hi = 0, *ffh_hi = 0, *w_hi = 0;
    float *x1 = 0, *xs0 = 0, *inl = 0, *x2 = 0, *bcat = 0;
    cudaGetSymbolAddress((void**)&xn_hi,  g_xn_hi);
    cudaGetSymbolAddress((void**)&qkv_hi, g_qkv_hi);
    cudaGetSymbolAddress((void**)&qkv_lo, g_qkv_lo);
    cudaGetSymbolAddress((void**)&att_hi, g_att_hi);
    cudaGetSymbolAddress((void**)&ctx_hi, g_ctx_hi);
    cudaGetSymbolAddress((void**)&h_hi,   g_h_hi);
    cudaGetSymbolAddress((void**)&ffh_hi, g_ffh_hi);
    cudaGetSymbolAddress((void**)&w_hi,   g_w_hi);
    cudaGetSymbolAddress((void**)&x1,     g_x1);
    cudaGetSymbolAddress((void**)&xs0,    g_xs0);
    cudaGetSymbolAddress((void**)&inl,    g_inl);
    cudaGetSymbolAddress((void**)&x2,     g_x2);
    cudaGetSymbolAddress((void**)&bcat,   g_bcat);

    cudaFuncSetAttribute(gemm_f16<0>,
        cudaFuncAttributeMaxDynamicSharedMemorySize, GEM_SMEM);
    cudaFuncSetAttribute(gemm_f16<1>,
        cudaFuncAttributeMaxDynamicSharedMemorySize, GEM_SMEM);
    cudaFuncSetAttribute(gemm_f16<2>,
        cudaFuncAttributeMaxDynamicSharedMemorySize, GEM_SMEM);
    cudaFuncSetAttribute(gemm_f16<3>,
        cudaFuncAttributeMaxDynamicSharedMemorySize, GEM_SMEM);
    cudaFuncSetAttribute(gemm_f16<4>,
        cudaFuncAttributeMaxDynamicSharedMemorySize, GEM_SMEM);
    cudaFuncSetAttribute(flash_attn_tc,
        cudaFuncAttributeMaxDynamicSharedMemorySize, FA_SMEM);

    // 0) weight plane conversion + bias concat
    conv_w_k<<<(int)(W_TOTAL / 512), 256>>>(
        attn_in_w, attn_out_w, inl_u_w, inl_a_w, inl_b_w, inl_g_w, ff1_w, ff2_w);
    bias_cat_k<<<16, 256>>>(inl_u_b, inl_a_b, inl_b_b, inl_g_b);

    // 1) pre-attn LN -> xn hi plane
    layernorm_h<<<ROWS, 256>>>(x, ln_attn_w, ln_attn_b, xn_hi);

    // 2) QKV projection -> qkv hi+lo planes
    gemm_f16<4><<<dim3(3*DD/128, ROWS/128), 128, GEM_SMEM>>>(
        xn_hi, w_hi + WOFF_ATTNIN,
        attn_in_b, ROWS, 3*DD, DD, (float*)0, (const float*)0, (float*)0,
        qkv_hi, qkv_lo);

    // 3) tensor-core causal flash attention -> att hi plane
    flash_attn_tc<<<dim3(SS/64, HH, BB), 128, FA_SMEM>>>(
        qkv_hi, qkv_lo, att_hi);

    // 4) out-projection: ctx hi = proj+bias, x1 = x + proj+bias
    gemm_f16<1><<<dim3(DD/128, ROWS/128), 128, GEM_SMEM>>>(
        att_hi, w_hi + WOFF_ATTNOUT,
        attn_out_b, ROWS, DD, DD, (float*)0, x, x1, ctx_hi, (__half*)0);

    // 5) LN1(x1) -> xs0 fp32
    layernorm_f<<<ROWS, 256>>>(x1, ln1_w, ln1_b, xs0);

    // 6) fused INL controller projections: [ROWS, 4096] fp32
    gemm_f16<0><<<dim3(4*DD/128, ROWS/128), 128, GEM_SMEM>>>(
        ctx_hi, w_hi + WOFF_INL,
        bcat, ROWS, 4*DD, DD, inl, (const float*)0, (float*)0,
        (__half*)0, (__half*)0);

    // 7+8) fused INL dynamics + LN2 -> x2 (fp32) and h hi plane
    inl_ln_k<<<ROWS, 256>>>(xs0, inl, x1, ln2_w, ln2_b, x2, h_hi);

    // 9) FF1 + exact GELU -> ffh hi plane
    gemm_f16<2><<<dim3(FFD/128, ROWS/128), 128, GEM_SMEM>>>(
        h_hi, w_hi + WOFF_FF1,
        ff1_b, ROWS, FFD, DD, (float*)0, (const float*)0, (float*)0,
        ffh_hi, (__half*)0);

    // 10) FF2 + bias + residual -> out
    gemm_f16<3><<<dim3(DD/128, ROWS/128), 128, GEM_SMEM>>>(
        ffh_hi, w_hi + WOFF_FF2,
        ff2_b, ROWS, DD, FFD, out, x2, (float*)0,
        (__half*)0, (__half*)0);
}